// round 9
// baseline (speedup 1.0000x reference)
#include <cuda_runtime.h>
#include <cuda_bf16.h>
#include <math.h>
#include <stdint.h>

#define BATCH 4
#define SEQT 2048
#define CDIM 768
#define NHEAD 12
#define HDIM 64
#define MROWS (BATCH * SEQT)   // 8192

// ---------------------------------------------------------------------------
// Scratch (allocation-free rule: device globals)
// ---------------------------------------------------------------------------
__device__ __nv_bfloat16 g_xhi[(size_t)MROWS * CDIM];
__device__ __nv_bfloat16 g_xlo[(size_t)MROWS * CDIM];
__device__ __nv_bfloat16 g_qhi[(size_t)MROWS * CDIM];
__device__ __nv_bfloat16 g_qlo[(size_t)MROWS * CDIM];
__device__ __nv_bfloat16 g_khi[(size_t)MROWS * CDIM];
__device__ __nv_bfloat16 g_klo[(size_t)MROWS * CDIM];
__device__ __nv_bfloat16 g_vhi[(size_t)MROWS * CDIM];
__device__ __nv_bfloat16 g_vlo[(size_t)MROWS * CDIM];
__device__ __nv_bfloat16 g_ahi[(size_t)MROWS * CDIM];
__device__ __nv_bfloat16 g_alo[(size_t)MROWS * CDIM];
// transposed+split weights: [4][N=CDIM][K=CDIM] (order: Wq, Wk, Wv, Wo)
__device__ __nv_bfloat16 g_wthi[4 * (size_t)CDIM * CDIM];
__device__ __nv_bfloat16 g_wtlo[4 * (size_t)CDIM * CDIM];

// ---------------------------------------------------------------------------
// PTX helpers (sm_80-era: legal under .target sm_103)
// ---------------------------------------------------------------------------
__device__ __forceinline__ uint32_t smem_to_u32(const void* p) {
    uint32_t a;
    asm("{ .reg .u64 t; cvta.to.shared.u64 t, %1; cvt.u32.u64 %0, t; }"
        : "=r"(a) : "l"(p));
    return a;
}

__device__ __forceinline__ void ldsm_x4(uint32_t* r, uint32_t addr) {
    asm volatile("ldmatrix.sync.aligned.m8n8.x4.shared.b16 {%0,%1,%2,%3}, [%4];"
        : "=r"(r[0]), "=r"(r[1]), "=r"(r[2]), "=r"(r[3]) : "r"(addr));
}

__device__ __forceinline__ void ldsm_x4_trans(uint32_t* r, uint32_t addr) {
    asm volatile("ldmatrix.sync.aligned.m8n8.x4.trans.shared.b16 {%0,%1,%2,%3}, [%4];"
        : "=r"(r[0]), "=r"(r[1]), "=r"(r[2]), "=r"(r[3]) : "r"(addr));
}

__device__ __forceinline__ void mma16816(float* c, const uint32_t* a, const uint32_t* b) {
    asm volatile(
        "mma.sync.aligned.m16n8k16.row.col.f32.bf16.bf16.f32 "
        "{%0,%1,%2,%3}, {%4,%5,%6,%7}, {%8,%9}, {%0,%1,%2,%3};"
        : "+f"(c[0]), "+f"(c[1]), "+f"(c[2]), "+f"(c[3])
        : "r"(a[0]), "r"(a[1]), "r"(a[2]), "r"(a[3]), "r"(b[0]), "r"(b[1]));
}

__device__ __forceinline__ float fast_ex2(float x) {
    float y;
    asm("ex2.approx.f32 %0, %1;" : "=f"(y) : "f"(x));
    return y;
}

#define CP16(dst, src) \
    asm volatile("cp.async.cg.shared.global [%0], [%1], 16;" \
                 :: "r"(dst), "l"(src) : "memory")
#define CP_COMMIT() asm volatile("cp.async.commit_group;" ::: "memory")
#define CP_WAIT0()  asm volatile("cp.async.wait_group 0;" ::: "memory")

#define SWZ128(off) ((off) ^ (((off) >> 3) & 0x70))

// 0.125 * log2(e): folded into Q at the QKV GEMM epilogue
#define QK_SCALE 0.18033688011112042f

// ---------------------------------------------------------------------------
// Conversion kernels
// ---------------------------------------------------------------------------
__global__ void split_f32(const float* __restrict__ in,
                          __nv_bfloat16* __restrict__ hi,
                          __nv_bfloat16* __restrict__ lo, int n) {
    int i = blockIdx.x * blockDim.x + threadIdx.x;
    if (i < n) {
        float v = in[i];
        __nv_bfloat16 h = __float2bfloat16(v);
        float r = v - __bfloat162float(h);
        hi[i] = h;
        lo[i] = __float2bfloat16(r);
    }
}

__global__ void wtrans_split4(const float* __restrict__ W0, const float* __restrict__ W1,
                              const float* __restrict__ W2, const float* __restrict__ W3,
                              __nv_bfloat16* __restrict__ hi,
                              __nv_bfloat16* __restrict__ lo) {
    __shared__ float t[32][33];
    const int z = blockIdx.z;
    const float* W = (z == 0) ? W0 : (z == 1) ? W1 : (z == 2) ? W2 : W3;
    const size_t zoff = (size_t)z * CDIM * CDIM;
    const int kx = blockIdx.x * 32;
    const int nx = blockIdx.y * 32;
    const int tx = threadIdx.x, ty = threadIdx.y;
    for (int j = ty; j < 32; j += 8)
        t[j][tx] = W[(size_t)(kx + j) * CDIM + nx + tx];
    __syncthreads();
    for (int j = ty; j < 32; j += 8) {
        float v = t[tx][j];
        __nv_bfloat16 h = __float2bfloat16(v);
        float r = v - __bfloat162float(h);
        size_t o = zoff + (size_t)(nx + j) * CDIM + kx + tx;
        hi[o] = h;
        lo[o] = __float2bfloat16(r);
    }
}

// ---------------------------------------------------------------------------
// mma.sync split-bf16 GEMM, 128x64 tile, 2 stages, 2 CTAs/SM. (unchanged)
// ---------------------------------------------------------------------------
#define GK 64
#define NCHUNK (CDIM / GK)        // 12
#define CH_BYTES 49152
#define GEMM_SMEM (2 * CH_BYTES)  // 98304
#define T_AHI 0
#define T_ALO 16384
#define T_BHI 32768
#define T_BLO 40960

template <bool SPLIT_OUT>
__global__ __launch_bounds__(256, 2) void gemm_mma_split(
    const __nv_bfloat16* __restrict__ Ahi, const __nv_bfloat16* __restrict__ Alo,
    const __nv_bfloat16* __restrict__ Wthi, const __nv_bfloat16* __restrict__ Wtlo,
    const float* __restrict__ b0, const float* __restrict__ b1,
    const float* __restrict__ b2,
    float* __restrict__ Cout,
    __nv_bfloat16* __restrict__ C0hi, __nv_bfloat16* __restrict__ C0lo,
    __nv_bfloat16* __restrict__ C1hi, __nv_bfloat16* __restrict__ C1lo,
    __nv_bfloat16* __restrict__ C2hi, __nv_bfloat16* __restrict__ C2lo)
{
    extern __shared__ char smem[];
    const uint32_t sbase = smem_to_u32(smem);
    const int tid = threadIdx.x;
    const int lane = tid & 31;
    const int wid = tid >> 5;
    const int warp_m = wid >> 1;
    const int warp_n = wid & 1;
    const int row0 = blockIdx.y * 128;

    int wsel, col0;
    if (SPLIT_OUT) { wsel = blockIdx.x / 12; col0 = (blockIdx.x % 12) * 64; }
    else           { wsel = 3;              col0 = blockIdx.x * 64; }

    const size_t WSZ = (size_t)CDIM * CDIM;
    const __nv_bfloat16* Bhi = Wthi + (size_t)wsel * WSZ;
    const __nv_bfloat16* Blo = Wtlo + (size_t)wsel * WSZ;
    const float* bias = SPLIT_OUT ? (wsel == 0 ? b0 : wsel == 1 ? b1 : b2) : b0;
    __nv_bfloat16* Chi = SPLIT_OUT ? (wsel == 0 ? C0hi : wsel == 1 ? C1hi : C2hi) : nullptr;
    __nv_bfloat16* Clo = SPLIT_OUT ? (wsel == 0 ? C0lo : wsel == 1 ? C1lo : C2lo) : nullptr;
    const float oscale = (SPLIT_OUT && wsel == 0) ? QK_SCALE : 1.0f;

    const int lrow = lane & 7;
    const int lgrp = lane >> 3;
    const int a_roff = ((lgrp & 1) << 3) + lrow;
    const int a_kh   = (lgrp >> 1) << 4;
    const int b_roff = ((lgrp >> 1) << 3) + lrow;
    const int b_kh   = (lgrp & 1) << 4;

    const int ld_r   = tid >> 3;
    const int ld_c16 = (tid & 7) << 4;

    float acc[2][4][4];
#pragma unroll
    for (int i = 0; i < 2; i++)
#pragma unroll
        for (int j = 0; j < 4; j++)
#pragma unroll
            for (int r = 0; r < 4; r++) acc[i][j][r] = 0.0f;

    auto load_chunk = [&](int kc, int stage) {
        const uint32_t sb = sbase + stage * CH_BYTES;
        const int kcol = kc * GK;
#pragma unroll
        for (int t = 0; t < 4; t++) {
            const int r = ld_r + t * 32;
            const uint32_t sw = SWZ128(r * 128 + ld_c16);
            const char* pa  = (const char*)(Ahi + (size_t)(row0 + r) * CDIM + kcol) + ld_c16;
            const char* pal = (const char*)(Alo + (size_t)(row0 + r) * CDIM + kcol) + ld_c16;
            CP16(sb + T_AHI + sw, pa);
            CP16(sb + T_ALO + sw, pal);
        }
#pragma unroll
        for (int t = 0; t < 2; t++) {
            const int idx = tid + t * 256;
            const int r = idx >> 3;
            const int c16 = (idx & 7) << 4;
            const uint32_t sw = SWZ128(r * 128 + c16);
            const char* pb  = (const char*)(Bhi + (size_t)(col0 + r) * CDIM + kcol) + c16;
            const char* pbl = (const char*)(Blo + (size_t)(col0 + r) * CDIM + kcol) + c16;
            CP16(sb + T_BHI + sw, pb);
            CP16(sb + T_BLO + sw, pbl);
        }
        CP_COMMIT();
    };

    load_chunk(0, 0);

    for (int kc = 0; kc < NCHUNK; kc++) {
        CP_WAIT0();
        __syncthreads();
        if (kc + 1 < NCHUNK) load_chunk(kc + 1, (kc + 1) & 1);

        const uint32_t sb = sbase + (kc & 1) * CH_BYTES;
#pragma unroll
        for (int s = 0; s < 4; s++) {
            const int kb = s * 32;
            uint32_t ahi[2][4], alo[2][4];
#pragma unroll
            for (int i = 0; i < 2; i++) {
                const uint32_t off =
                    SWZ128((warp_m * 32 + i * 16 + a_roff) * 128 + kb + a_kh);
                ldsm_x4(ahi[i], sb + T_AHI + off);
                ldsm_x4(alo[i], sb + T_ALO + off);
            }
            uint32_t bhi[4][2], blo[4][2];
#pragma unroll
            for (int j2 = 0; j2 < 2; j2++) {
                const uint32_t off =
                    SWZ128((warp_n * 32 + j2 * 16 + b_roff) * 128 + kb + b_kh);
                uint32_t t[4];
                ldsm_x4(t, sb + T_BHI + off);
                bhi[2 * j2][0] = t[0]; bhi[2 * j2][1] = t[1];
                bhi[2 * j2 + 1][0] = t[2]; bhi[2 * j2 + 1][1] = t[3];
                ldsm_x4(t, sb + T_BLO + off);
                blo[2 * j2][0] = t[0]; blo[2 * j2][1] = t[1];
                blo[2 * j2 + 1][0] = t[2]; blo[2 * j2 + 1][1] = t[3];
            }
#pragma unroll
            for (int i = 0; i < 2; i++)
#pragma unroll
                for (int j = 0; j < 4; j++)
                    mma16816(acc[i][j], ahi[i], bhi[j]);
#pragma unroll
            for (int i = 0; i < 2; i++)
#pragma unroll
                for (int j = 0; j < 4; j++)
                    mma16816(acc[i][j], ahi[i], blo[j]);
#pragma unroll
            for (int i = 0; i < 2; i++)
#pragma unroll
                for (int j = 0; j < 4; j++)
                    mma16816(acc[i][j], alo[i], bhi[j]);
        }
    }

    // ---- epilogue ----
#pragma unroll
    for (int i = 0; i < 2; i++) {
        const int mrow = row0 + warp_m * 32 + i * 16 + (lane >> 2);
#pragma unroll
        for (int j = 0; j < 4; j++) {
            const int ncol = col0 + warp_n * 32 + j * 8 + ((lane & 3) << 1);
            const float2 bv = *(const float2*)&bias[ncol];
            const float c0 = (acc[i][j][0] + bv.x) * oscale;
            const float c1 = (acc[i][j][1] + bv.y) * oscale;
            const float c2 = (acc[i][j][2] + bv.x) * oscale;
            const float c3 = (acc[i][j][3] + bv.y) * oscale;
            if (SPLIT_OUT) {
                __nv_bfloat162 h0 = __floats2bfloat162_rn(c0, c1);
                float2 hf0 = __bfloat1622float2(h0);
                __nv_bfloat162 l0 = __floats2bfloat162_rn(c0 - hf0.x, c1 - hf0.y);
                __nv_bfloat162 h1 = __floats2bfloat162_rn(c2, c3);
                float2 hf1 = __bfloat1622float2(h1);
                __nv_bfloat162 l1 = __floats2bfloat162_rn(c2 - hf1.x, c3 - hf1.y);
                *(__nv_bfloat162*)&Chi[(size_t)mrow * CDIM + ncol] = h0;
                *(__nv_bfloat162*)&Clo[(size_t)mrow * CDIM + ncol] = l0;
                *(__nv_bfloat162*)&Chi[(size_t)(mrow + 8) * CDIM + ncol] = h1;
                *(__nv_bfloat162*)&Clo[(size_t)(mrow + 8) * CDIM + ncol] = l1;
            } else {
                float2 o0, o1;
                o0.x = c0; o0.y = c1;
                o1.x = c2; o1.y = c3;
                *(float2*)&Cout[(size_t)mrow * CDIM + ncol] = o0;
                *(float2*)&Cout[(size_t)(mrow + 8) * CDIM + ncol] = o1;
            }
        }
    }
}

// ---------------------------------------------------------------------------
// Flash attention (causal): 128 threads, 2 CTAs/SM, TWO 64-row Q bands per CTA
//   sharing one KV stream (halves KV L2 traffic vs BQ=64 single-band).
//   Band0 = rows [qrow0, +64), band1 = rows [qrow0+64, +128).
//   2 KV buffers (64KB) + Q region (32KB) = 96KB/CTA.
//   Q pre-scaled by 0.125*log2(e) -> softmax uses raw ex2.
// ---------------------------------------------------------------------------
#define KV_BUF 32768
#define O_KHI 0
#define O_KLO 8192
#define O_VHI 16384
#define O_VLO 24576
#define Q_OFF (2 * KV_BUF)
#define FA_SMEM (2 * KV_BUF + 32768)   // 98304

__global__ __launch_bounds__(128, 2) void flash_attn_mma(
    const __nv_bfloat16* __restrict__ Qhi, const __nv_bfloat16* __restrict__ Qlo,
    const __nv_bfloat16* __restrict__ Khi, const __nv_bfloat16* __restrict__ Klo,
    const __nv_bfloat16* __restrict__ Vhi, const __nv_bfloat16* __restrict__ Vlo,
    __nv_bfloat16* __restrict__ Ohi, __nv_bfloat16* __restrict__ Olo)
{
    extern __shared__ char smem[];
    const uint32_t sbase = smem_to_u32(smem);
    const int tid = threadIdx.x;
    const int lane = tid & 31;
    const int wid = tid >> 5;                      // 0..3
    const int qi = (gridDim.x - 1) - blockIdx.x;   // heavy CTAs first
    const int h = blockIdx.y;
    const int b = blockIdx.z;
    const int qrow0 = qi * 128;
    const int m0 = wid * 16;
    const int lr = lane & 7;
    const int lg = lane >> 3;

    const int nkt = 2 * qi + 2;   // band1's tile count; band0 uses nkt-1

    // ---- load Q (128 rows; hi at Q_OFF, lo at Q_OFF+16KB) ----
#pragma unroll
    for (int t = 0; t < 8; t++) {
        const int idx = tid + t * 128;             // 0..1023
        const int r = idx >> 3;
        const int c16 = (idx & 7) << 4;
        const uint32_t sw = SWZ128(r * 128 + c16);
        const size_t grow = (size_t)(b * SEQT + qrow0 + r) * CDIM + h * HDIM;
        CP16(sbase + Q_OFF + sw, (const char*)(Qhi + grow) + c16);
        CP16(sbase + Q_OFF + 16384 + sw, (const char*)(Qlo + grow) + c16);
    }
    CP_COMMIT();

    auto load_kv = [&](int kt) {
        const uint32_t sb = sbase + (uint32_t)(kt & 1) * KV_BUF;
#pragma unroll
        for (int t = 0; t < 4; t++) {
            const int idx = tid + t * 128;         // 0..511
            const int r = idx >> 3;
            const int c16 = (idx & 7) << 4;
            const uint32_t sw = SWZ128(r * 128 + c16);
            const size_t grow = (size_t)(b * SEQT + kt * 64 + r) * CDIM + h * HDIM;
            CP16(sb + O_KHI + sw, (const char*)(Khi + grow) + c16);
            CP16(sb + O_KLO + sw, (const char*)(Klo + grow) + c16);
            CP16(sb + O_VHI + sw, (const char*)(Vhi + grow) + c16);
            CP16(sb + O_VLO + sw, (const char*)(Vlo + grow) + c16);
        }
        CP_COMMIT();
    };
    load_kv(0);

    // ---- Q + kv0 landed for all threads; hoist Q fragments (both bands) ----
    CP_WAIT0();
    __syncthreads();
    uint32_t qfhA[4][4], qflA[4][4], qfhB[4][4], qflB[4][4];
#pragma unroll
    for (int s = 0; s < 4; s++) {
        const int rbase = m0 + ((lg & 1) << 3) + lr;
        const int cbase = s * 32 + ((lg >> 1) << 4);
        const uint32_t swA = SWZ128(rbase * 128 + cbase);
        const uint32_t swB = SWZ128((rbase + 64) * 128 + cbase);
        ldsm_x4(qfhA[s], sbase + Q_OFF + swA);
        ldsm_x4(qflA[s], sbase + Q_OFF + 16384 + swA);
        ldsm_x4(qfhB[s], sbase + Q_OFF + swB);
        ldsm_x4(qflB[s], sbase + Q_OFF + 16384 + swB);
    }

    float oA[8][4], oB[8][4];
#pragma unroll
    for (int j = 0; j < 8; j++)
#pragma unroll
        for (int r = 0; r < 4; r++) { oA[j][r] = 0.0f; oB[j][r] = 0.0f; }
    float mRa[2] = {-1e30f, -1e30f}, lRa[2] = {0.0f, 0.0f};
    float mRb[2] = {-1e30f, -1e30f}, lRb[2] = {0.0f, 0.0f};

    // ---- QK for one band against buffer kb -> sc ----
    auto qk_band = [&](uint32_t kb, const uint32_t (&qfh)[4][4],
                       const uint32_t (&qfl)[4][4], float (&sc)[8][4]) {
#pragma unroll
        for (int j = 0; j < 8; j++)
#pragma unroll
            for (int r = 0; r < 4; r++) sc[j][r] = 0.0f;
#pragma unroll
        for (int s = 0; s < 4; s++) {
#pragma unroll
            for (int p = 0; p < 4; p++) {
                const uint32_t sw = SWZ128((p * 16 + ((lg >> 1) << 3) + lr) * 128
                                           + s * 32 + ((lg & 1) << 4));
                uint32_t kh[4], kl[4];
                ldsm_x4(kh, kb + O_KHI + sw);
                ldsm_x4(kl, kb + O_KLO + sw);
                mma16816(sc[2 * p],     qfh[s], &kh[0]);
                mma16816(sc[2 * p + 1], qfh[s], &kh[2]);
                mma16816(sc[2 * p],     qfh[s], &kl[0]);
                mma16816(sc[2 * p + 1], qfh[s], &kl[2]);
                mma16816(sc[2 * p],     qfl[s], &kh[0]);
                mma16816(sc[2 * p + 1], qfl[s], &kh[2]);
            }
        }
    };

    // ---- causal mask for one band (diagonal tile) ----
    auto mask_band = [&](int kt, int band_row0, float (&sc)[8][4]) {
        const int qg0 = band_row0 + m0 + (lane >> 2);
        const int qg1 = qg0 + 8;
#pragma unroll
        for (int j = 0; j < 8; j++) {
            const int kg = kt * 64 + j * 8 + ((lane & 3) << 1);
            if (kg > qg0)     sc[j][0] = -1e30f;
            if (kg + 1 > qg0) sc[j][1] = -1e30f;
            if (kg > qg1)     sc[j][2] = -1e30f;
            if (kg + 1 > qg1) sc[j][3] = -1e30f;
        }
    };

    // ---- online softmax + PV for one band ----
    auto sm_pv = [&](uint32_t kb, float (&sc)[8][4],
                     float (&mR)[2], float (&lR)[2], float (&o)[8][4]) {
        float mp0 = sc[0][0], mp1 = sc[0][2];
#pragma unroll
        for (int j = 0; j < 8; j++) {
            mp0 = fmaxf(mp0, fmaxf(sc[j][0], sc[j][1]));
            mp1 = fmaxf(mp1, fmaxf(sc[j][2], sc[j][3]));
        }
        mp0 = fmaxf(mp0, __shfl_xor_sync(0xffffffffu, mp0, 1));
        mp0 = fmaxf(mp0, __shfl_xor_sync(0xffffffffu, mp0, 2));
        mp1 = fmaxf(mp1, __shfl_xor_sync(0xffffffffu, mp1, 1));
        mp1 = fmaxf(mp1, __shfl_xor_sync(0xffffffffu, mp1, 2));
        const float mn0 = fmaxf(mR[0], mp0);
        const float mn1 = fmaxf(mR[1], mp1);
        const float f0 = fast_ex2(mR[0] - mn0);
        const float f1 = fast_ex2(mR[1] - mn1);
        float sum0 = 0.0f, sum1 = 0.0f;
#pragma unroll
        for (int j = 0; j < 8; j++) {
            sc[j][0] = fast_ex2(sc[j][0] - mn0);
            sc[j][1] = fast_ex2(sc[j][1] - mn0);
            sc[j][2] = fast_ex2(sc[j][2] - mn1);
            sc[j][3] = fast_ex2(sc[j][3] - mn1);
            sum0 += sc[j][0] + sc[j][1];
            sum1 += sc[j][2] + sc[j][3];
        }
        sum0 += __shfl_xor_sync(0xffffffffu, sum0, 1);
        sum0 += __shfl_xor_sync(0xffffffffu, sum0, 2);
        sum1 += __shfl_xor_sync(0xffffffffu, sum1, 1);
        sum1 += __shfl_xor_sync(0xffffffffu, sum1, 2);
        lR[0] = lR[0] * f0 + sum0;
        lR[1] = lR[1] * f1 + sum1;
        mR[0] = mn0;
        mR[1] = mn1;
#pragma unroll
        for (int j = 0; j < 8; j++) {
            o[j][0] *= f0; o[j][1] *= f0;
            o[j][2] *= f1; o[j][3] *= f1;
        }

#pragma unroll
        for (int s2 = 0; s2 < 4; s2++) {
            uint32_t ph[4], pl[4];
#pragma unroll
            for (int half = 0; half < 2; half++) {
                const int jt = 2 * s2 + half;
                __nv_bfloat162 h0 = __floats2bfloat162_rn(sc[jt][0], sc[jt][1]);
                float2 hf0 = __bfloat1622float2(h0);
                __nv_bfloat162 l0 =
                    __floats2bfloat162_rn(sc[jt][0] - hf0.x, sc[jt][1] - hf0.y);
                __nv_bfloat162 h1 = __floats2bfloat162_rn(sc[jt][2], sc[jt][3]);
                float2 hf1 = __bfloat1622float2(h1);
                __nv_bfloat162 l1 =
                    __floats2bfloat162_rn(sc[jt][2] - hf1.x, sc[jt][3] - hf1.y);
                ph[2 * half]     = *(uint32_t*)&h0;
                ph[2 * half + 1] = *(uint32_t*)&h1;
                pl[2 * half]     = *(uint32_t*)&l0;
                pl[2 * half + 1] = *(uint32_t*)&l1;
            }
#pragma unroll
            for (int dp = 0; dp < 4; dp++) {
                const uint32_t sw = SWZ128((s2 * 16 + ((lg & 1) << 3) + lr) * 128
                                           + dp * 32 + ((lg >> 1) << 4));
                uint32_t vh[4], vl[4];
                ldsm_x4_trans(vh, kb + O_VHI + sw);
                ldsm_x4_trans(vl, kb + O_VLO + sw);
                mma16816(o[2 * dp],     ph, &vh[0]);
                mma16816(o[2 * dp + 1], ph, &vh[2]);
                mma16816(o[2 * dp],     ph, &vl[0]);
                mma16816(o[2 * dp + 1], ph, &vl[2]);
                mma16816(o[2 * dp],     pl, &vh[0]);
                mma16816(o[2 * dp + 1], pl, &vh[2]);
            }
        }
    };

    float sacc[8][4];

    for (int kt = 0; kt < nkt; kt++) {
        CP_WAIT0();        // kv(kt) landed
        __syncthreads();   // everyone's writes visible; prev-iter reads done
        if (kt + 1 < nkt) load_kv(kt + 1);
        const uint32_t kb = sbase + (uint32_t)(kt & 1) * KV_BUF;

        // band 1 (rows qrow0+64..): active for all kt; diagonal at kt == nkt-1
        qk_band(kb, qfhB, qflB, sacc);
        if (kt == nkt - 1) mask_band(kt, qrow0 + 64, sacc);
        sm_pv(kb, sacc, mRb, lRb, oB);

        // band 0 (rows qrow0..): active for kt <= nkt-2; diagonal at nkt-2
        if (kt <= nkt - 2) {
            qk_band(kb, qfhA, qflA, sacc);
            if (kt == nkt - 2) mask_band(kt, qrow0, sacc);
            sm_pv(kb, sacc, mRa, lRa, oA);
        }
    }

    // ---- normalize + write both bands (bf16 hi/lo) ----
#pragma unroll
    for (int band = 0; band < 2; band++) {
        const float* lR = band ? lRb : lRa;
        float (&o)[8][4] = band ? oB : oA;
        const float inv0 = 1.0f / lR[0];
        const float inv1 = 1.0f / lR[1];
        const int r0 = b * SEQT + qrow0 + band * 64 + m0 + (lane >> 2);
#pragma unroll
        for (int j = 0; j < 8; j++) {
            const int col = h * HDIM + j * 8 + ((lane & 3) << 1);
            const float c0 = o[j][0] * inv0, c1 = o[j][1] * inv0;
            const float c2 = o[j][2] * inv1, c3 = o[j][3] * inv1;
            __nv_bfloat162 h0 = __floats2bfloat162_rn(c0, c1);
            float2 hf0 = __bfloat1622float2(h0);
            __nv_bfloat162 l0 = __floats2bfloat162_rn(c0 - hf0.x, c1 - hf0.y);
            __nv_bfloat162 h1 = __floats2bfloat162_rn(c2, c3);
            float2 hf1 = __bfloat1622float2(h1);
            __nv_bfloat162 l1 = __floats2bfloat162_rn(c2 - hf1.x, c3 - hf1.y);
            *(__nv_bfloat162*)&Ohi[(size_t)r0 * CDIM + col] = h0;
            *(__nv_bfloat162*)&Olo[(size_t)r0 * CDIM + col] = l0;
            *(__nv_bfloat162*)&Ohi[(size_t)(r0 + 8) * CDIM + col] = h1;
            *(__nv_bfloat162*)&Olo[(size_t)(r0 + 8) * CDIM + col] = l1;
        }
    }
}

// ---------------------------------------------------------------------------
// Launch
// ---------------------------------------------------------------------------
extern "C" void kernel_launch(void* const* d_in, const int* in_sizes, int n_in,
                              void* d_out, int out_size)
{
    (void)in_sizes; (void)n_in; (void)out_size;
    const float* x  = (const float*)d_in[0];
    const float* Wq = (const float*)d_in[1];
    const float* bq = (const float*)d_in[2];
    const float* Wk = (const float*)d_in[3];
    const float* bk = (const float*)d_in[4];
    const float* Wv = (const float*)d_in[5];
    const float* bv = (const float*)d_in[6];
    const float* Wo = (const float*)d_in[7];
    const float* bo = (const float*)d_in[8];
    float* out = (float*)d_out;

    __nv_bfloat16 *xhi, *xlo, *qhi, *qlo, *khi, *klo, *vhi, *vlo, *ahi, *alo, *wthi, *wtlo;
    cudaGetSymbolAddress((void**)&xhi,  g_xhi);
    cudaGetSymbolAddress((void**)&xlo,  g_xlo);
    cudaGetSymbolAddress((void**)&qhi,  g_qhi);
    cudaGetSymbolAddress((void**)&qlo,  g_qlo);
    cudaGetSymbolAddress((void**)&khi,  g_khi);
    cudaGetSymbolAddress((void**)&klo,  g_klo);
    cudaGetSymbolAddress((void**)&vhi,  g_vhi);
    cudaGetSymbolAddress((void**)&vlo,  g_vlo);
    cudaGetSymbolAddress((void**)&ahi,  g_ahi);
    cudaGetSymbolAddress((void**)&alo,  g_alo);
    cudaGetSymbolAddress((void**)&wthi, g_wthi);
    cudaGetSymbolAddress((void**)&wtlo, g_wtlo);

    cudaFuncSetAttribute(gemm_mma_split<true>,
                         cudaFuncAttributeMaxDynamicSharedMemorySize, GEMM_SMEM);
    cudaFuncSetAttribute(gemm_mma_split<false>,
                         cudaFuncAttributeMaxDynamicSharedMemorySize, GEMM_SMEM);
    cudaFuncSetAttribute(flash_attn_mma,
                         cudaFuncAttributeMaxDynamicSharedMemorySize, FA_SMEM);

    const int nelem = MROWS * CDIM;

    split_f32<<<(nelem + 255) / 256, 256>>>(x, xhi, xlo, nelem);

    dim3 wt_grid(CDIM / 32, CDIM / 32, 4);
    dim3 wt_blk(32, 8);
    wtrans_split4<<<wt_grid, wt_blk>>>(Wq, Wk, Wv, Wo, wthi, wtlo);

    dim3 qkv_grid(36, MROWS / 128);
    gemm_mma_split<true><<<qkv_grid, 256, GEMM_SMEM>>>(
        xhi, xlo, wthi, wtlo, bq, bk, bv,
        nullptr, qhi, qlo, khi, klo, vhi, vlo);

    dim3 fa_grid(SEQT / 128, NHEAD, BATCH);    // (16, 12, 4) = 768 CTAs
    flash_attn_mma<<<fa_grid, 128, FA_SMEM>>>(qhi, qlo, khi, klo, vhi, vlo, ahi, alo);

    dim3 wo_grid(12, MROWS / 128);
    gemm_mma_split<false><<<wo_grid, 256, GEMM_SMEM>>>(
        ahi, alo, wthi, wtlo, bo, nullptr, nullptr,
        out, nullptr, nullptr, nullptr, nullptr, nullptr, nullptr);
}

// round 10
// speedup vs baseline: 1.0196x; 1.0196x over previous
#include <cuda_runtime.h>
#include <cuda_bf16.h>
#include <math.h>
#include <stdint.h>

#define BATCH 4
#define SEQT 2048
#define CDIM 768
#define NHEAD 12
#define HDIM 64
#define MROWS (BATCH * SEQT)   // 8192

// ---------------------------------------------------------------------------
// Scratch (allocation-free rule: device globals)
// ---------------------------------------------------------------------------
__device__ __nv_bfloat16 g_xhi[(size_t)MROWS * CDIM];
__device__ __nv_bfloat16 g_xlo[(size_t)MROWS * CDIM];
__device__ __nv_bfloat16 g_qhi[(size_t)MROWS * CDIM];
__device__ __nv_bfloat16 g_qlo[(size_t)MROWS * CDIM];
__device__ __nv_bfloat16 g_khi[(size_t)MROWS * CDIM];
__device__ __nv_bfloat16 g_klo[(size_t)MROWS * CDIM];
__device__ __nv_bfloat16 g_vhi[(size_t)MROWS * CDIM];
__device__ __nv_bfloat16 g_vlo[(size_t)MROWS * CDIM];
__device__ __nv_bfloat16 g_ahi[(size_t)MROWS * CDIM];
__device__ __nv_bfloat16 g_alo[(size_t)MROWS * CDIM];
// transposed+split weights: [4][N=CDIM][K=CDIM] (order: Wq, Wk, Wv, Wo)
__device__ __nv_bfloat16 g_wthi[4 * (size_t)CDIM * CDIM];
__device__ __nv_bfloat16 g_wtlo[4 * (size_t)CDIM * CDIM];

// ---------------------------------------------------------------------------
// PTX helpers (sm_80-era: legal under .target sm_103)
// ---------------------------------------------------------------------------
__device__ __forceinline__ uint32_t smem_to_u32(const void* p) {
    uint32_t a;
    asm("{ .reg .u64 t; cvta.to.shared.u64 t, %1; cvt.u32.u64 %0, t; }"
        : "=r"(a) : "l"(p));
    return a;
}

__device__ __forceinline__ void ldsm_x4(uint32_t* r, uint32_t addr) {
    asm volatile("ldmatrix.sync.aligned.m8n8.x4.shared.b16 {%0,%1,%2,%3}, [%4];"
        : "=r"(r[0]), "=r"(r[1]), "=r"(r[2]), "=r"(r[3]) : "r"(addr));
}

__device__ __forceinline__ void ldsm_x4_trans(uint32_t* r, uint32_t addr) {
    asm volatile("ldmatrix.sync.aligned.m8n8.x4.trans.shared.b16 {%0,%1,%2,%3}, [%4];"
        : "=r"(r[0]), "=r"(r[1]), "=r"(r[2]), "=r"(r[3]) : "r"(addr));
}

__device__ __forceinline__ void mma16816(float* c, const uint32_t* a, const uint32_t* b) {
    asm volatile(
        "mma.sync.aligned.m16n8k16.row.col.f32.bf16.bf16.f32 "
        "{%0,%1,%2,%3}, {%4,%5,%6,%7}, {%8,%9}, {%0,%1,%2,%3};"
        : "+f"(c[0]), "+f"(c[1]), "+f"(c[2]), "+f"(c[3])
        : "r"(a[0]), "r"(a[1]), "r"(a[2]), "r"(a[3]), "r"(b[0]), "r"(b[1]));
}

__device__ __forceinline__ float fast_ex2(float x) {
    float y;
    asm("ex2.approx.f32 %0, %1;" : "=f"(y) : "f"(x));
    return y;
}

#define CP16(dst, src) \
    asm volatile("cp.async.cg.shared.global [%0], [%1], 16;" \
                 :: "r"(dst), "l"(src) : "memory")
#define CP_COMMIT() asm volatile("cp.async.commit_group;" ::: "memory")
#define CP_WAIT0()  asm volatile("cp.async.wait_group 0;" ::: "memory")

#define SWZ128(off) ((off) ^ (((off) >> 3) & 0x70))

// 0.125 * log2(e): folded into Q at the QKV GEMM epilogue
#define QK_SCALE 0.18033688011112042f

// ---------------------------------------------------------------------------
// Conversion kernels
// ---------------------------------------------------------------------------
__global__ void split_f32(const float* __restrict__ in,
                          __nv_bfloat16* __restrict__ hi,
                          __nv_bfloat16* __restrict__ lo, int n) {
    int i = blockIdx.x * blockDim.x + threadIdx.x;
    if (i < n) {
        float v = in[i];
        __nv_bfloat16 h = __float2bfloat16(v);
        float r = v - __bfloat162float(h);
        hi[i] = h;
        lo[i] = __float2bfloat16(r);
    }
}

__global__ void wtrans_split4(const float* __restrict__ W0, const float* __restrict__ W1,
                              const float* __restrict__ W2, const float* __restrict__ W3,
                              __nv_bfloat16* __restrict__ hi,
                              __nv_bfloat16* __restrict__ lo) {
    __shared__ float t[32][33];
    const int z = blockIdx.z;
    const float* W = (z == 0) ? W0 : (z == 1) ? W1 : (z == 2) ? W2 : W3;
    const size_t zoff = (size_t)z * CDIM * CDIM;
    const int kx = blockIdx.x * 32;
    const int nx = blockIdx.y * 32;
    const int tx = threadIdx.x, ty = threadIdx.y;
    for (int j = ty; j < 32; j += 8)
        t[j][tx] = W[(size_t)(kx + j) * CDIM + nx + tx];
    __syncthreads();
    for (int j = ty; j < 32; j += 8) {
        float v = t[tx][j];
        __nv_bfloat16 h = __float2bfloat16(v);
        float r = v - __bfloat162float(h);
        size_t o = zoff + (size_t)(nx + j) * CDIM + kx + tx;
        hi[o] = h;
        lo[o] = __float2bfloat16(r);
    }
}

// ---------------------------------------------------------------------------
// mma.sync split-bf16 GEMM, 128x64 tile, 2 stages, 2 CTAs/SM. (unchanged)
// ---------------------------------------------------------------------------
#define GK 64
#define NCHUNK (CDIM / GK)        // 12
#define CH_BYTES 49152
#define GEMM_SMEM (2 * CH_BYTES)  // 98304
#define T_AHI 0
#define T_ALO 16384
#define T_BHI 32768
#define T_BLO 40960

template <bool SPLIT_OUT>
__global__ __launch_bounds__(256, 2) void gemm_mma_split(
    const __nv_bfloat16* __restrict__ Ahi, const __nv_bfloat16* __restrict__ Alo,
    const __nv_bfloat16* __restrict__ Wthi, const __nv_bfloat16* __restrict__ Wtlo,
    const float* __restrict__ b0, const float* __restrict__ b1,
    const float* __restrict__ b2,
    float* __restrict__ Cout,
    __nv_bfloat16* __restrict__ C0hi, __nv_bfloat16* __restrict__ C0lo,
    __nv_bfloat16* __restrict__ C1hi, __nv_bfloat16* __restrict__ C1lo,
    __nv_bfloat16* __restrict__ C2hi, __nv_bfloat16* __restrict__ C2lo)
{
    extern __shared__ char smem[];
    const uint32_t sbase = smem_to_u32(smem);
    const int tid = threadIdx.x;
    const int lane = tid & 31;
    const int wid = tid >> 5;
    const int warp_m = wid >> 1;
    const int warp_n = wid & 1;
    const int row0 = blockIdx.y * 128;

    int wsel, col0;
    if (SPLIT_OUT) { wsel = blockIdx.x / 12; col0 = (blockIdx.x % 12) * 64; }
    else           { wsel = 3;              col0 = blockIdx.x * 64; }

    const size_t WSZ = (size_t)CDIM * CDIM;
    const __nv_bfloat16* Bhi = Wthi + (size_t)wsel * WSZ;
    const __nv_bfloat16* Blo = Wtlo + (size_t)wsel * WSZ;
    const float* bias = SPLIT_OUT ? (wsel == 0 ? b0 : wsel == 1 ? b1 : b2) : b0;
    __nv_bfloat16* Chi = SPLIT_OUT ? (wsel == 0 ? C0hi : wsel == 1 ? C1hi : C2hi) : nullptr;
    __nv_bfloat16* Clo = SPLIT_OUT ? (wsel == 0 ? C0lo : wsel == 1 ? C1lo : C2lo) : nullptr;
    const float oscale = (SPLIT_OUT && wsel == 0) ? QK_SCALE : 1.0f;

    const int lrow = lane & 7;
    const int lgrp = lane >> 3;
    const int a_roff = ((lgrp & 1) << 3) + lrow;
    const int a_kh   = (lgrp >> 1) << 4;
    const int b_roff = ((lgrp >> 1) << 3) + lrow;
    const int b_kh   = (lgrp & 1) << 4;

    const int ld_r   = tid >> 3;
    const int ld_c16 = (tid & 7) << 4;

    float acc[2][4][4];
#pragma unroll
    for (int i = 0; i < 2; i++)
#pragma unroll
        for (int j = 0; j < 4; j++)
#pragma unroll
            for (int r = 0; r < 4; r++) acc[i][j][r] = 0.0f;

    auto load_chunk = [&](int kc, int stage) {
        const uint32_t sb = sbase + stage * CH_BYTES;
        const int kcol = kc * GK;
#pragma unroll
        for (int t = 0; t < 4; t++) {
            const int r = ld_r + t * 32;
            const uint32_t sw = SWZ128(r * 128 + ld_c16);
            const char* pa  = (const char*)(Ahi + (size_t)(row0 + r) * CDIM + kcol) + ld_c16;
            const char* pal = (const char*)(Alo + (size_t)(row0 + r) * CDIM + kcol) + ld_c16;
            CP16(sb + T_AHI + sw, pa);
            CP16(sb + T_ALO + sw, pal);
        }
#pragma unroll
        for (int t = 0; t < 2; t++) {
            const int idx = tid + t * 256;
            const int r = idx >> 3;
            const int c16 = (idx & 7) << 4;
            const uint32_t sw = SWZ128(r * 128 + c16);
            const char* pb  = (const char*)(Bhi + (size_t)(col0 + r) * CDIM + kcol) + c16;
            const char* pbl = (const char*)(Blo + (size_t)(col0 + r) * CDIM + kcol) + c16;
            CP16(sb + T_BHI + sw, pb);
            CP16(sb + T_BLO + sw, pbl);
        }
        CP_COMMIT();
    };

    load_chunk(0, 0);

    for (int kc = 0; kc < NCHUNK; kc++) {
        CP_WAIT0();
        __syncthreads();
        if (kc + 1 < NCHUNK) load_chunk(kc + 1, (kc + 1) & 1);

        const uint32_t sb = sbase + (kc & 1) * CH_BYTES;
#pragma unroll
        for (int s = 0; s < 4; s++) {
            const int kb = s * 32;
            uint32_t ahi[2][4], alo[2][4];
#pragma unroll
            for (int i = 0; i < 2; i++) {
                const uint32_t off =
                    SWZ128((warp_m * 32 + i * 16 + a_roff) * 128 + kb + a_kh);
                ldsm_x4(ahi[i], sb + T_AHI + off);
                ldsm_x4(alo[i], sb + T_ALO + off);
            }
            uint32_t bhi[4][2], blo[4][2];
#pragma unroll
            for (int j2 = 0; j2 < 2; j2++) {
                const uint32_t off =
                    SWZ128((warp_n * 32 + j2 * 16 + b_roff) * 128 + kb + b_kh);
                uint32_t t[4];
                ldsm_x4(t, sb + T_BHI + off);
                bhi[2 * j2][0] = t[0]; bhi[2 * j2][1] = t[1];
                bhi[2 * j2 + 1][0] = t[2]; bhi[2 * j2 + 1][1] = t[3];
                ldsm_x4(t, sb + T_BLO + off);
                blo[2 * j2][0] = t[0]; blo[2 * j2][1] = t[1];
                blo[2 * j2 + 1][0] = t[2]; blo[2 * j2 + 1][1] = t[3];
            }
#pragma unroll
            for (int i = 0; i < 2; i++)
#pragma unroll
                for (int j = 0; j < 4; j++)
                    mma16816(acc[i][j], ahi[i], bhi[j]);
#pragma unroll
            for (int i = 0; i < 2; i++)
#pragma unroll
                for (int j = 0; j < 4; j++)
                    mma16816(acc[i][j], ahi[i], blo[j]);
#pragma unroll
            for (int i = 0; i < 2; i++)
#pragma unroll
                for (int j = 0; j < 4; j++)
                    mma16816(acc[i][j], alo[i], bhi[j]);
        }
    }

    // ---- epilogue ----
#pragma unroll
    for (int i = 0; i < 2; i++) {
        const int mrow = row0 + warp_m * 32 + i * 16 + (lane >> 2);
#pragma unroll
        for (int j = 0; j < 4; j++) {
            const int ncol = col0 + warp_n * 32 + j * 8 + ((lane & 3) << 1);
            const float2 bv = *(const float2*)&bias[ncol];
            const float c0 = (acc[i][j][0] + bv.x) * oscale;
            const float c1 = (acc[i][j][1] + bv.y) * oscale;
            const float c2 = (acc[i][j][2] + bv.x) * oscale;
            const float c3 = (acc[i][j][3] + bv.y) * oscale;
            if (SPLIT_OUT) {
                __nv_bfloat162 h0 = __floats2bfloat162_rn(c0, c1);
                float2 hf0 = __bfloat1622float2(h0);
                __nv_bfloat162 l0 = __floats2bfloat162_rn(c0 - hf0.x, c1 - hf0.y);
                __nv_bfloat162 h1 = __floats2bfloat162_rn(c2, c3);
                float2 hf1 = __bfloat1622float2(h1);
                __nv_bfloat162 l1 = __floats2bfloat162_rn(c2 - hf1.x, c3 - hf1.y);
                *(__nv_bfloat162*)&Chi[(size_t)mrow * CDIM + ncol] = h0;
                *(__nv_bfloat162*)&Clo[(size_t)mrow * CDIM + ncol] = l0;
                *(__nv_bfloat162*)&Chi[(size_t)(mrow + 8) * CDIM + ncol] = h1;
                *(__nv_bfloat162*)&Clo[(size_t)(mrow + 8) * CDIM + ncol] = l1;
            } else {
                float2 o0, o1;
                o0.x = c0; o0.y = c1;
                o1.x = c2; o1.y = c3;
                *(float2*)&Cout[(size_t)mrow * CDIM + ncol] = o0;
                *(float2*)&Cout[(size_t)(mrow + 8) * CDIM + ncol] = o1;
            }
        }
    }
}

// ---------------------------------------------------------------------------
// Flash attention (causal): 128 threads, 2 CTAs/SM, TWO 64-row Q bands per CTA
//   sharing one KV stream. Q fragments are RE-LOADED from smem per band-tile
//   (not register-resident) to stay under the 255-reg cap — R9's spill fix.
//   2 KV buffers (64KB) + Q region (32KB) = 96KB/CTA.
// ---------------------------------------------------------------------------
#define KV_BUF 32768
#define O_KHI 0
#define O_KLO 8192
#define O_VHI 16384
#define O_VLO 24576
#define Q_OFF (2 * KV_BUF)
#define FA_SMEM (2 * KV_BUF + 32768)   // 98304

__global__ __launch_bounds__(128, 2) void flash_attn_mma(
    const __nv_bfloat16* __restrict__ Qhi, const __nv_bfloat16* __restrict__ Qlo,
    const __nv_bfloat16* __restrict__ Khi, const __nv_bfloat16* __restrict__ Klo,
    const __nv_bfloat16* __restrict__ Vhi, const __nv_bfloat16* __restrict__ Vlo,
    __nv_bfloat16* __restrict__ Ohi, __nv_bfloat16* __restrict__ Olo)
{
    extern __shared__ char smem[];
    const uint32_t sbase = smem_to_u32(smem);
    const int tid = threadIdx.x;
    const int lane = tid & 31;
    const int wid = tid >> 5;                      // 0..3
    const int qi = (gridDim.x - 1) - blockIdx.x;   // heavy CTAs first
    const int h = blockIdx.y;
    const int b = blockIdx.z;
    const int qrow0 = qi * 128;
    const int m0 = wid * 16;
    const int lr = lane & 7;
    const int lg = lane >> 3;

    const int nkt = 2 * qi + 2;   // band1's tile count; band0 uses nkt-1

    // ---- load Q (128 rows; hi at Q_OFF, lo at Q_OFF+16KB) ----
#pragma unroll
    for (int t = 0; t < 8; t++) {
        const int idx = tid + t * 128;             // 0..1023
        const int r = idx >> 3;
        const int c16 = (idx & 7) << 4;
        const uint32_t sw = SWZ128(r * 128 + c16);
        const size_t grow = (size_t)(b * SEQT + qrow0 + r) * CDIM + h * HDIM;
        CP16(sbase + Q_OFF + sw, (const char*)(Qhi + grow) + c16);
        CP16(sbase + Q_OFF + 16384 + sw, (const char*)(Qlo + grow) + c16);
    }
    CP_COMMIT();

    auto load_kv = [&](int kt) {
        const uint32_t sb = sbase + (uint32_t)(kt & 1) * KV_BUF;
#pragma unroll
        for (int t = 0; t < 4; t++) {
            const int idx = tid + t * 128;         // 0..511
            const int r = idx >> 3;
            const int c16 = (idx & 7) << 4;
            const uint32_t sw = SWZ128(r * 128 + c16);
            const size_t grow = (size_t)(b * SEQT + kt * 64 + r) * CDIM + h * HDIM;
            CP16(sb + O_KHI + sw, (const char*)(Khi + grow) + c16);
            CP16(sb + O_KLO + sw, (const char*)(Klo + grow) + c16);
            CP16(sb + O_VHI + sw, (const char*)(Vhi + grow) + c16);
            CP16(sb + O_VLO + sw, (const char*)(Vlo + grow) + c16);
        }
        CP_COMMIT();
    };
    load_kv(0);

    float oA[8][4], oB[8][4];
#pragma unroll
    for (int j = 0; j < 8; j++)
#pragma unroll
        for (int r = 0; r < 4; r++) { oA[j][r] = 0.0f; oB[j][r] = 0.0f; }
    float mRa[2] = {-1e30f, -1e30f}, lRa[2] = {0.0f, 0.0f};
    float mRb[2] = {-1e30f, -1e30f}, lRb[2] = {0.0f, 0.0f};

    // ---- QK for one band (Q frags loaded from smem per call) ----
    auto qk_band = [&](uint32_t kb, int band_off, float (&sc)[8][4]) {
#pragma unroll
        for (int j = 0; j < 8; j++)
#pragma unroll
            for (int r = 0; r < 4; r++) sc[j][r] = 0.0f;
#pragma unroll
        for (int s = 0; s < 4; s++) {
            uint32_t qh[4], ql[4];
            {
                const int rbase = band_off + m0 + ((lg & 1) << 3) + lr;
                const uint32_t sw = SWZ128(rbase * 128 + s * 32 + ((lg >> 1) << 4));
                ldsm_x4(qh, sbase + Q_OFF + sw);
                ldsm_x4(ql, sbase + Q_OFF + 16384 + sw);
            }
#pragma unroll
            for (int p = 0; p < 4; p++) {
                const uint32_t sw = SWZ128((p * 16 + ((lg >> 1) << 3) + lr) * 128
                                           + s * 32 + ((lg & 1) << 4));
                uint32_t kh[4], kl[4];
                ldsm_x4(kh, kb + O_KHI + sw);
                ldsm_x4(kl, kb + O_KLO + sw);
                mma16816(sc[2 * p],     qh, &kh[0]);
                mma16816(sc[2 * p + 1], qh, &kh[2]);
                mma16816(sc[2 * p],     qh, &kl[0]);
                mma16816(sc[2 * p + 1], qh, &kl[2]);
                mma16816(sc[2 * p],     ql, &kh[0]);
                mma16816(sc[2 * p + 1], ql, &kh[2]);
            }
        }
    };

    // ---- causal mask for one band (diagonal tile) ----
    auto mask_band = [&](int kt, int band_row0, float (&sc)[8][4]) {
        const int qg0 = band_row0 + m0 + (lane >> 2);
        const int qg1 = qg0 + 8;
#pragma unroll
        for (int j = 0; j < 8; j++) {
            const int kg = kt * 64 + j * 8 + ((lane & 3) << 1);
            if (kg > qg0)     sc[j][0] = -1e30f;
            if (kg + 1 > qg0) sc[j][1] = -1e30f;
            if (kg > qg1)     sc[j][2] = -1e30f;
            if (kg + 1 > qg1) sc[j][3] = -1e30f;
        }
    };

    // ---- online softmax + PV for one band ----
    auto sm_pv = [&](uint32_t kb, float (&sc)[8][4],
                     float (&mR)[2], float (&lR)[2], float (&o)[8][4]) {
        float mp0 = sc[0][0], mp1 = sc[0][2];
#pragma unroll
        for (int j = 0; j < 8; j++) {
            mp0 = fmaxf(mp0, fmaxf(sc[j][0], sc[j][1]));
            mp1 = fmaxf(mp1, fmaxf(sc[j][2], sc[j][3]));
        }
        mp0 = fmaxf(mp0, __shfl_xor_sync(0xffffffffu, mp0, 1));
        mp0 = fmaxf(mp0, __shfl_xor_sync(0xffffffffu, mp0, 2));
        mp1 = fmaxf(mp1, __shfl_xor_sync(0xffffffffu, mp1, 1));
        mp1 = fmaxf(mp1, __shfl_xor_sync(0xffffffffu, mp1, 2));
        const float mn0 = fmaxf(mR[0], mp0);
        const float mn1 = fmaxf(mR[1], mp1);
        const float f0 = fast_ex2(mR[0] - mn0);
        const float f1 = fast_ex2(mR[1] - mn1);
        float sum0 = 0.0f, sum1 = 0.0f;
#pragma unroll
        for (int j = 0; j < 8; j++) {
            sc[j][0] = fast_ex2(sc[j][0] - mn0);
            sc[j][1] = fast_ex2(sc[j][1] - mn0);
            sc[j][2] = fast_ex2(sc[j][2] - mn1);
            sc[j][3] = fast_ex2(sc[j][3] - mn1);
            sum0 += sc[j][0] + sc[j][1];
            sum1 += sc[j][2] + sc[j][3];
        }
        sum0 += __shfl_xor_sync(0xffffffffu, sum0, 1);
        sum0 += __shfl_xor_sync(0xffffffffu, sum0, 2);
        sum1 += __shfl_xor_sync(0xffffffffu, sum1, 1);
        sum1 += __shfl_xor_sync(0xffffffffu, sum1, 2);
        lR[0] = lR[0] * f0 + sum0;
        lR[1] = lR[1] * f1 + sum1;
        mR[0] = mn0;
        mR[1] = mn1;
#pragma unroll
        for (int j = 0; j < 8; j++) {
            o[j][0] *= f0; o[j][1] *= f0;
            o[j][2] *= f1; o[j][3] *= f1;
        }

#pragma unroll
        for (int s2 = 0; s2 < 4; s2++) {
            uint32_t ph[4], pl[4];
#pragma unroll
            for (int half = 0; half < 2; half++) {
                const int jt = 2 * s2 + half;
                __nv_bfloat162 h0 = __floats2bfloat162_rn(sc[jt][0], sc[jt][1]);
                float2 hf0 = __bfloat1622float2(h0);
                __nv_bfloat162 l0 =
                    __floats2bfloat162_rn(sc[jt][0] - hf0.x, sc[jt][1] - hf0.y);
                __nv_bfloat162 h1 = __floats2bfloat162_rn(sc[jt][2], sc[jt][3]);
                float2 hf1 = __bfloat1622float2(h1);
                __nv_bfloat162 l1 =
                    __floats2bfloat162_rn(sc[jt][2] - hf1.x, sc[jt][3] - hf1.y);
                ph[2 * half]     = *(uint32_t*)&h0;
                ph[2 * half + 1] = *(uint32_t*)&h1;
                pl[2 * half]     = *(uint32_t*)&l0;
                pl[2 * half + 1] = *(uint32_t*)&l1;
            }
#pragma unroll
            for (int dp = 0; dp < 4; dp++) {
                const uint32_t sw = SWZ128((s2 * 16 + ((lg & 1) << 3) + lr) * 128
                                           + dp * 32 + ((lg >> 1) << 4));
                uint32_t vh[4], vl[4];
                ldsm_x4_trans(vh, kb + O_VHI + sw);
                ldsm_x4_trans(vl, kb + O_VLO + sw);
                mma16816(o[2 * dp],     ph, &vh[0]);
                mma16816(o[2 * dp + 1], ph, &vh[2]);
                mma16816(o[2 * dp],     ph, &vl[0]);
                mma16816(o[2 * dp + 1], ph, &vl[2]);
                mma16816(o[2 * dp],     pl, &vh[0]);
                mma16816(o[2 * dp + 1], pl, &vh[2]);
            }
        }
    };

    float sacc[8][4];

    for (int kt = 0; kt < nkt; kt++) {
        CP_WAIT0();        // Q (first iter) + kv(kt) landed for all cp.async
        __syncthreads();   // everyone's writes visible; prev-iter reads done
        if (kt + 1 < nkt) load_kv(kt + 1);
        const uint32_t kb = sbase + (uint32_t)(kt & 1) * KV_BUF;

        // band 1 (rows qrow0+64..): active for all kt; diagonal at kt == nkt-1
        qk_band(kb, 64, sacc);
        if (kt == nkt - 1) mask_band(kt, qrow0 + 64, sacc);
        sm_pv(kb, sacc, mRb, lRb, oB);

        // band 0 (rows qrow0..): active for kt <= nkt-2; diagonal at nkt-2
        if (kt <= nkt - 2) {
            qk_band(kb, 0, sacc);
            if (kt == nkt - 2) mask_band(kt, qrow0, sacc);
            sm_pv(kb, sacc, mRa, lRa, oA);
        }
    }

    // ---- normalize + write both bands (bf16 hi/lo) ----
#pragma unroll
    for (int band = 0; band < 2; band++) {
        const float* lR = band ? lRb : lRa;
        float (&o)[8][4] = band ? oB : oA;
        const float inv0 = 1.0f / lR[0];
        const float inv1 = 1.0f / lR[1];
        const int r0 = b * SEQT + qrow0 + band * 64 + m0 + (lane >> 2);
#pragma unroll
        for (int j = 0; j < 8; j++) {
            const int col = h * HDIM + j * 8 + ((lane & 3) << 1);
            const float c0 = o[j][0] * inv0, c1 = o[j][1] * inv0;
            const float c2 = o[j][2] * inv1, c3 = o[j][3] * inv1;
            __nv_bfloat162 h0 = __floats2bfloat162_rn(c0, c1);
            float2 hf0 = __bfloat1622float2(h0);
            __nv_bfloat162 l0 = __floats2bfloat162_rn(c0 - hf0.x, c1 - hf0.y);
            __nv_bfloat162 h1 = __floats2bfloat162_rn(c2, c3);
            float2 hf1 = __bfloat1622float2(h1);
            __nv_bfloat162 l1 = __floats2bfloat162_rn(c2 - hf1.x, c3 - hf1.y);
            *(__nv_bfloat162*)&Ohi[(size_t)r0 * CDIM + col] = h0;
            *(__nv_bfloat162*)&Olo[(size_t)r0 * CDIM + col] = l0;
            *(__nv_bfloat162*)&Ohi[(size_t)(r0 + 8) * CDIM + col] = h1;
            *(__nv_bfloat162*)&Olo[(size_t)(r0 + 8) * CDIM + col] = l1;
        }
    }
}

// ---------------------------------------------------------------------------
// Launch
// ---------------------------------------------------------------------------
extern "C" void kernel_launch(void* const* d_in, const int* in_sizes, int n_in,
                              void* d_out, int out_size)
{
    (void)in_sizes; (void)n_in; (void)out_size;
    const float* x  = (const float*)d_in[0];
    const float* Wq = (const float*)d_in[1];
    const float* bq = (const float*)d_in[2];
    const float* Wk = (const float*)d_in[3];
    const float* bk = (const float*)d_in[4];
    const float* Wv = (const float*)d_in[5];
    const float* bv = (const float*)d_in[6];
    const float* Wo = (const float*)d_in[7];
    const float* bo = (const float*)d_in[8];
    float* out = (float*)d_out;

    __nv_bfloat16 *xhi, *xlo, *qhi, *qlo, *khi, *klo, *vhi, *vlo, *ahi, *alo, *wthi, *wtlo;
    cudaGetSymbolAddress((void**)&xhi,  g_xhi);
    cudaGetSymbolAddress((void**)&xlo,  g_xlo);
    cudaGetSymbolAddress((void**)&qhi,  g_qhi);
    cudaGetSymbolAddress((void**)&qlo,  g_qlo);
    cudaGetSymbolAddress((void**)&khi,  g_khi);
    cudaGetSymbolAddress((void**)&klo,  g_klo);
    cudaGetSymbolAddress((void**)&vhi,  g_vhi);
    cudaGetSymbolAddress((void**)&vlo,  g_vlo);
    cudaGetSymbolAddress((void**)&ahi,  g_ahi);
    cudaGetSymbolAddress((void**)&alo,  g_alo);
    cudaGetSymbolAddress((void**)&wthi, g_wthi);
    cudaGetSymbolAddress((void**)&wtlo, g_wtlo);

    cudaFuncSetAttribute(gemm_mma_split<true>,
                         cudaFuncAttributeMaxDynamicSharedMemorySize, GEMM_SMEM);
    cudaFuncSetAttribute(gemm_mma_split<false>,
                         cudaFuncAttributeMaxDynamicSharedMemorySize, GEMM_SMEM);
    cudaFuncSetAttribute(flash_attn_mma,
                         cudaFuncAttributeMaxDynamicSharedMemorySize, FA_SMEM);

    const int nelem = MROWS * CDIM;

    split_f32<<<(nelem + 255) / 256, 256>>>(x, xhi, xlo, nelem);

    dim3 wt_grid(CDIM / 32, CDIM / 32, 4);
    dim3 wt_blk(32, 8);
    wtrans_split4<<<wt_grid, wt_blk>>>(Wq, Wk, Wv, Wo, wthi, wtlo);

    dim3 qkv_grid(36, MROWS / 128);
    gemm_mma_split<true><<<qkv_grid, 256, GEMM_SMEM>>>(
        xhi, xlo, wthi, wtlo, bq, bk, bv,
        nullptr, qhi, qlo, khi, klo, vhi, vlo);

    dim3 fa_grid(SEQT / 128, NHEAD, BATCH);    // (16, 12, 4) = 768 CTAs
    flash_attn_mma<<<fa_grid, 128, FA_SMEM>>>(qhi, qlo, khi, klo, vhi, vlo, ahi, alo);

    dim3 wo_grid(12, MROWS / 128);
    gemm_mma_split<false><<<wo_grid, 256, GEMM_SMEM>>>(
        ahi, alo, wthi, wtlo, bo, nullptr, nullptr,
        out, nullptr, nullptr, nullptr, nullptr, nullptr, nullptr);
}

// round 11
// speedup vs baseline: 1.0715x; 1.0509x over previous
#include <cuda_runtime.h>
#include <cuda_bf16.h>
#include <math.h>
#include <stdint.h>

#define BATCH 4
#define SEQT 2048
#define CDIM 768
#define NHEAD 12
#define HDIM 64
#define MROWS (BATCH * SEQT)   // 8192

// ---------------------------------------------------------------------------
// Scratch (allocation-free rule: device globals)
// ---------------------------------------------------------------------------
__device__ __nv_bfloat16 g_xhi[(size_t)MROWS * CDIM];
__device__ __nv_bfloat16 g_xlo[(size_t)MROWS * CDIM];
__device__ __nv_bfloat16 g_qhi[(size_t)MROWS * CDIM];
__device__ __nv_bfloat16 g_qlo[(size_t)MROWS * CDIM];
__device__ __nv_bfloat16 g_khi[(size_t)MROWS * CDIM];
__device__ __nv_bfloat16 g_klo[(size_t)MROWS * CDIM];
__device__ __nv_bfloat16 g_vhi[(size_t)MROWS * CDIM];
__device__ __nv_bfloat16 g_vlo[(size_t)MROWS * CDIM];
__device__ __nv_bfloat16 g_ahi[(size_t)MROWS * CDIM];
__device__ __nv_bfloat16 g_alo[(size_t)MROWS * CDIM];
// transposed+split weights: [4][N=CDIM][K=CDIM] (order: Wq, Wk, Wv, Wo)
__device__ __nv_bfloat16 g_wthi[4 * (size_t)CDIM * CDIM];
__device__ __nv_bfloat16 g_wtlo[4 * (size_t)CDIM * CDIM];

// ---------------------------------------------------------------------------
// PTX helpers (sm_80-era: legal under .target sm_103)
// ---------------------------------------------------------------------------
__device__ __forceinline__ uint32_t smem_to_u32(const void* p) {
    uint32_t a;
    asm("{ .reg .u64 t; cvta.to.shared.u64 t, %1; cvt.u32.u64 %0, t; }"
        : "=r"(a) : "l"(p));
    return a;
}

__device__ __forceinline__ void ldsm_x4(uint32_t* r, uint32_t addr) {
    asm volatile("ldmatrix.sync.aligned.m8n8.x4.shared.b16 {%0,%1,%2,%3}, [%4];"
        : "=r"(r[0]), "=r"(r[1]), "=r"(r[2]), "=r"(r[3]) : "r"(addr));
}

__device__ __forceinline__ void ldsm_x4_trans(uint32_t* r, uint32_t addr) {
    asm volatile("ldmatrix.sync.aligned.m8n8.x4.trans.shared.b16 {%0,%1,%2,%3}, [%4];"
        : "=r"(r[0]), "=r"(r[1]), "=r"(r[2]), "=r"(r[3]) : "r"(addr));
}

__device__ __forceinline__ void mma16816(float* c, const uint32_t* a, const uint32_t* b) {
    asm volatile(
        "mma.sync.aligned.m16n8k16.row.col.f32.bf16.bf16.f32 "
        "{%0,%1,%2,%3}, {%4,%5,%6,%7}, {%8,%9}, {%0,%1,%2,%3};"
        : "+f"(c[0]), "+f"(c[1]), "+f"(c[2]), "+f"(c[3])
        : "r"(a[0]), "r"(a[1]), "r"(a[2]), "r"(a[3]), "r"(b[0]), "r"(b[1]));
}

__device__ __forceinline__ float fast_ex2(float x) {
    float y;
    asm("ex2.approx.f32 %0, %1;" : "=f"(y) : "f"(x));
    return y;
}

#define CP16(dst, src) \
    asm volatile("cp.async.cg.shared.global [%0], [%1], 16;" \
                 :: "r"(dst), "l"(src) : "memory")
#define CP_COMMIT() asm volatile("cp.async.commit_group;" ::: "memory")
#define CP_WAIT2()  asm volatile("cp.async.wait_group 2;" ::: "memory")
#define CP_WAIT1()  asm volatile("cp.async.wait_group 1;" ::: "memory")
#define CP_WAIT0()  asm volatile("cp.async.wait_group 0;" ::: "memory")

#define SWZ128(off) ((off) ^ (((off) >> 3) & 0x70))

// 0.125 * log2(e): folded into Q at the QKV GEMM epilogue
#define QK_SCALE 0.18033688011112042f

// ---------------------------------------------------------------------------
// Conversion kernels
// ---------------------------------------------------------------------------
__global__ void split_f32(const float* __restrict__ in,
                          __nv_bfloat16* __restrict__ hi,
                          __nv_bfloat16* __restrict__ lo, int n) {
    int i = blockIdx.x * blockDim.x + threadIdx.x;
    if (i < n) {
        float v = in[i];
        __nv_bfloat16 h = __float2bfloat16(v);
        float r = v - __bfloat162float(h);
        hi[i] = h;
        lo[i] = __float2bfloat16(r);
    }
}

__global__ void wtrans_split4(const float* __restrict__ W0, const float* __restrict__ W1,
                              const float* __restrict__ W2, const float* __restrict__ W3,
                              __nv_bfloat16* __restrict__ hi,
                              __nv_bfloat16* __restrict__ lo) {
    __shared__ float t[32][33];
    const int z = blockIdx.z;
    const float* W = (z == 0) ? W0 : (z == 1) ? W1 : (z == 2) ? W2 : W3;
    const size_t zoff = (size_t)z * CDIM * CDIM;
    const int kx = blockIdx.x * 32;
    const int nx = blockIdx.y * 32;
    const int tx = threadIdx.x, ty = threadIdx.y;
    for (int j = ty; j < 32; j += 8)
        t[j][tx] = W[(size_t)(kx + j) * CDIM + nx + tx];
    __syncthreads();
    for (int j = ty; j < 32; j += 8) {
        float v = t[tx][j];
        __nv_bfloat16 h = __float2bfloat16(v);
        float r = v - __bfloat162float(h);
        size_t o = zoff + (size_t)(nx + j) * CDIM + kx + tx;
        hi[o] = h;
        lo[o] = __float2bfloat16(r);
    }
}

// ---------------------------------------------------------------------------
// mma.sync split-bf16 GEMM, 128x64 tile, 2 stages, 2 CTAs/SM. (unchanged)
// ---------------------------------------------------------------------------
#define GK 64
#define NCHUNK (CDIM / GK)        // 12
#define CH_BYTES 49152
#define GEMM_SMEM (2 * CH_BYTES)  // 98304
#define T_AHI 0
#define T_ALO 16384
#define T_BHI 32768
#define T_BLO 40960

template <bool SPLIT_OUT>
__global__ __launch_bounds__(256, 2) void gemm_mma_split(
    const __nv_bfloat16* __restrict__ Ahi, const __nv_bfloat16* __restrict__ Alo,
    const __nv_bfloat16* __restrict__ Wthi, const __nv_bfloat16* __restrict__ Wtlo,
    const float* __restrict__ b0, const float* __restrict__ b1,
    const float* __restrict__ b2,
    float* __restrict__ Cout,
    __nv_bfloat16* __restrict__ C0hi, __nv_bfloat16* __restrict__ C0lo,
    __nv_bfloat16* __restrict__ C1hi, __nv_bfloat16* __restrict__ C1lo,
    __nv_bfloat16* __restrict__ C2hi, __nv_bfloat16* __restrict__ C2lo)
{
    extern __shared__ char smem[];
    const uint32_t sbase = smem_to_u32(smem);
    const int tid = threadIdx.x;
    const int lane = tid & 31;
    const int wid = tid >> 5;
    const int warp_m = wid >> 1;
    const int warp_n = wid & 1;
    const int row0 = blockIdx.y * 128;

    int wsel, col0;
    if (SPLIT_OUT) { wsel = blockIdx.x / 12; col0 = (blockIdx.x % 12) * 64; }
    else           { wsel = 3;              col0 = blockIdx.x * 64; }

    const size_t WSZ = (size_t)CDIM * CDIM;
    const __nv_bfloat16* Bhi = Wthi + (size_t)wsel * WSZ;
    const __nv_bfloat16* Blo = Wtlo + (size_t)wsel * WSZ;
    const float* bias = SPLIT_OUT ? (wsel == 0 ? b0 : wsel == 1 ? b1 : b2) : b0;
    __nv_bfloat16* Chi = SPLIT_OUT ? (wsel == 0 ? C0hi : wsel == 1 ? C1hi : C2hi) : nullptr;
    __nv_bfloat16* Clo = SPLIT_OUT ? (wsel == 0 ? C0lo : wsel == 1 ? C1lo : C2lo) : nullptr;
    const float oscale = (SPLIT_OUT && wsel == 0) ? QK_SCALE : 1.0f;

    const int lrow = lane & 7;
    const int lgrp = lane >> 3;
    const int a_roff = ((lgrp & 1) << 3) + lrow;
    const int a_kh   = (lgrp >> 1) << 4;
    const int b_roff = ((lgrp >> 1) << 3) + lrow;
    const int b_kh   = (lgrp & 1) << 4;

    const int ld_r   = tid >> 3;
    const int ld_c16 = (tid & 7) << 4;

    float acc[2][4][4];
#pragma unroll
    for (int i = 0; i < 2; i++)
#pragma unroll
        for (int j = 0; j < 4; j++)
#pragma unroll
            for (int r = 0; r < 4; r++) acc[i][j][r] = 0.0f;

    auto load_chunk = [&](int kc, int stage) {
        const uint32_t sb = sbase + stage * CH_BYTES;
        const int kcol = kc * GK;
#pragma unroll
        for (int t = 0; t < 4; t++) {
            const int r = ld_r + t * 32;
            const uint32_t sw = SWZ128(r * 128 + ld_c16);
            const char* pa  = (const char*)(Ahi + (size_t)(row0 + r) * CDIM + kcol) + ld_c16;
            const char* pal = (const char*)(Alo + (size_t)(row0 + r) * CDIM + kcol) + ld_c16;
            CP16(sb + T_AHI + sw, pa);
            CP16(sb + T_ALO + sw, pal);
        }
#pragma unroll
        for (int t = 0; t < 2; t++) {
            const int idx = tid + t * 256;
            const int r = idx >> 3;
            const int c16 = (idx & 7) << 4;
            const uint32_t sw = SWZ128(r * 128 + c16);
            const char* pb  = (const char*)(Bhi + (size_t)(col0 + r) * CDIM + kcol) + c16;
            const char* pbl = (const char*)(Blo + (size_t)(col0 + r) * CDIM + kcol) + c16;
            CP16(sb + T_BHI + sw, pb);
            CP16(sb + T_BLO + sw, pbl);
        }
        CP_COMMIT();
    };

    load_chunk(0, 0);

    for (int kc = 0; kc < NCHUNK; kc++) {
        CP_WAIT0();
        __syncthreads();
        if (kc + 1 < NCHUNK) load_chunk(kc + 1, (kc + 1) & 1);

        const uint32_t sb = sbase + (kc & 1) * CH_BYTES;
#pragma unroll
        for (int s = 0; s < 4; s++) {
            const int kb = s * 32;
            uint32_t ahi[2][4], alo[2][4];
#pragma unroll
            for (int i = 0; i < 2; i++) {
                const uint32_t off =
                    SWZ128((warp_m * 32 + i * 16 + a_roff) * 128 + kb + a_kh);
                ldsm_x4(ahi[i], sb + T_AHI + off);
                ldsm_x4(alo[i], sb + T_ALO + off);
            }
            uint32_t bhi[4][2], blo[4][2];
#pragma unroll
            for (int j2 = 0; j2 < 2; j2++) {
                const uint32_t off =
                    SWZ128((warp_n * 32 + j2 * 16 + b_roff) * 128 + kb + b_kh);
                uint32_t t[4];
                ldsm_x4(t, sb + T_BHI + off);
                bhi[2 * j2][0] = t[0]; bhi[2 * j2][1] = t[1];
                bhi[2 * j2 + 1][0] = t[2]; bhi[2 * j2 + 1][1] = t[3];
                ldsm_x4(t, sb + T_BLO + off);
                blo[2 * j2][0] = t[0]; blo[2 * j2][1] = t[1];
                blo[2 * j2 + 1][0] = t[2]; blo[2 * j2 + 1][1] = t[3];
            }
#pragma unroll
            for (int i = 0; i < 2; i++)
#pragma unroll
                for (int j = 0; j < 4; j++)
                    mma16816(acc[i][j], ahi[i], bhi[j]);
#pragma unroll
            for (int i = 0; i < 2; i++)
#pragma unroll
                for (int j = 0; j < 4; j++)
                    mma16816(acc[i][j], ahi[i], blo[j]);
#pragma unroll
            for (int i = 0; i < 2; i++)
#pragma unroll
                for (int j = 0; j < 4; j++)
                    mma16816(acc[i][j], alo[i], bhi[j]);
        }
    }

    // ---- epilogue ----
#pragma unroll
    for (int i = 0; i < 2; i++) {
        const int mrow = row0 + warp_m * 32 + i * 16 + (lane >> 2);
#pragma unroll
        for (int j = 0; j < 4; j++) {
            const int ncol = col0 + warp_n * 32 + j * 8 + ((lane & 3) << 1);
            const float2 bv = *(const float2*)&bias[ncol];
            const float c0 = (acc[i][j][0] + bv.x) * oscale;
            const float c1 = (acc[i][j][1] + bv.y) * oscale;
            const float c2 = (acc[i][j][2] + bv.x) * oscale;
            const float c3 = (acc[i][j][3] + bv.y) * oscale;
            if (SPLIT_OUT) {
                __nv_bfloat162 h0 = __floats2bfloat162_rn(c0, c1);
                float2 hf0 = __bfloat1622float2(h0);
                __nv_bfloat162 l0 = __floats2bfloat162_rn(c0 - hf0.x, c1 - hf0.y);
                __nv_bfloat162 h1 = __floats2bfloat162_rn(c2, c3);
                float2 hf1 = __bfloat1622float2(h1);
                __nv_bfloat162 l1 = __floats2bfloat162_rn(c2 - hf1.x, c3 - hf1.y);
                *(__nv_bfloat162*)&Chi[(size_t)mrow * CDIM + ncol] = h0;
                *(__nv_bfloat162*)&Clo[(size_t)mrow * CDIM + ncol] = l0;
                *(__nv_bfloat162*)&Chi[(size_t)(mrow + 8) * CDIM + ncol] = h1;
                *(__nv_bfloat162*)&Clo[(size_t)(mrow + 8) * CDIM + ncol] = l1;
            } else {
                float2 o0, o1;
                o0.x = c0; o0.y = c1;
                o1.x = c2; o1.y = c3;
                *(float2*)&Cout[(size_t)mrow * CDIM + ncol] = o0;
                *(float2*)&Cout[(size_t)(mrow + 8) * CDIM + ncol] = o1;
            }
        }
    }
}

// ---------------------------------------------------------------------------
// Flash attention (causal): R8 structure (BQ=64, 128 threads, 2 CTAs/SM,
//   register-resident Q) + THIRD KV buffer for prefetch distance 2.
//   3 KV buffers (96KB) + Q region (16KB) = 112.6KB/CTA; 2 CTAs = 225KB/SM.
//   Q pre-scaled by 0.125*log2(e) -> softmax uses raw ex2.
// ---------------------------------------------------------------------------
#define KV_BUF 32768
#define O_KHI 0
#define O_KLO 8192
#define O_VHI 16384
#define O_VLO 24576
#define Q_OFF (3 * KV_BUF)
#define FA_SMEM (3 * KV_BUF + 16384)   // 114688

__global__ __launch_bounds__(128, 2) void flash_attn_mma(
    const __nv_bfloat16* __restrict__ Qhi, const __nv_bfloat16* __restrict__ Qlo,
    const __nv_bfloat16* __restrict__ Khi, const __nv_bfloat16* __restrict__ Klo,
    const __nv_bfloat16* __restrict__ Vhi, const __nv_bfloat16* __restrict__ Vlo,
    __nv_bfloat16* __restrict__ Ohi, __nv_bfloat16* __restrict__ Olo)
{
    extern __shared__ char smem[];
    const uint32_t sbase = smem_to_u32(smem);
    const int tid = threadIdx.x;
    const int lane = tid & 31;
    const int wid = tid >> 5;                      // 0..3
    const int qi = (gridDim.x - 1) - blockIdx.x;   // heavy CTAs first
    const int h = blockIdx.y;
    const int b = blockIdx.z;
    const int qrow0 = qi * 64;
    const int m0 = wid * 16;
    const int lr = lane & 7;
    const int lg = lane >> 3;

    const int nkt = qi + 1;

    // ---- load Q tile (64 rows; hi at Q_OFF, lo at Q_OFF+8KB) ----
#pragma unroll
    for (int t = 0; t < 4; t++) {
        const int idx = tid + t * 128;             // 0..511
        const int r = idx >> 3;
        const int c16 = (idx & 7) << 4;
        const uint32_t sw = SWZ128(r * 128 + c16);
        const size_t grow = (size_t)(b * SEQT + qrow0 + r) * CDIM + h * HDIM;
        CP16(sbase + Q_OFF + sw, (const char*)(Qhi + grow) + c16);
        CP16(sbase + Q_OFF + 8192 + sw, (const char*)(Qlo + grow) + c16);
    }
    CP_COMMIT();

    auto load_kv = [&](int kt) {
        const uint32_t sb = sbase + (uint32_t)(kt % 3) * KV_BUF;
#pragma unroll
        for (int t = 0; t < 4; t++) {
            const int idx = tid + t * 128;         // 0..511
            const int r = idx >> 3;
            const int c16 = (idx & 7) << 4;
            const uint32_t sw = SWZ128(r * 128 + c16);
            const size_t grow = (size_t)(b * SEQT + kt * 64 + r) * CDIM + h * HDIM;
            CP16(sb + O_KHI + sw, (const char*)(Khi + grow) + c16);
            CP16(sb + O_KLO + sw, (const char*)(Klo + grow) + c16);
            CP16(sb + O_VHI + sw, (const char*)(Vhi + grow) + c16);
            CP16(sb + O_VLO + sw, (const char*)(Vlo + grow) + c16);
        }
        CP_COMMIT();
    };
    load_kv(0);
    if (nkt > 1) load_kv(1);

    // ---- Q landed for all threads (kv0/kv1 may fly); hoist Q fragments ----
    if (nkt > 1) { CP_WAIT2(); } else { CP_WAIT1(); }
    __syncthreads();
    uint32_t qfh[4][4], qfl[4][4];
#pragma unroll
    for (int s = 0; s < 4; s++) {
        const uint32_t sw = SWZ128((m0 + ((lg & 1) << 3) + lr) * 128
                                   + s * 32 + ((lg >> 1) << 4));
        ldsm_x4(qfh[s], sbase + Q_OFF + sw);
        ldsm_x4(qfl[s], sbase + Q_OFF + 8192 + sw);
    }

    float o[8][4];
#pragma unroll
    for (int j = 0; j < 8; j++)
#pragma unroll
        for (int r = 0; r < 4; r++) o[j][r] = 0.0f;
    float mR[2] = {-1e30f, -1e30f};
    float lR[2] = {0.0f, 0.0f};

    for (int kt = 0; kt < nkt; kt++) {
        // kv(kt) must land; kv(kt+1) may remain in flight (distance-2 pipe)
        if (kt + 1 < nkt) { CP_WAIT1(); } else { CP_WAIT0(); }
        __syncthreads();   // everyone's writes visible; prev-iter reads done
        if (kt + 2 < nkt) load_kv(kt + 2);
        const uint32_t kb = sbase + (uint32_t)(kt % 3) * KV_BUF;

        // ---- S = Q @ K^T (split bf16, 3 combos) ----
        float sacc[8][4];
#pragma unroll
        for (int j = 0; j < 8; j++)
#pragma unroll
            for (int r = 0; r < 4; r++) sacc[j][r] = 0.0f;

#pragma unroll
        for (int s = 0; s < 4; s++) {
#pragma unroll
            for (int p = 0; p < 4; p++) {
                const uint32_t sw = SWZ128((p * 16 + ((lg >> 1) << 3) + lr) * 128
                                           + s * 32 + ((lg & 1) << 4));
                uint32_t kh[4], kl[4];
                ldsm_x4(kh, kb + O_KHI + sw);
                ldsm_x4(kl, kb + O_KLO + sw);
                mma16816(sacc[2 * p],     qfh[s], &kh[0]);
                mma16816(sacc[2 * p + 1], qfh[s], &kh[2]);
                mma16816(sacc[2 * p],     qfh[s], &kl[0]);
                mma16816(sacc[2 * p + 1], qfh[s], &kl[2]);
                mma16816(sacc[2 * p],     qfl[s], &kh[0]);
                mma16816(sacc[2 * p + 1], qfl[s], &kh[2]);
            }
        }

        // ---- causal mask (only the diagonal tile kt == qi) ----
        if (kt == nkt - 1) {
            const int qg0 = qrow0 + m0 + (lane >> 2);
            const int qg1 = qg0 + 8;
#pragma unroll
            for (int j = 0; j < 8; j++) {
                const int kg = kt * 64 + j * 8 + ((lane & 3) << 1);
                if (kg > qg0)     sacc[j][0] = -1e30f;
                if (kg + 1 > qg0) sacc[j][1] = -1e30f;
                if (kg > qg1)     sacc[j][2] = -1e30f;
                if (kg + 1 > qg1) sacc[j][3] = -1e30f;
            }
        }

        // ---- online softmax (scores already in log2 units) ----
        float mp0 = sacc[0][0], mp1 = sacc[0][2];
#pragma unroll
        for (int j = 0; j < 8; j++) {
            mp0 = fmaxf(mp0, fmaxf(sacc[j][0], sacc[j][1]));
            mp1 = fmaxf(mp1, fmaxf(sacc[j][2], sacc[j][3]));
        }
        mp0 = fmaxf(mp0, __shfl_xor_sync(0xffffffffu, mp0, 1));
        mp0 = fmaxf(mp0, __shfl_xor_sync(0xffffffffu, mp0, 2));
        mp1 = fmaxf(mp1, __shfl_xor_sync(0xffffffffu, mp1, 1));
        mp1 = fmaxf(mp1, __shfl_xor_sync(0xffffffffu, mp1, 2));
        const float mn0 = fmaxf(mR[0], mp0);
        const float mn1 = fmaxf(mR[1], mp1);
        const float f0 = fast_ex2(mR[0] - mn0);
        const float f1 = fast_ex2(mR[1] - mn1);
        float sum0 = 0.0f, sum1 = 0.0f;
#pragma unroll
        for (int j = 0; j < 8; j++) {
            sacc[j][0] = fast_ex2(sacc[j][0] - mn0);
            sacc[j][1] = fast_ex2(sacc[j][1] - mn0);
            sacc[j][2] = fast_ex2(sacc[j][2] - mn1);
            sacc[j][3] = fast_ex2(sacc[j][3] - mn1);
            sum0 += sacc[j][0] + sacc[j][1];
            sum1 += sacc[j][2] + sacc[j][3];
        }
        sum0 += __shfl_xor_sync(0xffffffffu, sum0, 1);
        sum0 += __shfl_xor_sync(0xffffffffu, sum0, 2);
        sum1 += __shfl_xor_sync(0xffffffffu, sum1, 1);
        sum1 += __shfl_xor_sync(0xffffffffu, sum1, 2);
        lR[0] = lR[0] * f0 + sum0;
        lR[1] = lR[1] * f1 + sum1;
        mR[0] = mn0;
        mR[1] = mn1;
#pragma unroll
        for (int j = 0; j < 8; j++) {
            o[j][0] *= f0; o[j][1] *= f0;
            o[j][2] *= f1; o[j][3] *= f1;
        }

        // ---- O += P @ V (P split in registers, V split from smem) ----
#pragma unroll
        for (int s2 = 0; s2 < 4; s2++) {
            uint32_t ph[4], pl[4];
#pragma unroll
            for (int half = 0; half < 2; half++) {
                const int jt = 2 * s2 + half;
                __nv_bfloat162 h0 = __floats2bfloat162_rn(sacc[jt][0], sacc[jt][1]);
                float2 hf0 = __bfloat1622float2(h0);
                __nv_bfloat162 l0 =
                    __floats2bfloat162_rn(sacc[jt][0] - hf0.x, sacc[jt][1] - hf0.y);
                __nv_bfloat162 h1 = __floats2bfloat162_rn(sacc[jt][2], sacc[jt][3]);
                float2 hf1 = __bfloat1622float2(h1);
                __nv_bfloat162 l1 =
                    __floats2bfloat162_rn(sacc[jt][2] - hf1.x, sacc[jt][3] - hf1.y);
                ph[2 * half]     = *(uint32_t*)&h0;
                ph[2 * half + 1] = *(uint32_t*)&h1;
                pl[2 * half]     = *(uint32_t*)&l0;
                pl[2 * half + 1] = *(uint32_t*)&l1;
            }
#pragma unroll
            for (int dp = 0; dp < 4; dp++) {
                const uint32_t sw = SWZ128((s2 * 16 + ((lg & 1) << 3) + lr) * 128
                                           + dp * 32 + ((lg >> 1) << 4));
                uint32_t vh[4], vl[4];
                ldsm_x4_trans(vh, kb + O_VHI + sw);
                ldsm_x4_trans(vl, kb + O_VLO + sw);
                mma16816(o[2 * dp],     ph, &vh[0]);
                mma16816(o[2 * dp + 1], ph, &vh[2]);
                mma16816(o[2 * dp],     ph, &vl[0]);
                mma16816(o[2 * dp + 1], ph, &vl[2]);
                mma16816(o[2 * dp],     pl, &vh[0]);
                mma16816(o[2 * dp + 1], pl, &vh[2]);
            }
        }
    }

    // ---- normalize + write bf16 hi/lo ----
    const float inv0 = 1.0f / lR[0];
    const float inv1 = 1.0f / lR[1];
    const int r0 = b * SEQT + qrow0 + m0 + (lane >> 2);
#pragma unroll
    for (int j = 0; j < 8; j++) {
        const int col = h * HDIM + j * 8 + ((lane & 3) << 1);
        const float c0 = o[j][0] * inv0, c1 = o[j][1] * inv0;
        const float c2 = o[j][2] * inv1, c3 = o[j][3] * inv1;
        __nv_bfloat162 h0 = __floats2bfloat162_rn(c0, c1);
        float2 hf0 = __bfloat1622float2(h0);
        __nv_bfloat162 l0 = __floats2bfloat162_rn(c0 - hf0.x, c1 - hf0.y);
        __nv_bfloat162 h1 = __floats2bfloat162_rn(c2, c3);
        float2 hf1 = __bfloat1622float2(h1);
        __nv_bfloat162 l1 = __floats2bfloat162_rn(c2 - hf1.x, c3 - hf1.y);
        *(__nv_bfloat162*)&Ohi[(size_t)r0 * CDIM + col] = h0;
        *(__nv_bfloat162*)&Olo[(size_t)r0 * CDIM + col] = l0;
        *(__nv_bfloat162*)&Ohi[(size_t)(r0 + 8) * CDIM + col] = h1;
        *(__nv_bfloat162*)&Olo[(size_t)(r0 + 8) * CDIM + col] = l1;
    }
}

// ---------------------------------------------------------------------------
// Launch
// ---------------------------------------------------------------------------
extern "C" void kernel_launch(void* const* d_in, const int* in_sizes, int n_in,
                              void* d_out, int out_size)
{
    (void)in_sizes; (void)n_in; (void)out_size;
    const float* x  = (const float*)d_in[0];
    const float* Wq = (const float*)d_in[1];
    const float* bq = (const float*)d_in[2];
    const float* Wk = (const float*)d_in[3];
    const float* bk = (const float*)d_in[4];
    const float* Wv = (const float*)d_in[5];
    const float* bv = (const float*)d_in[6];
    const float* Wo = (const float*)d_in[7];
    const float* bo = (const float*)d_in[8];
    float* out = (float*)d_out;

    __nv_bfloat16 *xhi, *xlo, *qhi, *qlo, *khi, *klo, *vhi, *vlo, *ahi, *alo, *wthi, *wtlo;
    cudaGetSymbolAddress((void**)&xhi,  g_xhi);
    cudaGetSymbolAddress((void**)&xlo,  g_xlo);
    cudaGetSymbolAddress((void**)&qhi,  g_qhi);
    cudaGetSymbolAddress((void**)&qlo,  g_qlo);
    cudaGetSymbolAddress((void**)&khi,  g_khi);
    cudaGetSymbolAddress((void**)&klo,  g_klo);
    cudaGetSymbolAddress((void**)&vhi,  g_vhi);
    cudaGetSymbolAddress((void**)&vlo,  g_vlo);
    cudaGetSymbolAddress((void**)&ahi,  g_ahi);
    cudaGetSymbolAddress((void**)&alo,  g_alo);
    cudaGetSymbolAddress((void**)&wthi, g_wthi);
    cudaGetSymbolAddress((void**)&wtlo, g_wtlo);

    cudaFuncSetAttribute(gemm_mma_split<true>,
                         cudaFuncAttributeMaxDynamicSharedMemorySize, GEMM_SMEM);
    cudaFuncSetAttribute(gemm_mma_split<false>,
                         cudaFuncAttributeMaxDynamicSharedMemorySize, GEMM_SMEM);
    cudaFuncSetAttribute(flash_attn_mma,
                         cudaFuncAttributeMaxDynamicSharedMemorySize, FA_SMEM);

    const int nelem = MROWS * CDIM;

    split_f32<<<(nelem + 255) / 256, 256>>>(x, xhi, xlo, nelem);

    dim3 wt_grid(CDIM / 32, CDIM / 32, 4);
    dim3 wt_blk(32, 8);
    wtrans_split4<<<wt_grid, wt_blk>>>(Wq, Wk, Wv, Wo, wthi, wtlo);

    dim3 qkv_grid(36, MROWS / 128);
    gemm_mma_split<true><<<qkv_grid, 256, GEMM_SMEM>>>(
        xhi, xlo, wthi, wtlo, bq, bk, bv,
        nullptr, qhi, qlo, khi, klo, vhi, vlo);

    dim3 fa_grid(SEQT / 64, NHEAD, BATCH);     // (32, 12, 4) = 1536 CTAs
    flash_attn_mma<<<fa_grid, 128, FA_SMEM>>>(qhi, qlo, khi, klo, vhi, vlo, ahi, alo);

    dim3 wo_grid(12, MROWS / 128);
    gemm_mma_split<false><<<wo_grid, 256, GEMM_SMEM>>>(
        ahi, alo, wthi, wtlo, bo, nullptr, nullptr,
        out, nullptr, nullptr, nullptr, nullptr, nullptr, nullptr);
}

// round 12
// speedup vs baseline: 1.1289x; 1.0536x over previous
#include <cuda_runtime.h>
#include <cuda_bf16.h>
#include <cuda_fp16.h>
#include <math.h>
#include <stdint.h>

#define BATCH 4
#define SEQT 2048
#define CDIM 768
#define NHEAD 12
#define HDIM 64
#define MROWS (BATCH * SEQT)   // 8192

// ---------------------------------------------------------------------------
// Scratch (allocation-free rule: device globals)
// ---------------------------------------------------------------------------
__device__ __nv_bfloat16 g_xhi[(size_t)MROWS * CDIM];
__device__ __nv_bfloat16 g_xlo[(size_t)MROWS * CDIM];
__device__ __half g_qhi[(size_t)MROWS * CDIM];
__device__ __half g_qlo[(size_t)MROWS * CDIM];
__device__ __half g_khi[(size_t)MROWS * CDIM];
__device__ __half g_klo[(size_t)MROWS * CDIM];
__device__ __half g_vhi[(size_t)MROWS * CDIM];
__device__ __half g_vlo[(size_t)MROWS * CDIM];
__device__ __nv_bfloat16 g_ahi[(size_t)MROWS * CDIM];
__device__ __nv_bfloat16 g_alo[(size_t)MROWS * CDIM];
// transposed+split weights: [4][N=CDIM][K=CDIM] (order: Wq, Wk, Wv, Wo)
__device__ __nv_bfloat16 g_wthi[4 * (size_t)CDIM * CDIM];
__device__ __nv_bfloat16 g_wtlo[4 * (size_t)CDIM * CDIM];

// ---------------------------------------------------------------------------
// PTX helpers (sm_80-era: legal under .target sm_103)
// ---------------------------------------------------------------------------
__device__ __forceinline__ uint32_t smem_to_u32(const void* p) {
    uint32_t a;
    asm("{ .reg .u64 t; cvta.to.shared.u64 t, %1; cvt.u32.u64 %0, t; }"
        : "=r"(a) : "l"(p));
    return a;
}

__device__ __forceinline__ void ldsm_x4(uint32_t* r, uint32_t addr) {
    asm volatile("ldmatrix.sync.aligned.m8n8.x4.shared.b16 {%0,%1,%2,%3}, [%4];"
        : "=r"(r[0]), "=r"(r[1]), "=r"(r[2]), "=r"(r[3]) : "r"(addr));
}

__device__ __forceinline__ void ldsm_x4_trans(uint32_t* r, uint32_t addr) {
    asm volatile("ldmatrix.sync.aligned.m8n8.x4.trans.shared.b16 {%0,%1,%2,%3}, [%4];"
        : "=r"(r[0]), "=r"(r[1]), "=r"(r[2]), "=r"(r[3]) : "r"(addr));
}

// bf16 MMA (GEMM path)
__device__ __forceinline__ void mma16816(float* c, const uint32_t* a, const uint32_t* b) {
    asm volatile(
        "mma.sync.aligned.m16n8k16.row.col.f32.bf16.bf16.f32 "
        "{%0,%1,%2,%3}, {%4,%5,%6,%7}, {%8,%9}, {%0,%1,%2,%3};"
        : "+f"(c[0]), "+f"(c[1]), "+f"(c[2]), "+f"(c[3])
        : "r"(a[0]), "r"(a[1]), "r"(a[2]), "r"(a[3]), "r"(b[0]), "r"(b[1]));
}

// fp16 MMA (attention path)
__device__ __forceinline__ void mma16816h(float* c, const uint32_t* a, const uint32_t* b) {
    asm volatile(
        "mma.sync.aligned.m16n8k16.row.col.f32.f16.f16.f32 "
        "{%0,%1,%2,%3}, {%4,%5,%6,%7}, {%8,%9}, {%0,%1,%2,%3};"
        : "+f"(c[0]), "+f"(c[1]), "+f"(c[2]), "+f"(c[3])
        : "r"(a[0]), "r"(a[1]), "r"(a[2]), "r"(a[3]), "r"(b[0]), "r"(b[1]));
}

__device__ __forceinline__ float fast_ex2(float x) {
    float y;
    asm("ex2.approx.f32 %0, %1;" : "=f"(y) : "f"(x));
    return y;
}

#define CP16(dst, src) \
    asm volatile("cp.async.cg.shared.global [%0], [%1], 16;" \
                 :: "r"(dst), "l"(src) : "memory")
#define CP_COMMIT() asm volatile("cp.async.commit_group;" ::: "memory")
#define CP_WAIT2()  asm volatile("cp.async.wait_group 2;" ::: "memory")
#define CP_WAIT1()  asm volatile("cp.async.wait_group 1;" ::: "memory")
#define CP_WAIT0()  asm volatile("cp.async.wait_group 0;" ::: "memory")

#define SWZ128(off) ((off) ^ (((off) >> 3) & 0x70))

// 0.125 * log2(e): folded into Q at the QKV GEMM epilogue
#define QK_SCALE 0.18033688011112042f

// ---------------------------------------------------------------------------
// Conversion kernels
// ---------------------------------------------------------------------------
__global__ void split_f32(const float* __restrict__ in,
                          __nv_bfloat16* __restrict__ hi,
                          __nv_bfloat16* __restrict__ lo, int n) {
    int i = blockIdx.x * blockDim.x + threadIdx.x;
    if (i < n) {
        float v = in[i];
        __nv_bfloat16 h = __float2bfloat16(v);
        float r = v - __bfloat162float(h);
        hi[i] = h;
        lo[i] = __float2bfloat16(r);
    }
}

__global__ void wtrans_split4(const float* __restrict__ W0, const float* __restrict__ W1,
                              const float* __restrict__ W2, const float* __restrict__ W3,
                              __nv_bfloat16* __restrict__ hi,
                              __nv_bfloat16* __restrict__ lo) {
    __shared__ float t[32][33];
    const int z = blockIdx.z;
    const float* W = (z == 0) ? W0 : (z == 1) ? W1 : (z == 2) ? W2 : W3;
    const size_t zoff = (size_t)z * CDIM * CDIM;
    const int kx = blockIdx.x * 32;
    const int nx = blockIdx.y * 32;
    const int tx = threadIdx.x, ty = threadIdx.y;
    for (int j = ty; j < 32; j += 8)
        t[j][tx] = W[(size_t)(kx + j) * CDIM + nx + tx];
    __syncthreads();
    for (int j = ty; j < 32; j += 8) {
        float v = t[tx][j];
        __nv_bfloat16 h = __float2bfloat16(v);
        float r = v - __bfloat162float(h);
        size_t o = zoff + (size_t)(nx + j) * CDIM + kx + tx;
        hi[o] = h;
        lo[o] = __float2bfloat16(r);
    }
}

// ---------------------------------------------------------------------------
// mma.sync split-bf16 GEMM, 128x64 tile, 2 stages, 2 CTAs/SM.
//   SPLIT_OUT=true: fused QKV, outputs fp16 hi/lo (attention consumes fp16).
//   SPLIT_OUT=false: Wo, fp32 output.
// ---------------------------------------------------------------------------
#define GK 64
#define NCHUNK (CDIM / GK)        // 12
#define CH_BYTES 49152
#define GEMM_SMEM (2 * CH_BYTES)  // 98304
#define T_AHI 0
#define T_ALO 16384
#define T_BHI 32768
#define T_BLO 40960

template <bool SPLIT_OUT>
__global__ __launch_bounds__(256, 2) void gemm_mma_split(
    const __nv_bfloat16* __restrict__ Ahi, const __nv_bfloat16* __restrict__ Alo,
    const __nv_bfloat16* __restrict__ Wthi, const __nv_bfloat16* __restrict__ Wtlo,
    const float* __restrict__ b0, const float* __restrict__ b1,
    const float* __restrict__ b2,
    float* __restrict__ Cout,
    __half* __restrict__ C0hi, __half* __restrict__ C0lo,
    __half* __restrict__ C1hi, __half* __restrict__ C1lo,
    __half* __restrict__ C2hi, __half* __restrict__ C2lo)
{
    extern __shared__ char smem[];
    const uint32_t sbase = smem_to_u32(smem);
    const int tid = threadIdx.x;
    const int lane = tid & 31;
    const int wid = tid >> 5;
    const int warp_m = wid >> 1;
    const int warp_n = wid & 1;
    const int row0 = blockIdx.y * 128;

    int wsel, col0;
    if (SPLIT_OUT) { wsel = blockIdx.x / 12; col0 = (blockIdx.x % 12) * 64; }
    else           { wsel = 3;              col0 = blockIdx.x * 64; }

    const size_t WSZ = (size_t)CDIM * CDIM;
    const __nv_bfloat16* Bhi = Wthi + (size_t)wsel * WSZ;
    const __nv_bfloat16* Blo = Wtlo + (size_t)wsel * WSZ;
    const float* bias = SPLIT_OUT ? (wsel == 0 ? b0 : wsel == 1 ? b1 : b2) : b0;
    __half* Chi = SPLIT_OUT ? (wsel == 0 ? C0hi : wsel == 1 ? C1hi : C2hi) : nullptr;
    __half* Clo = SPLIT_OUT ? (wsel == 0 ? C0lo : wsel == 1 ? C1lo : C2lo) : nullptr;
    const float oscale = (SPLIT_OUT && wsel == 0) ? QK_SCALE : 1.0f;

    const int lrow = lane & 7;
    const int lgrp = lane >> 3;
    const int a_roff = ((lgrp & 1) << 3) + lrow;
    const int a_kh   = (lgrp >> 1) << 4;
    const int b_roff = ((lgrp >> 1) << 3) + lrow;
    const int b_kh   = (lgrp & 1) << 4;

    const int ld_r   = tid >> 3;
    const int ld_c16 = (tid & 7) << 4;

    float acc[2][4][4];
#pragma unroll
    for (int i = 0; i < 2; i++)
#pragma unroll
        for (int j = 0; j < 4; j++)
#pragma unroll
            for (int r = 0; r < 4; r++) acc[i][j][r] = 0.0f;

    auto load_chunk = [&](int kc, int stage) {
        const uint32_t sb = sbase + stage * CH_BYTES;
        const int kcol = kc * GK;
#pragma unroll
        for (int t = 0; t < 4; t++) {
            const int r = ld_r + t * 32;
            const uint32_t sw = SWZ128(r * 128 + ld_c16);
            const char* pa  = (const char*)(Ahi + (size_t)(row0 + r) * CDIM + kcol) + ld_c16;
            const char* pal = (const char*)(Alo + (size_t)(row0 + r) * CDIM + kcol) + ld_c16;
            CP16(sb + T_AHI + sw, pa);
            CP16(sb + T_ALO + sw, pal);
        }
#pragma unroll
        for (int t = 0; t < 2; t++) {
            const int idx = tid + t * 256;
            const int r = idx >> 3;
            const int c16 = (idx & 7) << 4;
            const uint32_t sw = SWZ128(r * 128 + c16);
            const char* pb  = (const char*)(Bhi + (size_t)(col0 + r) * CDIM + kcol) + c16;
            const char* pbl = (const char*)(Blo + (size_t)(col0 + r) * CDIM + kcol) + c16;
            CP16(sb + T_BHI + sw, pb);
            CP16(sb + T_BLO + sw, pbl);
        }
        CP_COMMIT();
    };

    load_chunk(0, 0);

    for (int kc = 0; kc < NCHUNK; kc++) {
        CP_WAIT0();
        __syncthreads();
        if (kc + 1 < NCHUNK) load_chunk(kc + 1, (kc + 1) & 1);

        const uint32_t sb = sbase + (kc & 1) * CH_BYTES;
#pragma unroll
        for (int s = 0; s < 4; s++) {
            const int kb = s * 32;
            uint32_t ahi[2][4], alo[2][4];
#pragma unroll
            for (int i = 0; i < 2; i++) {
                const uint32_t off =
                    SWZ128((warp_m * 32 + i * 16 + a_roff) * 128 + kb + a_kh);
                ldsm_x4(ahi[i], sb + T_AHI + off);
                ldsm_x4(alo[i], sb + T_ALO + off);
            }
            uint32_t bhi[4][2], blo[4][2];
#pragma unroll
            for (int j2 = 0; j2 < 2; j2++) {
                const uint32_t off =
                    SWZ128((warp_n * 32 + j2 * 16 + b_roff) * 128 + kb + b_kh);
                uint32_t t[4];
                ldsm_x4(t, sb + T_BHI + off);
                bhi[2 * j2][0] = t[0]; bhi[2 * j2][1] = t[1];
                bhi[2 * j2 + 1][0] = t[2]; bhi[2 * j2 + 1][1] = t[3];
                ldsm_x4(t, sb + T_BLO + off);
                blo[2 * j2][0] = t[0]; blo[2 * j2][1] = t[1];
                blo[2 * j2 + 1][0] = t[2]; blo[2 * j2 + 1][1] = t[3];
            }
#pragma unroll
            for (int i = 0; i < 2; i++)
#pragma unroll
                for (int j = 0; j < 4; j++)
                    mma16816(acc[i][j], ahi[i], bhi[j]);
#pragma unroll
            for (int i = 0; i < 2; i++)
#pragma unroll
                for (int j = 0; j < 4; j++)
                    mma16816(acc[i][j], ahi[i], blo[j]);
#pragma unroll
            for (int i = 0; i < 2; i++)
#pragma unroll
                for (int j = 0; j < 4; j++)
                    mma16816(acc[i][j], alo[i], bhi[j]);
        }
    }

    // ---- epilogue ----
#pragma unroll
    for (int i = 0; i < 2; i++) {
        const int mrow = row0 + warp_m * 32 + i * 16 + (lane >> 2);
#pragma unroll
        for (int j = 0; j < 4; j++) {
            const int ncol = col0 + warp_n * 32 + j * 8 + ((lane & 3) << 1);
            const float2 bv = *(const float2*)&bias[ncol];
            const float c0 = (acc[i][j][0] + bv.x) * oscale;
            const float c1 = (acc[i][j][1] + bv.y) * oscale;
            const float c2 = (acc[i][j][2] + bv.x) * oscale;
            const float c3 = (acc[i][j][3] + bv.y) * oscale;
            if (SPLIT_OUT) {
                __half2 h0 = __floats2half2_rn(c0, c1);
                float2 hf0 = __half22float2(h0);
                __half2 l0 = __floats2half2_rn(c0 - hf0.x, c1 - hf0.y);
                __half2 h1 = __floats2half2_rn(c2, c3);
                float2 hf1 = __half22float2(h1);
                __half2 l1 = __floats2half2_rn(c2 - hf1.x, c3 - hf1.y);
                *(__half2*)&Chi[(size_t)mrow * CDIM + ncol] = h0;
                *(__half2*)&Clo[(size_t)mrow * CDIM + ncol] = l0;
                *(__half2*)&Chi[(size_t)(mrow + 8) * CDIM + ncol] = h1;
                *(__half2*)&Clo[(size_t)(mrow + 8) * CDIM + ncol] = l1;
            } else {
                float2 o0, o1;
                o0.x = c0; o0.y = c1;
                o1.x = c2; o1.y = c3;
                *(float2*)&Cout[(size_t)mrow * CDIM + ncol] = o0;
                *(float2*)&Cout[(size_t)(mrow + 8) * CDIM + ncol] = o1;
            }
        }
    }
}

// ---------------------------------------------------------------------------
// Flash attention (causal), fp16 datapath: BQ=64, 128 threads, 2 CTAs/SM,
//   register-resident Q, 3 KV buffers (prefetch distance 2).
//   QK: fp16 hi/lo, 3 combos. PV: P single fp16 x V fp16 hi/lo, 2 combos.
//   Output written as bf16 hi/lo (Wo GEMM stays bf16).
// ---------------------------------------------------------------------------
#define KV_BUF 32768
#define O_KHI 0
#define O_KLO 8192
#define O_VHI 16384
#define O_VLO 24576
#define Q_OFF (3 * KV_BUF)
#define FA_SMEM (3 * KV_BUF + 16384)   // 114688

__global__ __launch_bounds__(128, 2) void flash_attn_mma(
    const __half* __restrict__ Qhi, const __half* __restrict__ Qlo,
    const __half* __restrict__ Khi, const __half* __restrict__ Klo,
    const __half* __restrict__ Vhi, const __half* __restrict__ Vlo,
    __nv_bfloat16* __restrict__ Ohi, __nv_bfloat16* __restrict__ Olo)
{
    extern __shared__ char smem[];
    const uint32_t sbase = smem_to_u32(smem);
    const int tid = threadIdx.x;
    const int lane = tid & 31;
    const int wid = tid >> 5;                      // 0..3
    const int qi = (gridDim.x - 1) - blockIdx.x;   // heavy CTAs first
    const int h = blockIdx.y;
    const int b = blockIdx.z;
    const int qrow0 = qi * 64;
    const int m0 = wid * 16;
    const int lr = lane & 7;
    const int lg = lane >> 3;

    const int nkt = qi + 1;

    // ---- load Q tile (64 rows; hi at Q_OFF, lo at Q_OFF+8KB) ----
#pragma unroll
    for (int t = 0; t < 4; t++) {
        const int idx = tid + t * 128;             // 0..511
        const int r = idx >> 3;
        const int c16 = (idx & 7) << 4;
        const uint32_t sw = SWZ128(r * 128 + c16);
        const size_t grow = (size_t)(b * SEQT + qrow0 + r) * CDIM + h * HDIM;
        CP16(sbase + Q_OFF + sw, (const char*)(Qhi + grow) + c16);
        CP16(sbase + Q_OFF + 8192 + sw, (const char*)(Qlo + grow) + c16);
    }
    CP_COMMIT();

    auto load_kv = [&](int kt) {
        const uint32_t sb = sbase + (uint32_t)(kt % 3) * KV_BUF;
#pragma unroll
        for (int t = 0; t < 4; t++) {
            const int idx = tid + t * 128;         // 0..511
            const int r = idx >> 3;
            const int c16 = (idx & 7) << 4;
            const uint32_t sw = SWZ128(r * 128 + c16);
            const size_t grow = (size_t)(b * SEQT + kt * 64 + r) * CDIM + h * HDIM;
            CP16(sb + O_KHI + sw, (const char*)(Khi + grow) + c16);
            CP16(sb + O_KLO + sw, (const char*)(Klo + grow) + c16);
            CP16(sb + O_VHI + sw, (const char*)(Vhi + grow) + c16);
            CP16(sb + O_VLO + sw, (const char*)(Vlo + grow) + c16);
        }
        CP_COMMIT();
    };
    load_kv(0);
    if (nkt > 1) load_kv(1);

    // ---- Q landed for all threads (kv0/kv1 may fly); hoist Q fragments ----
    if (nkt > 1) { CP_WAIT2(); } else { CP_WAIT1(); }
    __syncthreads();
    uint32_t qfh[4][4], qfl[4][4];
#pragma unroll
    for (int s = 0; s < 4; s++) {
        const uint32_t sw = SWZ128((m0 + ((lg & 1) << 3) + lr) * 128
                                   + s * 32 + ((lg >> 1) << 4));
        ldsm_x4(qfh[s], sbase + Q_OFF + sw);
        ldsm_x4(qfl[s], sbase + Q_OFF + 8192 + sw);
    }

    float o[8][4];
#pragma unroll
    for (int j = 0; j < 8; j++)
#pragma unroll
        for (int r = 0; r < 4; r++) o[j][r] = 0.0f;
    float mR[2] = {-1e30f, -1e30f};
    float lR[2] = {0.0f, 0.0f};

    for (int kt = 0; kt < nkt; kt++) {
        if (kt + 1 < nkt) { CP_WAIT1(); } else { CP_WAIT0(); }
        __syncthreads();   // everyone's writes visible; prev-iter reads done
        if (kt + 2 < nkt) load_kv(kt + 2);
        const uint32_t kb = sbase + (uint32_t)(kt % 3) * KV_BUF;

        // ---- S = Q @ K^T (fp16 split, 3 combos) ----
        float sacc[8][4];
#pragma unroll
        for (int j = 0; j < 8; j++)
#pragma unroll
            for (int r = 0; r < 4; r++) sacc[j][r] = 0.0f;

#pragma unroll
        for (int s = 0; s < 4; s++) {
#pragma unroll
            for (int p = 0; p < 4; p++) {
                const uint32_t sw = SWZ128((p * 16 + ((lg >> 1) << 3) + lr) * 128
                                           + s * 32 + ((lg & 1) << 4));
                uint32_t kh[4], kl[4];
                ldsm_x4(kh, kb + O_KHI + sw);
                ldsm_x4(kl, kb + O_KLO + sw);
                mma16816h(sacc[2 * p],     qfh[s], &kh[0]);
                mma16816h(sacc[2 * p + 1], qfh[s], &kh[2]);
                mma16816h(sacc[2 * p],     qfh[s], &kl[0]);
                mma16816h(sacc[2 * p + 1], qfh[s], &kl[2]);
                mma16816h(sacc[2 * p],     qfl[s], &kh[0]);
                mma16816h(sacc[2 * p + 1], qfl[s], &kh[2]);
            }
        }

        // ---- causal mask (only the diagonal tile kt == qi) ----
        if (kt == nkt - 1) {
            const int qg0 = qrow0 + m0 + (lane >> 2);
            const int qg1 = qg0 + 8;
#pragma unroll
            for (int j = 0; j < 8; j++) {
                const int kg = kt * 64 + j * 8 + ((lane & 3) << 1);
                if (kg > qg0)     sacc[j][0] = -1e30f;
                if (kg + 1 > qg0) sacc[j][1] = -1e30f;
                if (kg > qg1)     sacc[j][2] = -1e30f;
                if (kg + 1 > qg1) sacc[j][3] = -1e30f;
            }
        }

        // ---- online softmax (scores already in log2 units) ----
        float mp0 = sacc[0][0], mp1 = sacc[0][2];
#pragma unroll
        for (int j = 0; j < 8; j++) {
            mp0 = fmaxf(mp0, fmaxf(sacc[j][0], sacc[j][1]));
            mp1 = fmaxf(mp1, fmaxf(sacc[j][2], sacc[j][3]));
        }
        mp0 = fmaxf(mp0, __shfl_xor_sync(0xffffffffu, mp0, 1));
        mp0 = fmaxf(mp0, __shfl_xor_sync(0xffffffffu, mp0, 2));
        mp1 = fmaxf(mp1, __shfl_xor_sync(0xffffffffu, mp1, 1));
        mp1 = fmaxf(mp1, __shfl_xor_sync(0xffffffffu, mp1, 2));
        const float mn0 = fmaxf(mR[0], mp0);
        const float mn1 = fmaxf(mR[1], mp1);
        const float f0 = fast_ex2(mR[0] - mn0);
        const float f1 = fast_ex2(mR[1] - mn1);
        float sum0 = 0.0f, sum1 = 0.0f;
#pragma unroll
        for (int j = 0; j < 8; j++) {
            sacc[j][0] = fast_ex2(sacc[j][0] - mn0);
            sacc[j][1] = fast_ex2(sacc[j][1] - mn0);
            sacc[j][2] = fast_ex2(sacc[j][2] - mn1);
            sacc[j][3] = fast_ex2(sacc[j][3] - mn1);
            sum0 += sacc[j][0] + sacc[j][1];
            sum1 += sacc[j][2] + sacc[j][3];
        }
        sum0 += __shfl_xor_sync(0xffffffffu, sum0, 1);
        sum0 += __shfl_xor_sync(0xffffffffu, sum0, 2);
        sum1 += __shfl_xor_sync(0xffffffffu, sum1, 1);
        sum1 += __shfl_xor_sync(0xffffffffu, sum1, 2);
        lR[0] = lR[0] * f0 + sum0;
        lR[1] = lR[1] * f1 + sum1;
        mR[0] = mn0;
        mR[1] = mn1;
#pragma unroll
        for (int j = 0; j < 8; j++) {
            o[j][0] *= f0; o[j][1] *= f0;
            o[j][2] *= f1; o[j][3] *= f1;
        }

        // ---- O += P @ V (P single fp16 in regs, V fp16 split from smem) ----
#pragma unroll
        for (int s2 = 0; s2 < 4; s2++) {
            uint32_t ph[4];
#pragma unroll
            for (int half = 0; half < 2; half++) {
                const int jt = 2 * s2 + half;
                __half2 p0 = __floats2half2_rn(sacc[jt][0], sacc[jt][1]);
                __half2 p1 = __floats2half2_rn(sacc[jt][2], sacc[jt][3]);
                ph[2 * half]     = *(uint32_t*)&p0;
                ph[2 * half + 1] = *(uint32_t*)&p1;
            }
#pragma unroll
            for (int dp = 0; dp < 4; dp++) {
                const uint32_t sw = SWZ128((s2 * 16 + ((lg & 1) << 3) + lr) * 128
                                           + dp * 32 + ((lg >> 1) << 4));
                uint32_t vh[4], vl[4];
                ldsm_x4_trans(vh, kb + O_VHI + sw);
                ldsm_x4_trans(vl, kb + O_VLO + sw);
                mma16816h(o[2 * dp],     ph, &vh[0]);
                mma16816h(o[2 * dp + 1], ph, &vh[2]);
                mma16816h(o[2 * dp],     ph, &vl[0]);
                mma16816h(o[2 * dp + 1], ph, &vl[2]);
            }
        }
    }

    // ---- normalize + write bf16 hi/lo (Wo GEMM input format) ----
    const float inv0 = 1.0f / lR[0];
    const float inv1 = 1.0f / lR[1];
    const int r0 = b * SEQT + qrow0 + m0 + (lane >> 2);
#pragma unroll
    for (int j = 0; j < 8; j++) {
        const int col = h * HDIM + j * 8 + ((lane & 3) << 1);
        const float c0 = o[j][0] * inv0, c1 = o[j][1] * inv0;
        const float c2 = o[j][2] * inv1, c3 = o[j][3] * inv1;
        __nv_bfloat162 h0 = __floats2bfloat162_rn(c0, c1);
        float2 hf0 = __bfloat1622float2(h0);
        __nv_bfloat162 l0 = __floats2bfloat162_rn(c0 - hf0.x, c1 - hf0.y);
        __nv_bfloat162 h1 = __floats2bfloat162_rn(c2, c3);
        float2 hf1 = __bfloat1622float2(h1);
        __nv_bfloat162 l1 = __floats2bfloat162_rn(c2 - hf1.x, c3 - hf1.y);
        *(__nv_bfloat162*)&Ohi[(size_t)r0 * CDIM + col] = h0;
        *(__nv_bfloat162*)&Olo[(size_t)r0 * CDIM + col] = l0;
        *(__nv_bfloat162*)&Ohi[(size_t)(r0 + 8) * CDIM + col] = h1;
        *(__nv_bfloat162*)&Olo[(size_t)(r0 + 8) * CDIM + col] = l1;
    }
}

// ---------------------------------------------------------------------------
// Launch
// ---------------------------------------------------------------------------
extern "C" void kernel_launch(void* const* d_in, const int* in_sizes, int n_in,
                              void* d_out, int out_size)
{
    (void)in_sizes; (void)n_in; (void)out_size;
    const float* x  = (const float*)d_in[0];
    const float* Wq = (const float*)d_in[1];
    const float* bq = (const float*)d_in[2];
    const float* Wk = (const float*)d_in[3];
    const float* bk = (const float*)d_in[4];
    const float* Wv = (const float*)d_in[5];
    const float* bv = (const float*)d_in[6];
    const float* Wo = (const float*)d_in[7];
    const float* bo = (const float*)d_in[8];
    float* out = (float*)d_out;

    __nv_bfloat16 *xhi, *xlo, *ahi, *alo, *wthi, *wtlo;
    __half *qhi, *qlo, *khi, *klo, *vhi, *vlo;
    cudaGetSymbolAddress((void**)&xhi,  g_xhi);
    cudaGetSymbolAddress((void**)&xlo,  g_xlo);
    cudaGetSymbolAddress((void**)&qhi,  g_qhi);
    cudaGetSymbolAddress((void**)&qlo,  g_qlo);
    cudaGetSymbolAddress((void**)&khi,  g_khi);
    cudaGetSymbolAddress((void**)&klo,  g_klo);
    cudaGetSymbolAddress((void**)&vhi,  g_vhi);
    cudaGetSymbolAddress((void**)&vlo,  g_vlo);
    cudaGetSymbolAddress((void**)&ahi,  g_ahi);
    cudaGetSymbolAddress((void**)&alo,  g_alo);
    cudaGetSymbolAddress((void**)&wthi, g_wthi);
    cudaGetSymbolAddress((void**)&wtlo, g_wtlo);

    cudaFuncSetAttribute(gemm_mma_split<true>,
                         cudaFuncAttributeMaxDynamicSharedMemorySize, GEMM_SMEM);
    cudaFuncSetAttribute(gemm_mma_split<false>,
                         cudaFuncAttributeMaxDynamicSharedMemorySize, GEMM_SMEM);
    cudaFuncSetAttribute(flash_attn_mma,
                         cudaFuncAttributeMaxDynamicSharedMemorySize, FA_SMEM);

    const int nelem = MROWS * CDIM;

    split_f32<<<(nelem + 255) / 256, 256>>>(x, xhi, xlo, nelem);

    dim3 wt_grid(CDIM / 32, CDIM / 32, 4);
    dim3 wt_blk(32, 8);
    wtrans_split4<<<wt_grid, wt_blk>>>(Wq, Wk, Wv, Wo, wthi, wtlo);

    dim3 qkv_grid(36, MROWS / 128);
    gemm_mma_split<true><<<qkv_grid, 256, GEMM_SMEM>>>(
        xhi, xlo, wthi, wtlo, bq, bk, bv,
        nullptr, qhi, qlo, khi, klo, vhi, vlo);

    dim3 fa_grid(SEQT / 64, NHEAD, BATCH);     // (32, 12, 4) = 1536 CTAs
    flash_attn_mma<<<fa_grid, 128, FA_SMEM>>>(qhi, qlo, khi, klo, vhi, vlo, ahi, alo);

    dim3 wo_grid(12, MROWS / 128);
    gemm_mma_split<false><<<wo_grid, 256, GEMM_SMEM>>>(
        ahi, alo, wthi, wtlo, bo, nullptr, nullptr,
        out, nullptr, nullptr, nullptr, nullptr, nullptr, nullptr);
}

// round 13
// speedup vs baseline: 1.3074x; 1.1581x over previous
#include <cuda_runtime.h>
#include <cuda_bf16.h>
#include <cuda_fp16.h>
#include <math.h>
#include <stdint.h>

#define BATCH 4
#define SEQT 2048
#define CDIM 768
#define NHEAD 12
#define HDIM 64
#define MROWS (BATCH * SEQT)   // 8192

// ---------------------------------------------------------------------------
// Scratch (allocation-free rule: device globals)
// ---------------------------------------------------------------------------
__device__ __nv_bfloat16 g_xhi[(size_t)MROWS * CDIM];
__device__ __nv_bfloat16 g_xlo[(size_t)MROWS * CDIM];
__device__ __half g_qhi[(size_t)MROWS * CDIM];
__device__ __half g_qlo[(size_t)MROWS * CDIM];
__device__ __half g_khi[(size_t)MROWS * CDIM];    // K single fp16
__device__ __half g_vhi[(size_t)MROWS * CDIM];    // V single fp16
__device__ __nv_bfloat16 g_ahi[(size_t)MROWS * CDIM];
__device__ __nv_bfloat16 g_alo[(size_t)MROWS * CDIM];
// transposed+split weights: [4][N=CDIM][K=CDIM] (order: Wq, Wk, Wv, Wo)
__device__ __nv_bfloat16 g_wthi[4 * (size_t)CDIM * CDIM];
__device__ __nv_bfloat16 g_wtlo[4 * (size_t)CDIM * CDIM];

// ---------------------------------------------------------------------------
// PTX helpers (sm_80-era: legal under .target sm_103)
// ---------------------------------------------------------------------------
__device__ __forceinline__ uint32_t smem_to_u32(const void* p) {
    uint32_t a;
    asm("{ .reg .u64 t; cvta.to.shared.u64 t, %1; cvt.u32.u64 %0, t; }"
        : "=r"(a) : "l"(p));
    return a;
}

__device__ __forceinline__ void ldsm_x4(uint32_t* r, uint32_t addr) {
    asm volatile("ldmatrix.sync.aligned.m8n8.x4.shared.b16 {%0,%1,%2,%3}, [%4];"
        : "=r"(r[0]), "=r"(r[1]), "=r"(r[2]), "=r"(r[3]) : "r"(addr));
}

__device__ __forceinline__ void ldsm_x4_trans(uint32_t* r, uint32_t addr) {
    asm volatile("ldmatrix.sync.aligned.m8n8.x4.trans.shared.b16 {%0,%1,%2,%3}, [%4];"
        : "=r"(r[0]), "=r"(r[1]), "=r"(r[2]), "=r"(r[3]) : "r"(addr));
}

// bf16 MMA (GEMM path)
__device__ __forceinline__ void mma16816(float* c, const uint32_t* a, const uint32_t* b) {
    asm volatile(
        "mma.sync.aligned.m16n8k16.row.col.f32.bf16.bf16.f32 "
        "{%0,%1,%2,%3}, {%4,%5,%6,%7}, {%8,%9}, {%0,%1,%2,%3};"
        : "+f"(c[0]), "+f"(c[1]), "+f"(c[2]), "+f"(c[3])
        : "r"(a[0]), "r"(a[1]), "r"(a[2]), "r"(a[3]), "r"(b[0]), "r"(b[1]));
}

// fp16 MMA (attention path)
__device__ __forceinline__ void mma16816h(float* c, const uint32_t* a, const uint32_t* b) {
    asm volatile(
        "mma.sync.aligned.m16n8k16.row.col.f32.f16.f16.f32 "
        "{%0,%1,%2,%3}, {%4,%5,%6,%7}, {%8,%9}, {%0,%1,%2,%3};"
        : "+f"(c[0]), "+f"(c[1]), "+f"(c[2]), "+f"(c[3])
        : "r"(a[0]), "r"(a[1]), "r"(a[2]), "r"(a[3]), "r"(b[0]), "r"(b[1]));
}

__device__ __forceinline__ float fast_ex2(float x) {
    float y;
    asm("ex2.approx.f32 %0, %1;" : "=f"(y) : "f"(x));
    return y;
}

#define CP16(dst, src) \
    asm volatile("cp.async.cg.shared.global [%0], [%1], 16;" \
                 :: "r"(dst), "l"(src) : "memory")
#define CP_COMMIT() asm volatile("cp.async.commit_group;" ::: "memory")
#define CP_WAIT2()  asm volatile("cp.async.wait_group 2;" ::: "memory")
#define CP_WAIT1()  asm volatile("cp.async.wait_group 1;" ::: "memory")
#define CP_WAIT0()  asm volatile("cp.async.wait_group 0;" ::: "memory")

#define SWZ128(off) ((off) ^ (((off) >> 3) & 0x70))

// 0.125 * log2(e): folded into Q at the QKV GEMM epilogue
#define QK_SCALE 0.18033688011112042f

// ---------------------------------------------------------------------------
// Conversion kernels
// ---------------------------------------------------------------------------
__global__ void split_f32(const float* __restrict__ in,
                          __nv_bfloat16* __restrict__ hi,
                          __nv_bfloat16* __restrict__ lo, int n) {
    int i = blockIdx.x * blockDim.x + threadIdx.x;
    if (i < n) {
        float v = in[i];
        __nv_bfloat16 h = __float2bfloat16(v);
        float r = v - __bfloat162float(h);
        hi[i] = h;
        lo[i] = __float2bfloat16(r);
    }
}

__global__ void wtrans_split4(const float* __restrict__ W0, const float* __restrict__ W1,
                              const float* __restrict__ W2, const float* __restrict__ W3,
                              __nv_bfloat16* __restrict__ hi,
                              __nv_bfloat16* __restrict__ lo) {
    __shared__ float t[32][33];
    const int z = blockIdx.z;
    const float* W = (z == 0) ? W0 : (z == 1) ? W1 : (z == 2) ? W2 : W3;
    const size_t zoff = (size_t)z * CDIM * CDIM;
    const int kx = blockIdx.x * 32;
    const int nx = blockIdx.y * 32;
    const int tx = threadIdx.x, ty = threadIdx.y;
    for (int j = ty; j < 32; j += 8)
        t[j][tx] = W[(size_t)(kx + j) * CDIM + nx + tx];
    __syncthreads();
    for (int j = ty; j < 32; j += 8) {
        float v = t[tx][j];
        __nv_bfloat16 h = __float2bfloat16(v);
        float r = v - __bfloat162float(h);
        size_t o = zoff + (size_t)(nx + j) * CDIM + kx + tx;
        hi[o] = h;
        lo[o] = __float2bfloat16(r);
    }
}

// ---------------------------------------------------------------------------
// mma.sync split-bf16 GEMM, 128x64 tile, 2 stages, 2 CTAs/SM.
//   SPLIT_OUT=true: fused QKV. Q -> fp16 hi/lo; K,V -> single fp16.
//   SPLIT_OUT=false: Wo, fp32 output.
// ---------------------------------------------------------------------------
#define GK 64
#define NCHUNK (CDIM / GK)        // 12
#define CH_BYTES 49152
#define GEMM_SMEM (2 * CH_BYTES)  // 98304
#define T_AHI 0
#define T_ALO 16384
#define T_BHI 32768
#define T_BLO 40960

template <bool SPLIT_OUT>
__global__ __launch_bounds__(256, 2) void gemm_mma_split(
    const __nv_bfloat16* __restrict__ Ahi, const __nv_bfloat16* __restrict__ Alo,
    const __nv_bfloat16* __restrict__ Wthi, const __nv_bfloat16* __restrict__ Wtlo,
    const float* __restrict__ b0, const float* __restrict__ b1,
    const float* __restrict__ b2,
    float* __restrict__ Cout,
    __half* __restrict__ C0hi, __half* __restrict__ C0lo,
    __half* __restrict__ C1hi,
    __half* __restrict__ C2hi)
{
    extern __shared__ char smem[];
    const uint32_t sbase = smem_to_u32(smem);
    const int tid = threadIdx.x;
    const int lane = tid & 31;
    const int wid = tid >> 5;
    const int warp_m = wid >> 1;
    const int warp_n = wid & 1;
    const int row0 = blockIdx.y * 128;

    int wsel, col0;
    if (SPLIT_OUT) { wsel = blockIdx.x / 12; col0 = (blockIdx.x % 12) * 64; }
    else           { wsel = 3;              col0 = blockIdx.x * 64; }

    const size_t WSZ = (size_t)CDIM * CDIM;
    const __nv_bfloat16* Bhi = Wthi + (size_t)wsel * WSZ;
    const __nv_bfloat16* Blo = Wtlo + (size_t)wsel * WSZ;
    const float* bias = SPLIT_OUT ? (wsel == 0 ? b0 : wsel == 1 ? b1 : b2) : b0;
    __half* Chi = SPLIT_OUT ? (wsel == 0 ? C0hi : wsel == 1 ? C1hi : C2hi) : nullptr;
    __half* Clo = (SPLIT_OUT && wsel == 0) ? C0lo : nullptr;   // only Q keeps lo
    const float oscale = (SPLIT_OUT && wsel == 0) ? QK_SCALE : 1.0f;

    const int lrow = lane & 7;
    const int lgrp = lane >> 3;
    const int a_roff = ((lgrp & 1) << 3) + lrow;
    const int a_kh   = (lgrp >> 1) << 4;
    const int b_roff = ((lgrp >> 1) << 3) + lrow;
    const int b_kh   = (lgrp & 1) << 4;

    const int ld_r   = tid >> 3;
    const int ld_c16 = (tid & 7) << 4;

    float acc[2][4][4];
#pragma unroll
    for (int i = 0; i < 2; i++)
#pragma unroll
        for (int j = 0; j < 4; j++)
#pragma unroll
            for (int r = 0; r < 4; r++) acc[i][j][r] = 0.0f;

    auto load_chunk = [&](int kc, int stage) {
        const uint32_t sb = sbase + stage * CH_BYTES;
        const int kcol = kc * GK;
#pragma unroll
        for (int t = 0; t < 4; t++) {
            const int r = ld_r + t * 32;
            const uint32_t sw = SWZ128(r * 128 + ld_c16);
            const char* pa  = (const char*)(Ahi + (size_t)(row0 + r) * CDIM + kcol) + ld_c16;
            const char* pal = (const char*)(Alo + (size_t)(row0 + r) * CDIM + kcol) + ld_c16;
            CP16(sb + T_AHI + sw, pa);
            CP16(sb + T_ALO + sw, pal);
        }
#pragma unroll
        for (int t = 0; t < 2; t++) {
            const int idx = tid + t * 256;
            const int r = idx >> 3;
            const int c16 = (idx & 7) << 4;
            const uint32_t sw = SWZ128(r * 128 + c16);
            const char* pb  = (const char*)(Bhi + (size_t)(col0 + r) * CDIM + kcol) + c16;
            const char* pbl = (const char*)(Blo + (size_t)(col0 + r) * CDIM + kcol) + c16;
            CP16(sb + T_BHI + sw, pb);
            CP16(sb + T_BLO + sw, pbl);
        }
        CP_COMMIT();
    };

    load_chunk(0, 0);

    for (int kc = 0; kc < NCHUNK; kc++) {
        CP_WAIT0();
        __syncthreads();
        if (kc + 1 < NCHUNK) load_chunk(kc + 1, (kc + 1) & 1);

        const uint32_t sb = sbase + (kc & 1) * CH_BYTES;
#pragma unroll
        for (int s = 0; s < 4; s++) {
            const int kb = s * 32;
            uint32_t ahi[2][4], alo[2][4];
#pragma unroll
            for (int i = 0; i < 2; i++) {
                const uint32_t off =
                    SWZ128((warp_m * 32 + i * 16 + a_roff) * 128 + kb + a_kh);
                ldsm_x4(ahi[i], sb + T_AHI + off);
                ldsm_x4(alo[i], sb + T_ALO + off);
            }
            uint32_t bhi[4][2], blo[4][2];
#pragma unroll
            for (int j2 = 0; j2 < 2; j2++) {
                const uint32_t off =
                    SWZ128((warp_n * 32 + j2 * 16 + b_roff) * 128 + kb + b_kh);
                uint32_t t[4];
                ldsm_x4(t, sb + T_BHI + off);
                bhi[2 * j2][0] = t[0]; bhi[2 * j2][1] = t[1];
                bhi[2 * j2 + 1][0] = t[2]; bhi[2 * j2 + 1][1] = t[3];
                ldsm_x4(t, sb + T_BLO + off);
                blo[2 * j2][0] = t[0]; blo[2 * j2][1] = t[1];
                blo[2 * j2 + 1][0] = t[2]; blo[2 * j2 + 1][1] = t[3];
            }
#pragma unroll
            for (int i = 0; i < 2; i++)
#pragma unroll
                for (int j = 0; j < 4; j++)
                    mma16816(acc[i][j], ahi[i], bhi[j]);
#pragma unroll
            for (int i = 0; i < 2; i++)
#pragma unroll
                for (int j = 0; j < 4; j++)
                    mma16816(acc[i][j], ahi[i], blo[j]);
#pragma unroll
            for (int i = 0; i < 2; i++)
#pragma unroll
                for (int j = 0; j < 4; j++)
                    mma16816(acc[i][j], alo[i], bhi[j]);
        }
    }

    // ---- epilogue ----
#pragma unroll
    for (int i = 0; i < 2; i++) {
        const int mrow = row0 + warp_m * 32 + i * 16 + (lane >> 2);
#pragma unroll
        for (int j = 0; j < 4; j++) {
            const int ncol = col0 + warp_n * 32 + j * 8 + ((lane & 3) << 1);
            const float2 bv = *(const float2*)&bias[ncol];
            const float c0 = (acc[i][j][0] + bv.x) * oscale;
            const float c1 = (acc[i][j][1] + bv.y) * oscale;
            const float c2 = (acc[i][j][2] + bv.x) * oscale;
            const float c3 = (acc[i][j][3] + bv.y) * oscale;
            if (SPLIT_OUT) {
                __half2 h0 = __floats2half2_rn(c0, c1);
                __half2 h1 = __floats2half2_rn(c2, c3);
                *(__half2*)&Chi[(size_t)mrow * CDIM + ncol] = h0;
                *(__half2*)&Chi[(size_t)(mrow + 8) * CDIM + ncol] = h1;
                if (Clo) {
                    float2 hf0 = __half22float2(h0);
                    __half2 l0 = __floats2half2_rn(c0 - hf0.x, c1 - hf0.y);
                    float2 hf1 = __half22float2(h1);
                    __half2 l1 = __floats2half2_rn(c2 - hf1.x, c3 - hf1.y);
                    *(__half2*)&Clo[(size_t)mrow * CDIM + ncol] = l0;
                    *(__half2*)&Clo[(size_t)(mrow + 8) * CDIM + ncol] = l1;
                }
            } else {
                float2 o0, o1;
                o0.x = c0; o0.y = c1;
                o1.x = c2; o1.y = c3;
                *(float2*)&Cout[(size_t)mrow * CDIM + ncol] = o0;
                *(float2*)&Cout[(size_t)(mrow + 8) * CDIM + ncol] = o1;
            }
        }
    }
}

// ---------------------------------------------------------------------------
// Flash attention (causal), lean fp16 datapath:
//   Q fp16 hi/lo (register-resident), K single fp16, V single fp16.
//   QK: 2 combos (qhi@K + qlo@K). PV: 1 combo (P@V). 96 MMAs/tile (was 160).
//   BQ=64, 128 threads, 2 CTAs/SM, 3 KV buffers (16KB each, distance 2).
//   Output bf16 hi/lo (Wo GEMM stays bf16).
// ---------------------------------------------------------------------------
#define KV_BUF 16384
#define O_KHI 0
#define O_VHI 8192
#define Q_OFF (3 * KV_BUF)             // 49152
#define FA_SMEM (3 * KV_BUF + 16384)   // 65536

__global__ __launch_bounds__(128, 2) void flash_attn_mma(
    const __half* __restrict__ Qhi, const __half* __restrict__ Qlo,
    const __half* __restrict__ Khi,
    const __half* __restrict__ Vhi,
    __nv_bfloat16* __restrict__ Ohi, __nv_bfloat16* __restrict__ Olo)
{
    extern __shared__ char smem[];
    const uint32_t sbase = smem_to_u32(smem);
    const int tid = threadIdx.x;
    const int lane = tid & 31;
    const int wid = tid >> 5;                      // 0..3
    const int qi = (gridDim.x - 1) - blockIdx.x;   // heavy CTAs first
    const int h = blockIdx.y;
    const int b = blockIdx.z;
    const int qrow0 = qi * 64;
    const int m0 = wid * 16;
    const int lr = lane & 7;
    const int lg = lane >> 3;

    const int nkt = qi + 1;

    // ---- load Q tile (64 rows; hi at Q_OFF, lo at Q_OFF+8KB) ----
#pragma unroll
    for (int t = 0; t < 4; t++) {
        const int idx = tid + t * 128;             // 0..511
        const int r = idx >> 3;
        const int c16 = (idx & 7) << 4;
        const uint32_t sw = SWZ128(r * 128 + c16);
        const size_t grow = (size_t)(b * SEQT + qrow0 + r) * CDIM + h * HDIM;
        CP16(sbase + Q_OFF + sw, (const char*)(Qhi + grow) + c16);
        CP16(sbase + Q_OFF + 8192 + sw, (const char*)(Qlo + grow) + c16);
    }
    CP_COMMIT();

    auto load_kv = [&](int kt) {
        const uint32_t sb = sbase + (uint32_t)(kt % 3) * KV_BUF;
#pragma unroll
        for (int t = 0; t < 4; t++) {
            const int idx = tid + t * 128;         // 0..511
            const int r = idx >> 3;
            const int c16 = (idx & 7) << 4;
            const uint32_t sw = SWZ128(r * 128 + c16);
            const size_t grow = (size_t)(b * SEQT + kt * 64 + r) * CDIM + h * HDIM;
            CP16(sb + O_KHI + sw, (const char*)(Khi + grow) + c16);
            CP16(sb + O_VHI + sw, (const char*)(Vhi + grow) + c16);
        }
        CP_COMMIT();
    };
    load_kv(0);
    if (nkt > 1) load_kv(1);

    // ---- Q landed for all threads (kv0/kv1 may fly); hoist Q fragments ----
    if (nkt > 1) { CP_WAIT2(); } else { CP_WAIT1(); }
    __syncthreads();
    uint32_t qfh[4][4], qfl[4][4];
#pragma unroll
    for (int s = 0; s < 4; s++) {
        const uint32_t sw = SWZ128((m0 + ((lg & 1) << 3) + lr) * 128
                                   + s * 32 + ((lg >> 1) << 4));
        ldsm_x4(qfh[s], sbase + Q_OFF + sw);
        ldsm_x4(qfl[s], sbase + Q_OFF + 8192 + sw);
    }

    float o[8][4];
#pragma unroll
    for (int j = 0; j < 8; j++)
#pragma unroll
        for (int r = 0; r < 4; r++) o[j][r] = 0.0f;
    float mR[2] = {-1e30f, -1e30f};
    float lR[2] = {0.0f, 0.0f};

    for (int kt = 0; kt < nkt; kt++) {
        if (kt + 1 < nkt) { CP_WAIT1(); } else { CP_WAIT0(); }
        __syncthreads();   // everyone's writes visible; prev-iter reads done
        if (kt + 2 < nkt) load_kv(kt + 2);
        const uint32_t kb = sbase + (uint32_t)(kt % 3) * KV_BUF;

        // ---- S = Q @ K^T (Q fp16 split x K single: 2 combos) ----
        float sacc[8][4];
#pragma unroll
        for (int j = 0; j < 8; j++)
#pragma unroll
            for (int r = 0; r < 4; r++) sacc[j][r] = 0.0f;

#pragma unroll
        for (int s = 0; s < 4; s++) {
#pragma unroll
            for (int p = 0; p < 4; p++) {
                const uint32_t sw = SWZ128((p * 16 + ((lg >> 1) << 3) + lr) * 128
                                           + s * 32 + ((lg & 1) << 4));
                uint32_t kh[4];
                ldsm_x4(kh, kb + O_KHI + sw);
                mma16816h(sacc[2 * p],     qfh[s], &kh[0]);
                mma16816h(sacc[2 * p + 1], qfh[s], &kh[2]);
                mma16816h(sacc[2 * p],     qfl[s], &kh[0]);
                mma16816h(sacc[2 * p + 1], qfl[s], &kh[2]);
            }
        }

        // ---- causal mask (only the diagonal tile kt == qi) ----
        if (kt == nkt - 1) {
            const int qg0 = qrow0 + m0 + (lane >> 2);
            const int qg1 = qg0 + 8;
#pragma unroll
            for (int j = 0; j < 8; j++) {
                const int kg = kt * 64 + j * 8 + ((lane & 3) << 1);
                if (kg > qg0)     sacc[j][0] = -1e30f;
                if (kg + 1 > qg0) sacc[j][1] = -1e30f;
                if (kg > qg1)     sacc[j][2] = -1e30f;
                if (kg + 1 > qg1) sacc[j][3] = -1e30f;
            }
        }

        // ---- online softmax (scores already in log2 units) ----
        float mp0 = sacc[0][0], mp1 = sacc[0][2];
#pragma unroll
        for (int j = 0; j < 8; j++) {
            mp0 = fmaxf(mp0, fmaxf(sacc[j][0], sacc[j][1]));
            mp1 = fmaxf(mp1, fmaxf(sacc[j][2], sacc[j][3]));
        }
        mp0 = fmaxf(mp0, __shfl_xor_sync(0xffffffffu, mp0, 1));
        mp0 = fmaxf(mp0, __shfl_xor_sync(0xffffffffu, mp0, 2));
        mp1 = fmaxf(mp1, __shfl_xor_sync(0xffffffffu, mp1, 1));
        mp1 = fmaxf(mp1, __shfl_xor_sync(0xffffffffu, mp1, 2));
        const float mn0 = fmaxf(mR[0], mp0);
        const float mn1 = fmaxf(mR[1], mp1);
        const float f0 = fast_ex2(mR[0] - mn0);
        const float f1 = fast_ex2(mR[1] - mn1);
        float sum0 = 0.0f, sum1 = 0.0f;
#pragma unroll
        for (int j = 0; j < 8; j++) {
            sacc[j][0] = fast_ex2(sacc[j][0] - mn0);
            sacc[j][1] = fast_ex2(sacc[j][1] - mn0);
            sacc[j][2] = fast_ex2(sacc[j][2] - mn1);
            sacc[j][3] = fast_ex2(sacc[j][3] - mn1);
            sum0 += sacc[j][0] + sacc[j][1];
            sum1 += sacc[j][2] + sacc[j][3];
        }
        sum0 += __shfl_xor_sync(0xffffffffu, sum0, 1);
        sum0 += __shfl_xor_sync(0xffffffffu, sum0, 2);
        sum1 += __shfl_xor_sync(0xffffffffu, sum1, 1);
        sum1 += __shfl_xor_sync(0xffffffffu, sum1, 2);
        lR[0] = lR[0] * f0 + sum0;
        lR[1] = lR[1] * f1 + sum1;
        mR[0] = mn0;
        mR[1] = mn1;
#pragma unroll
        for (int j = 0; j < 8; j++) {
            o[j][0] *= f0; o[j][1] *= f0;
            o[j][2] *= f1; o[j][3] *= f1;
        }

        // ---- O += P @ V (P single fp16 in regs, V single fp16 from smem) ----
#pragma unroll
        for (int s2 = 0; s2 < 4; s2++) {
            uint32_t ph[4];
#pragma unroll
            for (int half = 0; half < 2; half++) {
                const int jt = 2 * s2 + half;
                __half2 p0 = __floats2half2_rn(sacc[jt][0], sacc[jt][1]);
                __half2 p1 = __floats2half2_rn(sacc[jt][2], sacc[jt][3]);
                ph[2 * half]     = *(uint32_t*)&p0;
                ph[2 * half + 1] = *(uint32_t*)&p1;
            }
#pragma unroll
            for (int dp = 0; dp < 4; dp++) {
                const uint32_t sw = SWZ128((s2 * 16 + ((lg & 1) << 3) + lr) * 128
                                           + dp * 32 + ((lg >> 1) << 4));
                uint32_t vh[4];
                ldsm_x4_trans(vh, kb + O_VHI + sw);
                mma16816h(o[2 * dp],     ph, &vh[0]);
                mma16816h(o[2 * dp + 1], ph, &vh[2]);
            }
        }
    }

    // ---- normalize + write bf16 hi/lo (Wo GEMM input format) ----
    const float inv0 = 1.0f / lR[0];
    const float inv1 = 1.0f / lR[1];
    const int r0 = b * SEQT + qrow0 + m0 + (lane >> 2);
#pragma unroll
    for (int j = 0; j < 8; j++) {
        const int col = h * HDIM + j * 8 + ((lane & 3) << 1);
        const float c0 = o[j][0] * inv0, c1 = o[j][1] * inv0;
        const float c2 = o[j][2] * inv1, c3 = o[j][3] * inv1;
        __nv_bfloat162 h0 = __floats2bfloat162_rn(c0, c1);
        float2 hf0 = __bfloat1622float2(h0);
        __nv_bfloat162 l0 = __floats2bfloat162_rn(c0 - hf0.x, c1 - hf0.y);
        __nv_bfloat162 h1 = __floats2bfloat162_rn(c2, c3);
        float2 hf1 = __bfloat1622float2(h1);
        __nv_bfloat162 l1 = __floats2bfloat162_rn(c2 - hf1.x, c3 - hf1.y);
        *(__nv_bfloat162*)&Ohi[(size_t)r0 * CDIM + col] = h0;
        *(__nv_bfloat162*)&Olo[(size_t)r0 * CDIM + col] = l0;
        *(__nv_bfloat162*)&Ohi[(size_t)(r0 + 8) * CDIM + col] = h1;
        *(__nv_bfloat162*)&Olo[(size_t)(r0 + 8) * CDIM + col] = l1;
    }
}

// ---------------------------------------------------------------------------
// Launch
// ---------------------------------------------------------------------------
extern "C" void kernel_launch(void* const* d_in, const int* in_sizes, int n_in,
                              void* d_out, int out_size)
{
    (void)in_sizes; (void)n_in; (void)out_size;
    const float* x  = (const float*)d_in[0];
    const float* Wq = (const float*)d_in[1];
    const float* bq = (const float*)d_in[2];
    const float* Wk = (const float*)d_in[3];
    const float* bk = (const float*)d_in[4];
    const float* Wv = (const float*)d_in[5];
    const float* bv = (const float*)d_in[6];
    const float* Wo = (const float*)d_in[7];
    const float* bo = (const float*)d_in[8];
    float* out = (float*)d_out;

    __nv_bfloat16 *xhi, *xlo, *ahi, *alo, *wthi, *wtlo;
    __half *qhi, *qlo, *khi, *vhi;
    cudaGetSymbolAddress((void**)&xhi,  g_xhi);
    cudaGetSymbolAddress((void**)&xlo,  g_xlo);
    cudaGetSymbolAddress((void**)&qhi,  g_qhi);
    cudaGetSymbolAddress((void**)&qlo,  g_qlo);
    cudaGetSymbolAddress((void**)&khi,  g_khi);
    cudaGetSymbolAddress((void**)&vhi,  g_vhi);
    cudaGetSymbolAddress((void**)&ahi,  g_ahi);
    cudaGetSymbolAddress((void**)&alo,  g_alo);
    cudaGetSymbolAddress((void**)&wthi, g_wthi);
    cudaGetSymbolAddress((void**)&wtlo, g_wtlo);

    cudaFuncSetAttribute(gemm_mma_split<true>,
                         cudaFuncAttributeMaxDynamicSharedMemorySize, GEMM_SMEM);
    cudaFuncSetAttribute(gemm_mma_split<false>,
                         cudaFuncAttributeMaxDynamicSharedMemorySize, GEMM_SMEM);
    cudaFuncSetAttribute(flash_attn_mma,
                         cudaFuncAttributeMaxDynamicSharedMemorySize, FA_SMEM);

    const int nelem = MROWS * CDIM;

    split_f32<<<(nelem + 255) / 256, 256>>>(x, xhi, xlo, nelem);

    dim3 wt_grid(CDIM / 32, CDIM / 32, 4);
    dim3 wt_blk(32, 8);
    wtrans_split4<<<wt_grid, wt_blk>>>(Wq, Wk, Wv, Wo, wthi, wtlo);

    dim3 qkv_grid(36, MROWS / 128);
    gemm_mma_split<true><<<qkv_grid, 256, GEMM_SMEM>>>(
        xhi, xlo, wthi, wtlo, bq, bk, bv,
        nullptr, qhi, qlo, khi, vhi);

    dim3 fa_grid(SEQT / 64, NHEAD, BATCH);     // (32, 12, 4) = 1536 CTAs
    flash_attn_mma<<<fa_grid, 128, FA_SMEM>>>(qhi, qlo, khi, vhi, ahi, alo);

    dim3 wo_grid(12, MROWS / 128);
    gemm_mma_split<false><<<wo_grid, 256, GEMM_SMEM>>>(
        ahi, alo, wthi, wtlo, bo, nullptr, nullptr,
        out, nullptr, nullptr, nullptr, nullptr);
}

// round 14
// speedup vs baseline: 1.7001x; 1.3004x over previous
#include <cuda_runtime.h>
#include <cuda_bf16.h>
#include <cuda_fp16.h>
#include <math.h>
#include <stdint.h>

#define BATCH 4
#define SEQT 2048
#define CDIM 768
#define NHEAD 12
#define HDIM 64
#define MROWS (BATCH * SEQT)   // 8192

// ---------------------------------------------------------------------------
// Scratch (allocation-free rule: device globals)
// ---------------------------------------------------------------------------
__device__ __half g_xhi[(size_t)MROWS * CDIM];
__device__ __half g_xlo[(size_t)MROWS * CDIM];
__device__ __half g_q[(size_t)MROWS * CDIM];     // Q single fp16 (pre-scaled)
__device__ __half g_k[(size_t)MROWS * CDIM];     // K single fp16
__device__ __half g_v[(size_t)MROWS * CDIM];     // V single fp16
__device__ __half g_ahi[(size_t)MROWS * CDIM];   // attention out hi
__device__ __half g_alo[(size_t)MROWS * CDIM];   // attention out lo
// transposed weights, single fp16: [4][N=CDIM][K=CDIM] (Wq, Wk, Wv, Wo)
__device__ __half g_wt[4 * (size_t)CDIM * CDIM];

// ---------------------------------------------------------------------------
// PTX helpers (sm_80-era: legal under .target sm_103)
// ---------------------------------------------------------------------------
__device__ __forceinline__ uint32_t smem_to_u32(const void* p) {
    uint32_t a;
    asm("{ .reg .u64 t; cvta.to.shared.u64 t, %1; cvt.u32.u64 %0, t; }"
        : "=r"(a) : "l"(p));
    return a;
}

__device__ __forceinline__ void ldsm_x4(uint32_t* r, uint32_t addr) {
    asm volatile("ldmatrix.sync.aligned.m8n8.x4.shared.b16 {%0,%1,%2,%3}, [%4];"
        : "=r"(r[0]), "=r"(r[1]), "=r"(r[2]), "=r"(r[3]) : "r"(addr));
}

__device__ __forceinline__ void ldsm_x4_trans(uint32_t* r, uint32_t addr) {
    asm volatile("ldmatrix.sync.aligned.m8n8.x4.trans.shared.b16 {%0,%1,%2,%3}, [%4];"
        : "=r"(r[0]), "=r"(r[1]), "=r"(r[2]), "=r"(r[3]) : "r"(addr));
}

// fp16 MMA
__device__ __forceinline__ void mma16816h(float* c, const uint32_t* a, const uint32_t* b) {
    asm volatile(
        "mma.sync.aligned.m16n8k16.row.col.f32.f16.f16.f32 "
        "{%0,%1,%2,%3}, {%4,%5,%6,%7}, {%8,%9}, {%0,%1,%2,%3};"
        : "+f"(c[0]), "+f"(c[1]), "+f"(c[2]), "+f"(c[3])
        : "r"(a[0]), "r"(a[1]), "r"(a[2]), "r"(a[3]), "r"(b[0]), "r"(b[1]));
}

__device__ __forceinline__ float fast_ex2(float x) {
    float y;
    asm("ex2.approx.f32 %0, %1;" : "=f"(y) : "f"(x));
    return y;
}

#define CP16(dst, src) \
    asm volatile("cp.async.cg.shared.global [%0], [%1], 16;" \
                 :: "r"(dst), "l"(src) : "memory")
#define CP_COMMIT() asm volatile("cp.async.commit_group;" ::: "memory")
#define CP_WAIT2()  asm volatile("cp.async.wait_group 2;" ::: "memory")
#define CP_WAIT1()  asm volatile("cp.async.wait_group 1;" ::: "memory")
#define CP_WAIT0()  asm volatile("cp.async.wait_group 0;" ::: "memory")

#define SWZ128(off) ((off) ^ (((off) >> 3) & 0x70))

// 0.125 * log2(e): folded into Q at the QKV GEMM epilogue
#define QK_SCALE 0.18033688011112042f

// ---------------------------------------------------------------------------
// Conversion kernels
// ---------------------------------------------------------------------------
__global__ void split_f32(const float* __restrict__ in,
                          __half* __restrict__ hi,
                          __half* __restrict__ lo, int n) {
    int i = blockIdx.x * blockDim.x + threadIdx.x;
    if (i < n) {
        float v = in[i];
        __half h = __float2half_rn(v);
        float r = v - __half2float(h);
        hi[i] = h;
        lo[i] = __float2half_rn(r);
    }
}

// 4 weights W[k][n] (fp32) -> Wt[z][n][k] single fp16, tiled transpose
__global__ void wtrans4(const float* __restrict__ W0, const float* __restrict__ W1,
                        const float* __restrict__ W2, const float* __restrict__ W3,
                        __half* __restrict__ wt) {
    __shared__ float t[32][33];
    const int z = blockIdx.z;
    const float* W = (z == 0) ? W0 : (z == 1) ? W1 : (z == 2) ? W2 : W3;
    const size_t zoff = (size_t)z * CDIM * CDIM;
    const int kx = blockIdx.x * 32;
    const int nx = blockIdx.y * 32;
    const int tx = threadIdx.x, ty = threadIdx.y;
    for (int j = ty; j < 32; j += 8)
        t[j][tx] = W[(size_t)(kx + j) * CDIM + nx + tx];
    __syncthreads();
    for (int j = ty; j < 32; j += 8)
        wt[zoff + (size_t)(nx + j) * CDIM + kx + tx] = __float2half_rn(t[tx][j]);
}

// ---------------------------------------------------------------------------
// fp16 GEMM: C = A @ W + bias. A fp16 hi/lo (2 combos), W single fp16.
//   128x64 tile, 2 stages, 2 CTAs/SM.
//   SPLIT_OUT=true: fused QKV -> single fp16 outputs (Q pre-scaled).
//   SPLIT_OUT=false: Wo -> fp32 output.
// ---------------------------------------------------------------------------
#define GK 64
#define NCHUNK (CDIM / GK)        // 12
#define CH_BYTES 40960            // A 2x16KB + B 8KB
#define GEMM_SMEM (2 * CH_BYTES)  // 81920
#define T_AHI 0
#define T_ALO 16384
#define T_B   32768

template <bool SPLIT_OUT>
__global__ __launch_bounds__(256, 2) void gemm_mma_fp16(
    const __half* __restrict__ Ahi, const __half* __restrict__ Alo,
    const __half* __restrict__ Wt,
    const float* __restrict__ b0, const float* __restrict__ b1,
    const float* __restrict__ b2,
    float* __restrict__ Cout,
    __half* __restrict__ C0, __half* __restrict__ C1, __half* __restrict__ C2)
{
    extern __shared__ char smem[];
    const uint32_t sbase = smem_to_u32(smem);
    const int tid = threadIdx.x;
    const int lane = tid & 31;
    const int wid = tid >> 5;
    const int warp_m = wid >> 1;
    const int warp_n = wid & 1;
    const int row0 = blockIdx.y * 128;

    int wsel, col0;
    if (SPLIT_OUT) { wsel = blockIdx.x / 12; col0 = (blockIdx.x % 12) * 64; }
    else           { wsel = 3;              col0 = blockIdx.x * 64; }

    const size_t WSZ = (size_t)CDIM * CDIM;
    const __half* B = Wt + (size_t)wsel * WSZ;
    const float* bias = SPLIT_OUT ? (wsel == 0 ? b0 : wsel == 1 ? b1 : b2) : b0;
    __half* Cov = SPLIT_OUT ? (wsel == 0 ? C0 : wsel == 1 ? C1 : C2) : nullptr;
    const float oscale = (SPLIT_OUT && wsel == 0) ? QK_SCALE : 1.0f;

    const int lrow = lane & 7;
    const int lgrp = lane >> 3;
    const int a_roff = ((lgrp & 1) << 3) + lrow;
    const int a_kh   = (lgrp >> 1) << 4;
    const int b_roff = ((lgrp >> 1) << 3) + lrow;
    const int b_kh   = (lgrp & 1) << 4;

    const int ld_r   = tid >> 3;
    const int ld_c16 = (tid & 7) << 4;

    float acc[2][4][4];
#pragma unroll
    for (int i = 0; i < 2; i++)
#pragma unroll
        for (int j = 0; j < 4; j++)
#pragma unroll
            for (int r = 0; r < 4; r++) acc[i][j][r] = 0.0f;

    auto load_chunk = [&](int kc, int stage) {
        const uint32_t sb = sbase + stage * CH_BYTES;
        const int kcol = kc * GK;
#pragma unroll
        for (int t = 0; t < 4; t++) {   // A hi+lo: 128 rows each
            const int r = ld_r + t * 32;
            const uint32_t sw = SWZ128(r * 128 + ld_c16);
            const char* pa  = (const char*)(Ahi + (size_t)(row0 + r) * CDIM + kcol) + ld_c16;
            const char* pal = (const char*)(Alo + (size_t)(row0 + r) * CDIM + kcol) + ld_c16;
            CP16(sb + T_AHI + sw, pa);
            CP16(sb + T_ALO + sw, pal);
        }
#pragma unroll
        for (int t = 0; t < 2; t++) {   // B: 64 rows single
            const int idx = tid + t * 256;
            const int r = idx >> 3;
            const int c16 = (idx & 7) << 4;
            const uint32_t sw = SWZ128(r * 128 + c16);
            const char* pb = (const char*)(B + (size_t)(col0 + r) * CDIM + kcol) + c16;
            CP16(sb + T_B + sw, pb);
        }
        CP_COMMIT();
    };

    load_chunk(0, 0);

    for (int kc = 0; kc < NCHUNK; kc++) {
        CP_WAIT0();
        __syncthreads();
        if (kc + 1 < NCHUNK) load_chunk(kc + 1, (kc + 1) & 1);

        const uint32_t sb = sbase + (kc & 1) * CH_BYTES;
#pragma unroll
        for (int s = 0; s < 4; s++) {
            const int kb = s * 32;
            uint32_t ahi[2][4], alo[2][4];
#pragma unroll
            for (int i = 0; i < 2; i++) {
                const uint32_t off =
                    SWZ128((warp_m * 32 + i * 16 + a_roff) * 128 + kb + a_kh);
                ldsm_x4(ahi[i], sb + T_AHI + off);
                ldsm_x4(alo[i], sb + T_ALO + off);
            }
            uint32_t bf[4][2];
#pragma unroll
            for (int j2 = 0; j2 < 2; j2++) {
                const uint32_t off =
                    SWZ128((warp_n * 32 + j2 * 16 + b_roff) * 128 + kb + b_kh);
                uint32_t t[4];
                ldsm_x4(t, sb + T_B + off);
                bf[2 * j2][0] = t[0]; bf[2 * j2][1] = t[1];
                bf[2 * j2 + 1][0] = t[2]; bf[2 * j2 + 1][1] = t[3];
            }
#pragma unroll
            for (int i = 0; i < 2; i++)
#pragma unroll
                for (int j = 0; j < 4; j++)
                    mma16816h(acc[i][j], ahi[i], bf[j]);
#pragma unroll
            for (int i = 0; i < 2; i++)
#pragma unroll
                for (int j = 0; j < 4; j++)
                    mma16816h(acc[i][j], alo[i], bf[j]);
        }
    }

    // ---- epilogue ----
#pragma unroll
    for (int i = 0; i < 2; i++) {
        const int mrow = row0 + warp_m * 32 + i * 16 + (lane >> 2);
#pragma unroll
        for (int j = 0; j < 4; j++) {
            const int ncol = col0 + warp_n * 32 + j * 8 + ((lane & 3) << 1);
            const float2 bv = *(const float2*)&bias[ncol];
            const float c0 = (acc[i][j][0] + bv.x) * oscale;
            const float c1 = (acc[i][j][1] + bv.y) * oscale;
            const float c2 = (acc[i][j][2] + bv.x) * oscale;
            const float c3 = (acc[i][j][3] + bv.y) * oscale;
            if (SPLIT_OUT) {
                *(__half2*)&Cov[(size_t)mrow * CDIM + ncol] = __floats2half2_rn(c0, c1);
                *(__half2*)&Cov[(size_t)(mrow + 8) * CDIM + ncol] = __floats2half2_rn(c2, c3);
            } else {
                float2 o0, o1;
                o0.x = c0; o0.y = c1;
                o1.x = c2; o1.y = c3;
                *(float2*)&Cout[(size_t)mrow * CDIM + ncol] = o0;
                *(float2*)&Cout[(size_t)(mrow + 8) * CDIM + ncol] = o1;
            }
        }
    }
}

// ---------------------------------------------------------------------------
// Flash attention (causal), minimal fp16 datapath:
//   Q single fp16 (register-resident, pre-scaled), K single, V single.
//   QK: 1 combo. PV: 1 combo. 64 MMAs/tile.
//   BQ=64, 128 threads, 2 CTAs/SM, 3 KV buffers (16KB each, distance 2).
//   Output fp16 hi/lo (feeds Wo GEMM).
// ---------------------------------------------------------------------------
#define KV_BUF 16384
#define O_KHI 0
#define O_VHI 8192
#define Q_OFF (3 * KV_BUF)             // 49152
#define FA_SMEM (3 * KV_BUF + 8192)    // 57344

__global__ __launch_bounds__(128, 2) void flash_attn_mma(
    const __half* __restrict__ Qg,
    const __half* __restrict__ Kg,
    const __half* __restrict__ Vg,
    __half* __restrict__ Ohi, __half* __restrict__ Olo)
{
    extern __shared__ char smem[];
    const uint32_t sbase = smem_to_u32(smem);
    const int tid = threadIdx.x;
    const int lane = tid & 31;
    const int wid = tid >> 5;                      // 0..3
    const int qi = (gridDim.x - 1) - blockIdx.x;   // heavy CTAs first
    const int h = blockIdx.y;
    const int b = blockIdx.z;
    const int qrow0 = qi * 64;
    const int m0 = wid * 16;
    const int lr = lane & 7;
    const int lg = lane >> 3;

    const int nkt = qi + 1;

    // ---- load Q tile (64 rows x 128B) ----
#pragma unroll
    for (int t = 0; t < 4; t++) {
        const int idx = tid + t * 128;             // 0..511
        const int r = idx >> 3;
        const int c16 = (idx & 7) << 4;
        const uint32_t sw = SWZ128(r * 128 + c16);
        const size_t grow = (size_t)(b * SEQT + qrow0 + r) * CDIM + h * HDIM;
        CP16(sbase + Q_OFF + sw, (const char*)(Qg + grow) + c16);
    }
    CP_COMMIT();

    auto load_kv = [&](int kt) {
        const uint32_t sb = sbase + (uint32_t)(kt % 3) * KV_BUF;
#pragma unroll
        for (int t = 0; t < 4; t++) {
            const int idx = tid + t * 128;         // 0..511
            const int r = idx >> 3;
            const int c16 = (idx & 7) << 4;
            const uint32_t sw = SWZ128(r * 128 + c16);
            const size_t grow = (size_t)(b * SEQT + kt * 64 + r) * CDIM + h * HDIM;
            CP16(sb + O_KHI + sw, (const char*)(Kg + grow) + c16);
            CP16(sb + O_VHI + sw, (const char*)(Vg + grow) + c16);
        }
        CP_COMMIT();
    };
    load_kv(0);
    if (nkt > 1) load_kv(1);

    // ---- Q landed (kv0/kv1 may fly); hoist Q fragments ----
    if (nkt > 1) { CP_WAIT2(); } else { CP_WAIT1(); }
    __syncthreads();
    uint32_t qf[4][4];
#pragma unroll
    for (int s = 0; s < 4; s++) {
        const uint32_t sw = SWZ128((m0 + ((lg & 1) << 3) + lr) * 128
                                   + s * 32 + ((lg >> 1) << 4));
        ldsm_x4(qf[s], sbase + Q_OFF + sw);
    }

    float o[8][4];
#pragma unroll
    for (int j = 0; j < 8; j++)
#pragma unroll
        for (int r = 0; r < 4; r++) o[j][r] = 0.0f;
    float mR[2] = {-1e30f, -1e30f};
    float lR[2] = {0.0f, 0.0f};

    for (int kt = 0; kt < nkt; kt++) {
        if (kt + 1 < nkt) { CP_WAIT1(); } else { CP_WAIT0(); }
        __syncthreads();   // everyone's writes visible; prev-iter reads done
        if (kt + 2 < nkt) load_kv(kt + 2);
        const uint32_t kb = sbase + (uint32_t)(kt % 3) * KV_BUF;

        // ---- S = Q @ K^T (single fp16: 1 combo) ----
        float sacc[8][4];
#pragma unroll
        for (int j = 0; j < 8; j++)
#pragma unroll
            for (int r = 0; r < 4; r++) sacc[j][r] = 0.0f;

#pragma unroll
        for (int s = 0; s < 4; s++) {
#pragma unroll
            for (int p = 0; p < 4; p++) {
                const uint32_t sw = SWZ128((p * 16 + ((lg >> 1) << 3) + lr) * 128
                                           + s * 32 + ((lg & 1) << 4));
                uint32_t kh[4];
                ldsm_x4(kh, kb + O_KHI + sw);
                mma16816h(sacc[2 * p],     qf[s], &kh[0]);
                mma16816h(sacc[2 * p + 1], qf[s], &kh[2]);
            }
        }

        // ---- causal mask (only the diagonal tile kt == qi) ----
        if (kt == nkt - 1) {
            const int qg0 = qrow0 + m0 + (lane >> 2);
            const int qg1 = qg0 + 8;
#pragma unroll
            for (int j = 0; j < 8; j++) {
                const int kg = kt * 64 + j * 8 + ((lane & 3) << 1);
                if (kg > qg0)     sacc[j][0] = -1e30f;
                if (kg + 1 > qg0) sacc[j][1] = -1e30f;
                if (kg > qg1)     sacc[j][2] = -1e30f;
                if (kg + 1 > qg1) sacc[j][3] = -1e30f;
            }
        }

        // ---- online softmax (scores already in log2 units) ----
        float mp0 = sacc[0][0], mp1 = sacc[0][2];
#pragma unroll
        for (int j = 0; j < 8; j++) {
            mp0 = fmaxf(mp0, fmaxf(sacc[j][0], sacc[j][1]));
            mp1 = fmaxf(mp1, fmaxf(sacc[j][2], sacc[j][3]));
        }
        mp0 = fmaxf(mp0, __shfl_xor_sync(0xffffffffu, mp0, 1));
        mp0 = fmaxf(mp0, __shfl_xor_sync(0xffffffffu, mp0, 2));
        mp1 = fmaxf(mp1, __shfl_xor_sync(0xffffffffu, mp1, 1));
        mp1 = fmaxf(mp1, __shfl_xor_sync(0xffffffffu, mp1, 2));
        const float mn0 = fmaxf(mR[0], mp0);
        const float mn1 = fmaxf(mR[1], mp1);
        const float f0 = fast_ex2(mR[0] - mn0);
        const float f1 = fast_ex2(mR[1] - mn1);
        float sum0 = 0.0f, sum1 = 0.0f;
#pragma unroll
        for (int j = 0; j < 8; j++) {
            sacc[j][0] = fast_ex2(sacc[j][0] - mn0);
            sacc[j][1] = fast_ex2(sacc[j][1] - mn0);
            sacc[j][2] = fast_ex2(sacc[j][2] - mn1);
            sacc[j][3] = fast_ex2(sacc[j][3] - mn1);
            sum0 += sacc[j][0] + sacc[j][1];
            sum1 += sacc[j][2] + sacc[j][3];
        }
        sum0 += __shfl_xor_sync(0xffffffffu, sum0, 1);
        sum0 += __shfl_xor_sync(0xffffffffu, sum0, 2);
        sum1 += __shfl_xor_sync(0xffffffffu, sum1, 1);
        sum1 += __shfl_xor_sync(0xffffffffu, sum1, 2);
        lR[0] = lR[0] * f0 + sum0;
        lR[1] = lR[1] * f1 + sum1;
        mR[0] = mn0;
        mR[1] = mn1;
#pragma unroll
        for (int j = 0; j < 8; j++) {
            o[j][0] *= f0; o[j][1] *= f0;
            o[j][2] *= f1; o[j][3] *= f1;
        }

        // ---- O += P @ V (P single fp16, V single fp16: 1 combo) ----
#pragma unroll
        for (int s2 = 0; s2 < 4; s2++) {
            uint32_t ph[4];
#pragma unroll
            for (int half = 0; half < 2; half++) {
                const int jt = 2 * s2 + half;
                __half2 p0 = __floats2half2_rn(sacc[jt][0], sacc[jt][1]);
                __half2 p1 = __floats2half2_rn(sacc[jt][2], sacc[jt][3]);
                ph[2 * half]     = *(uint32_t*)&p0;
                ph[2 * half + 1] = *(uint32_t*)&p1;
            }
#pragma unroll
            for (int dp = 0; dp < 4; dp++) {
                const uint32_t sw = SWZ128((s2 * 16 + ((lg & 1) << 3) + lr) * 128
                                           + dp * 32 + ((lg >> 1) << 4));
                uint32_t vh[4];
                ldsm_x4_trans(vh, kb + O_VHI + sw);
                mma16816h(o[2 * dp],     ph, &vh[0]);
                mma16816h(o[2 * dp + 1], ph, &vh[2]);
            }
        }
    }

    // ---- normalize + write fp16 hi/lo (Wo GEMM input format) ----
    const float inv0 = 1.0f / lR[0];
    const float inv1 = 1.0f / lR[1];
    const int r0 = b * SEQT + qrow0 + m0 + (lane >> 2);
#pragma unroll
    for (int j = 0; j < 8; j++) {
        const int col = h * HDIM + j * 8 + ((lane & 3) << 1);
        const float c0 = o[j][0] * inv0, c1 = o[j][1] * inv0;
        const float c2 = o[j][2] * inv1, c3 = o[j][3] * inv1;
        __half2 h0 = __floats2half2_rn(c0, c1);
        float2 hf0 = __half22float2(h0);
        __half2 l0 = __floats2half2_rn(c0 - hf0.x, c1 - hf0.y);
        __half2 h1 = __floats2half2_rn(c2, c3);
        float2 hf1 = __half22float2(h1);
        __half2 l1 = __floats2half2_rn(c2 - hf1.x, c3 - hf1.y);
        *(__half2*)&Ohi[(size_t)r0 * CDIM + col] = h0;
        *(__half2*)&Olo[(size_t)r0 * CDIM + col] = l0;
        *(__half2*)&Ohi[(size_t)(r0 + 8) * CDIM + col] = h1;
        *(__half2*)&Olo[(size_t)(r0 + 8) * CDIM + col] = l1;
    }
}

// ---------------------------------------------------------------------------
// Launch
// ---------------------------------------------------------------------------
extern "C" void kernel_launch(void* const* d_in, const int* in_sizes, int n_in,
                              void* d_out, int out_size)
{
    (void)in_sizes; (void)n_in; (void)out_size;
    const float* x  = (const float*)d_in[0];
    const float* Wq = (const float*)d_in[1];
    const float* bq = (const float*)d_in[2];
    const float* Wk = (const float*)d_in[3];
    const float* bk = (const float*)d_in[4];
    const float* Wv = (const float*)d_in[5];
    const float* bv = (const float*)d_in[6];
    const float* Wo = (const float*)d_in[7];
    const float* bo = (const float*)d_in[8];
    float* out = (float*)d_out;

    __half *xhi, *xlo, *q, *k, *v, *ahi, *alo, *wt;
    cudaGetSymbolAddress((void**)&xhi, g_xhi);
    cudaGetSymbolAddress((void**)&xlo, g_xlo);
    cudaGetSymbolAddress((void**)&q,   g_q);
    cudaGetSymbolAddress((void**)&k,   g_k);
    cudaGetSymbolAddress((void**)&v,   g_v);
    cudaGetSymbolAddress((void**)&ahi, g_ahi);
    cudaGetSymbolAddress((void**)&alo, g_alo);
    cudaGetSymbolAddress((void**)&wt,  g_wt);

    cudaFuncSetAttribute(gemm_mma_fp16<true>,
                         cudaFuncAttributeMaxDynamicSharedMemorySize, GEMM_SMEM);
    cudaFuncSetAttribute(gemm_mma_fp16<false>,
                         cudaFuncAttributeMaxDynamicSharedMemorySize, GEMM_SMEM);
    cudaFuncSetAttribute(flash_attn_mma,
                         cudaFuncAttributeMaxDynamicSharedMemorySize, FA_SMEM);

    const int nelem = MROWS * CDIM;

    // 1. split x -> fp16 hi/lo
    split_f32<<<(nelem + 255) / 256, 256>>>(x, xhi, xlo, nelem);

    // 2. transpose weights -> single fp16
    dim3 wt_grid(CDIM / 32, CDIM / 32, 4);
    dim3 wt_blk(32, 8);
    wtrans4<<<wt_grid, wt_blk>>>(Wq, Wk, Wv, Wo, wt);

    // 3. fused QKV projection (2 combos) -> single fp16 q/k/v
    dim3 qkv_grid(36, MROWS / 128);
    gemm_mma_fp16<true><<<qkv_grid, 256, GEMM_SMEM>>>(
        xhi, xlo, wt, bq, bk, bv, nullptr, q, k, v);

    // 4. flash attention (1-combo QK, 1-combo PV) -> fp16 hi/lo
    dim3 fa_grid(SEQT / 64, NHEAD, BATCH);     // (32, 12, 4) = 1536 CTAs
    flash_attn_mma<<<fa_grid, 128, FA_SMEM>>>(q, k, v, ahi, alo);

    // 5. output projection (2 combos) -> fp32 out
    dim3 wo_grid(12, MROWS / 128);
    gemm_mma_fp16<false><<<wo_grid, 256, GEMM_SMEM>>>(
        ahi, alo, wt, bo, nullptr, nullptr, out, nullptr, nullptr, nullptr);
}

// round 15
// speedup vs baseline: 1.7569x; 1.0334x over previous
#include <cuda_runtime.h>
#include <cuda_bf16.h>
#include <cuda_fp16.h>
#include <math.h>
#include <stdint.h>

#define BATCH 4
#define SEQT 2048
#define CDIM 768
#define NHEAD 12
#define HDIM 64
#define MROWS (BATCH * SEQT)   // 8192

// ---------------------------------------------------------------------------
// Scratch (allocation-free rule: device globals)
// ---------------------------------------------------------------------------
__device__ __half g_xhi[(size_t)MROWS * CDIM];
__device__ __half g_xlo[(size_t)MROWS * CDIM];
__device__ __half g_q[(size_t)MROWS * CDIM];     // Q single fp16 (pre-scaled)
__device__ __half g_k[(size_t)MROWS * CDIM];     // K single fp16
__device__ __half g_v[(size_t)MROWS * CDIM];     // V single fp16
__device__ __half g_ahi[(size_t)MROWS * CDIM];   // attention out hi
__device__ __half g_alo[(size_t)MROWS * CDIM];   // attention out lo
// transposed weights, single fp16: [4][N=CDIM][K=CDIM] (Wq, Wk, Wv, Wo)
__device__ __half g_wt[4 * (size_t)CDIM * CDIM];

// ---------------------------------------------------------------------------
// PTX helpers (sm_80-era: legal under .target sm_103)
// ---------------------------------------------------------------------------
__device__ __forceinline__ uint32_t smem_to_u32(const void* p) {
    uint32_t a;
    asm("{ .reg .u64 t; cvta.to.shared.u64 t, %1; cvt.u32.u64 %0, t; }"
        : "=r"(a) : "l"(p));
    return a;
}

__device__ __forceinline__ void ldsm_x4(uint32_t* r, uint32_t addr) {
    asm volatile("ldmatrix.sync.aligned.m8n8.x4.shared.b16 {%0,%1,%2,%3}, [%4];"
        : "=r"(r[0]), "=r"(r[1]), "=r"(r[2]), "=r"(r[3]) : "r"(addr));
}

__device__ __forceinline__ void ldsm_x4_trans(uint32_t* r, uint32_t addr) {
    asm volatile("ldmatrix.sync.aligned.m8n8.x4.trans.shared.b16 {%0,%1,%2,%3}, [%4];"
        : "=r"(r[0]), "=r"(r[1]), "=r"(r[2]), "=r"(r[3]) : "r"(addr));
}

// fp16 MMA
__device__ __forceinline__ void mma16816h(float* c, const uint32_t* a, const uint32_t* b) {
    asm volatile(
        "mma.sync.aligned.m16n8k16.row.col.f32.f16.f16.f32 "
        "{%0,%1,%2,%3}, {%4,%5,%6,%7}, {%8,%9}, {%0,%1,%2,%3};"
        : "+f"(c[0]), "+f"(c[1]), "+f"(c[2]), "+f"(c[3])
        : "r"(a[0]), "r"(a[1]), "r"(a[2]), "r"(a[3]), "r"(b[0]), "r"(b[1]));
}

__device__ __forceinline__ float fast_ex2(float x) {
    float y;
    asm("ex2.approx.f32 %0, %1;" : "=f"(y) : "f"(x));
    return y;
}

// two fp16 exponentials in one MUFU op
__device__ __forceinline__ uint32_t ex2_h2(float a, float b) {
    __half2 h = __floats2half2_rn(a, b);
    uint32_t r;
    asm("ex2.approx.f16x2 %0, %1;" : "=r"(r) : "r"(*(uint32_t*)&h));
    return r;
}

#define CP16(dst, src) \
    asm volatile("cp.async.cg.shared.global [%0], [%1], 16;" \
                 :: "r"(dst), "l"(src) : "memory")
#define CP_COMMIT() asm volatile("cp.async.commit_group;" ::: "memory")
#define CP_WAIT2()  asm volatile("cp.async.wait_group 2;" ::: "memory")
#define CP_WAIT1()  asm volatile("cp.async.wait_group 1;" ::: "memory")
#define CP_WAIT0()  asm volatile("cp.async.wait_group 0;" ::: "memory")

#define SWZ128(off) ((off) ^ (((off) >> 3) & 0x70))

// 0.125 * log2(e): folded into Q at the QKV GEMM epilogue
#define QK_SCALE 0.18033688011112042f

// ---------------------------------------------------------------------------
// Conversion kernels
// ---------------------------------------------------------------------------
__global__ void split_f32(const float* __restrict__ in,
                          __half* __restrict__ hi,
                          __half* __restrict__ lo, int n) {
    int i = blockIdx.x * blockDim.x + threadIdx.x;
    if (i < n) {
        float v = in[i];
        __half h = __float2half_rn(v);
        float r = v - __half2float(h);
        hi[i] = h;
        lo[i] = __float2half_rn(r);
    }
}

__global__ void wtrans4(const float* __restrict__ W0, const float* __restrict__ W1,
                        const float* __restrict__ W2, const float* __restrict__ W3,
                        __half* __restrict__ wt) {
    __shared__ float t[32][33];
    const int z = blockIdx.z;
    const float* W = (z == 0) ? W0 : (z == 1) ? W1 : (z == 2) ? W2 : W3;
    const size_t zoff = (size_t)z * CDIM * CDIM;
    const int kx = blockIdx.x * 32;
    const int nx = blockIdx.y * 32;
    const int tx = threadIdx.x, ty = threadIdx.y;
    for (int j = ty; j < 32; j += 8)
        t[j][tx] = W[(size_t)(kx + j) * CDIM + nx + tx];
    __syncthreads();
    for (int j = ty; j < 32; j += 8)
        wt[zoff + (size_t)(nx + j) * CDIM + kx + tx] = __float2half_rn(t[tx][j]);
}

// ---------------------------------------------------------------------------
// fp16 GEMM: C = A @ W + bias. A fp16 hi/lo (2 combos), W single fp16.
//   (unchanged from R14)
// ---------------------------------------------------------------------------
#define GK 64
#define NCHUNK (CDIM / GK)        // 12
#define CH_BYTES 40960
#define GEMM_SMEM (2 * CH_BYTES)  // 81920
#define T_AHI 0
#define T_ALO 16384
#define T_B   32768

template <bool SPLIT_OUT>
__global__ __launch_bounds__(256, 2) void gemm_mma_fp16(
    const __half* __restrict__ Ahi, const __half* __restrict__ Alo,
    const __half* __restrict__ Wt,
    const float* __restrict__ b0, const float* __restrict__ b1,
    const float* __restrict__ b2,
    float* __restrict__ Cout,
    __half* __restrict__ C0, __half* __restrict__ C1, __half* __restrict__ C2)
{
    extern __shared__ char smem[];
    const uint32_t sbase = smem_to_u32(smem);
    const int tid = threadIdx.x;
    const int lane = tid & 31;
    const int wid = tid >> 5;
    const int warp_m = wid >> 1;
    const int warp_n = wid & 1;
    const int row0 = blockIdx.y * 128;

    int wsel, col0;
    if (SPLIT_OUT) { wsel = blockIdx.x / 12; col0 = (blockIdx.x % 12) * 64; }
    else           { wsel = 3;              col0 = blockIdx.x * 64; }

    const size_t WSZ = (size_t)CDIM * CDIM;
    const __half* B = Wt + (size_t)wsel * WSZ;
    const float* bias = SPLIT_OUT ? (wsel == 0 ? b0 : wsel == 1 ? b1 : b2) : b0;
    __half* Cov = SPLIT_OUT ? (wsel == 0 ? C0 : wsel == 1 ? C1 : C2) : nullptr;
    const float oscale = (SPLIT_OUT && wsel == 0) ? QK_SCALE : 1.0f;

    const int lrow = lane & 7;
    const int lgrp = lane >> 3;
    const int a_roff = ((lgrp & 1) << 3) + lrow;
    const int a_kh   = (lgrp >> 1) << 4;
    const int b_roff = ((lgrp >> 1) << 3) + lrow;
    const int b_kh   = (lgrp & 1) << 4;

    const int ld_r   = tid >> 3;
    const int ld_c16 = (tid & 7) << 4;

    float acc[2][4][4];
#pragma unroll
    for (int i = 0; i < 2; i++)
#pragma unroll
        for (int j = 0; j < 4; j++)
#pragma unroll
            for (int r = 0; r < 4; r++) acc[i][j][r] = 0.0f;

    auto load_chunk = [&](int kc, int stage) {
        const uint32_t sb = sbase + stage * CH_BYTES;
        const int kcol = kc * GK;
#pragma unroll
        for (int t = 0; t < 4; t++) {
            const int r = ld_r + t * 32;
            const uint32_t sw = SWZ128(r * 128 + ld_c16);
            const char* pa  = (const char*)(Ahi + (size_t)(row0 + r) * CDIM + kcol) + ld_c16;
            const char* pal = (const char*)(Alo + (size_t)(row0 + r) * CDIM + kcol) + ld_c16;
            CP16(sb + T_AHI + sw, pa);
            CP16(sb + T_ALO + sw, pal);
        }
#pragma unroll
        for (int t = 0; t < 2; t++) {
            const int idx = tid + t * 256;
            const int r = idx >> 3;
            const int c16 = (idx & 7) << 4;
            const uint32_t sw = SWZ128(r * 128 + c16);
            const char* pb = (const char*)(B + (size_t)(col0 + r) * CDIM + kcol) + c16;
            CP16(sb + T_B + sw, pb);
        }
        CP_COMMIT();
    };

    load_chunk(0, 0);

    for (int kc = 0; kc < NCHUNK; kc++) {
        CP_WAIT0();
        __syncthreads();
        if (kc + 1 < NCHUNK) load_chunk(kc + 1, (kc + 1) & 1);

        const uint32_t sb = sbase + (kc & 1) * CH_BYTES;
#pragma unroll
        for (int s = 0; s < 4; s++) {
            const int kb = s * 32;
            uint32_t ahi[2][4], alo[2][4];
#pragma unroll
            for (int i = 0; i < 2; i++) {
                const uint32_t off =
                    SWZ128((warp_m * 32 + i * 16 + a_roff) * 128 + kb + a_kh);
                ldsm_x4(ahi[i], sb + T_AHI + off);
                ldsm_x4(alo[i], sb + T_ALO + off);
            }
            uint32_t bf[4][2];
#pragma unroll
            for (int j2 = 0; j2 < 2; j2++) {
                const uint32_t off =
                    SWZ128((warp_n * 32 + j2 * 16 + b_roff) * 128 + kb + b_kh);
                uint32_t t[4];
                ldsm_x4(t, sb + T_B + off);
                bf[2 * j2][0] = t[0]; bf[2 * j2][1] = t[1];
                bf[2 * j2 + 1][0] = t[2]; bf[2 * j2 + 1][1] = t[3];
            }
#pragma unroll
            for (int i = 0; i < 2; i++)
#pragma unroll
                for (int j = 0; j < 4; j++)
                    mma16816h(acc[i][j], ahi[i], bf[j]);
#pragma unroll
            for (int i = 0; i < 2; i++)
#pragma unroll
                for (int j = 0; j < 4; j++)
                    mma16816h(acc[i][j], alo[i], bf[j]);
        }
    }

    // ---- epilogue ----
#pragma unroll
    for (int i = 0; i < 2; i++) {
        const int mrow = row0 + warp_m * 32 + i * 16 + (lane >> 2);
#pragma unroll
        for (int j = 0; j < 4; j++) {
            const int ncol = col0 + warp_n * 32 + j * 8 + ((lane & 3) << 1);
            const float2 bv = *(const float2*)&bias[ncol];
            const float c0 = (acc[i][j][0] + bv.x) * oscale;
            const float c1 = (acc[i][j][1] + bv.y) * oscale;
            const float c2 = (acc[i][j][2] + bv.x) * oscale;
            const float c3 = (acc[i][j][3] + bv.y) * oscale;
            if (SPLIT_OUT) {
                *(__half2*)&Cov[(size_t)mrow * CDIM + ncol] = __floats2half2_rn(c0, c1);
                *(__half2*)&Cov[(size_t)(mrow + 8) * CDIM + ncol] = __floats2half2_rn(c2, c3);
            } else {
                float2 o0, o1;
                o0.x = c0; o0.y = c1;
                o1.x = c2; o1.y = c3;
                *(float2*)&Cout[(size_t)mrow * CDIM + ncol] = o0;
                *(float2*)&Cout[(size_t)(mrow + 8) * CDIM + ncol] = o1;
            }
        }
    }
}

// ---------------------------------------------------------------------------
// Flash attention (causal), minimal fp16 datapath + lean softmax:
//   - p computed via ex2.approx.f16x2 (half the MUFU ops, result IS the
//     P fragment -> no separate pack)
//   - row sums l computed by an extra MMA against a constant all-ones B
//     fragment (exact fp32, no FADD chain, no shuffles; consistent with
//     the exact fp16 P used in PV)
//   BQ=64, 128 threads, 2 CTAs/SM, 3 KV buffers (distance 2).
// ---------------------------------------------------------------------------
#define KV_BUF 16384
#define O_KHI 0
#define O_VHI 8192
#define Q_OFF (3 * KV_BUF)             // 49152
#define FA_SMEM (3 * KV_BUF + 8192)    // 57344

__global__ __launch_bounds__(128, 2) void flash_attn_mma(
    const __half* __restrict__ Qg,
    const __half* __restrict__ Kg,
    const __half* __restrict__ Vg,
    __half* __restrict__ Ohi, __half* __restrict__ Olo)
{
    extern __shared__ char smem[];
    const uint32_t sbase = smem_to_u32(smem);
    const int tid = threadIdx.x;
    const int lane = tid & 31;
    const int wid = tid >> 5;                      // 0..3
    const int qi = (gridDim.x - 1) - blockIdx.x;   // heavy CTAs first
    const int h = blockIdx.y;
    const int b = blockIdx.z;
    const int qrow0 = qi * 64;
    const int m0 = wid * 16;
    const int lr = lane & 7;
    const int lg = lane >> 3;

    const int nkt = qi + 1;

    // constant all-ones B fragment (fp16 1.0 pairs) for row-sum MMA
    const uint32_t ones[2] = {0x3C003C00u, 0x3C003C00u};

    // ---- load Q tile (64 rows x 128B) ----
#pragma unroll
    for (int t = 0; t < 4; t++) {
        const int idx = tid + t * 128;             // 0..511
        const int r = idx >> 3;
        const int c16 = (idx & 7) << 4;
        const uint32_t sw = SWZ128(r * 128 + c16);
        const size_t grow = (size_t)(b * SEQT + qrow0 + r) * CDIM + h * HDIM;
        CP16(sbase + Q_OFF + sw, (const char*)(Qg + grow) + c16);
    }
    CP_COMMIT();

    auto load_kv = [&](int kt) {
        const uint32_t sb = sbase + (uint32_t)(kt % 3) * KV_BUF;
#pragma unroll
        for (int t = 0; t < 4; t++) {
            const int idx = tid + t * 128;         // 0..511
            const int r = idx >> 3;
            const int c16 = (idx & 7) << 4;
            const uint32_t sw = SWZ128(r * 128 + c16);
            const size_t grow = (size_t)(b * SEQT + kt * 64 + r) * CDIM + h * HDIM;
            CP16(sb + O_KHI + sw, (const char*)(Kg + grow) + c16);
            CP16(sb + O_VHI + sw, (const char*)(Vg + grow) + c16);
        }
        CP_COMMIT();
    };
    load_kv(0);
    if (nkt > 1) load_kv(1);

    // ---- Q landed (kv0/kv1 may fly); hoist Q fragments ----
    if (nkt > 1) { CP_WAIT2(); } else { CP_WAIT1(); }
    __syncthreads();
    uint32_t qf[4][4];
#pragma unroll
    for (int s = 0; s < 4; s++) {
        const uint32_t sw = SWZ128((m0 + ((lg & 1) << 3) + lr) * 128
                                   + s * 32 + ((lg >> 1) << 4));
        ldsm_x4(qf[s], sbase + Q_OFF + sw);
    }

    float o[8][4];
#pragma unroll
    for (int j = 0; j < 8; j++)
#pragma unroll
        for (int r = 0; r < 4; r++) o[j][r] = 0.0f;
    float mR[2] = {-1e30f, -1e30f};
    float lR[2] = {0.0f, 0.0f};

    for (int kt = 0; kt < nkt; kt++) {
        if (kt + 1 < nkt) { CP_WAIT1(); } else { CP_WAIT0(); }
        __syncthreads();   // everyone's writes visible; prev-iter reads done
        if (kt + 2 < nkt) load_kv(kt + 2);
        const uint32_t kb = sbase + (uint32_t)(kt % 3) * KV_BUF;

        // ---- S = Q @ K^T (single fp16: 1 combo) ----
        float sacc[8][4];
#pragma unroll
        for (int j = 0; j < 8; j++)
#pragma unroll
            for (int r = 0; r < 4; r++) sacc[j][r] = 0.0f;

#pragma unroll
        for (int s = 0; s < 4; s++) {
#pragma unroll
            for (int p = 0; p < 4; p++) {
                const uint32_t sw = SWZ128((p * 16 + ((lg >> 1) << 3) + lr) * 128
                                           + s * 32 + ((lg & 1) << 4));
                uint32_t kh[4];
                ldsm_x4(kh, kb + O_KHI + sw);
                mma16816h(sacc[2 * p],     qf[s], &kh[0]);
                mma16816h(sacc[2 * p + 1], qf[s], &kh[2]);
            }
        }

        // ---- causal mask (only the diagonal tile kt == qi) ----
        if (kt == nkt - 1) {
            const int qg0 = qrow0 + m0 + (lane >> 2);
            const int qg1 = qg0 + 8;
#pragma unroll
            for (int j = 0; j < 8; j++) {
                const int kg = kt * 64 + j * 8 + ((lane & 3) << 1);
                if (kg > qg0)     sacc[j][0] = -1e30f;
                if (kg + 1 > qg0) sacc[j][1] = -1e30f;
                if (kg > qg1)     sacc[j][2] = -1e30f;
                if (kg + 1 > qg1) sacc[j][3] = -1e30f;
            }
        }

        // ---- row max (scores already in log2 units) ----
        float mp0 = sacc[0][0], mp1 = sacc[0][2];
#pragma unroll
        for (int j = 0; j < 8; j++) {
            mp0 = fmaxf(mp0, fmaxf(sacc[j][0], sacc[j][1]));
            mp1 = fmaxf(mp1, fmaxf(sacc[j][2], sacc[j][3]));
        }
        mp0 = fmaxf(mp0, __shfl_xor_sync(0xffffffffu, mp0, 1));
        mp0 = fmaxf(mp0, __shfl_xor_sync(0xffffffffu, mp0, 2));
        mp1 = fmaxf(mp1, __shfl_xor_sync(0xffffffffu, mp1, 1));
        mp1 = fmaxf(mp1, __shfl_xor_sync(0xffffffffu, mp1, 2));
        const float mn0 = fmaxf(mR[0], mp0);
        const float mn1 = fmaxf(mR[1], mp1);
        const float f0 = fast_ex2(mR[0] - mn0);
        const float f1 = fast_ex2(mR[1] - mn1);
        mR[0] = mn0;
        mR[1] = mn1;
#pragma unroll
        for (int j = 0; j < 8; j++) {
            o[j][0] *= f0; o[j][1] *= f0;
            o[j][2] *= f1; o[j][3] *= f1;
        }

        // ---- P = exp2(S - m) directly in fp16 fragments; l via ones-MMA;
        //      O += P @ V ----
        float lacc[4];
        lacc[0] = lacc[1] = lacc[2] = lacc[3] = 0.0f;
#pragma unroll
        for (int s2 = 0; s2 < 4; s2++) {
            uint32_t ph[4];
#pragma unroll
            for (int half = 0; half < 2; half++) {
                const int jt = 2 * s2 + half;
                ph[2 * half]     = ex2_h2(sacc[jt][0] - mn0, sacc[jt][1] - mn0);
                ph[2 * half + 1] = ex2_h2(sacc[jt][2] - mn1, sacc[jt][3] - mn1);
            }
            mma16816h(lacc, ph, ones);   // exact row sums of this P chunk
#pragma unroll
            for (int dp = 0; dp < 4; dp++) {
                const uint32_t sw = SWZ128((s2 * 16 + ((lg & 1) << 3) + lr) * 128
                                           + dp * 32 + ((lg >> 1) << 4));
                uint32_t vh[4];
                ldsm_x4_trans(vh, kb + O_VHI + sw);
                mma16816h(o[2 * dp],     ph, &vh[0]);
                mma16816h(o[2 * dp + 1], ph, &vh[2]);
            }
        }
        lR[0] = lR[0] * f0 + lacc[0];
        lR[1] = lR[1] * f1 + lacc[2];
    }

    // ---- normalize + write fp16 hi/lo (Wo GEMM input format) ----
    const float inv0 = 1.0f / lR[0];
    const float inv1 = 1.0f / lR[1];
    const int r0 = b * SEQT + qrow0 + m0 + (lane >> 2);
#pragma unroll
    for (int j = 0; j < 8; j++) {
        const int col = h * HDIM + j * 8 + ((lane & 3) << 1);
        const float c0 = o[j][0] * inv0, c1 = o[j][1] * inv0;
        const float c2 = o[j][2] * inv1, c3 = o[j][3] * inv1;
        __half2 h0 = __floats2half2_rn(c0, c1);
        float2 hf0 = __half22float2(h0);
        __half2 l0 = __floats2half2_rn(c0 - hf0.x, c1 - hf0.y);
        __half2 h1 = __floats2half2_rn(c2, c3);
        float2 hf1 = __half22float2(h1);
        __half2 l1 = __floats2half2_rn(c2 - hf1.x, c3 - hf1.y);
        *(__half2*)&Ohi[(size_t)r0 * CDIM + col] = h0;
        *(__half2*)&Olo[(size_t)r0 * CDIM + col] = l0;
        *(__half2*)&Ohi[(size_t)(r0 + 8) * CDIM + col] = h1;
        *(__half2*)&Olo[(size_t)(r0 + 8) * CDIM + col] = l1;
    }
}

// ---------------------------------------------------------------------------
// Launch
// ---------------------------------------------------------------------------
extern "C" void kernel_launch(void* const* d_in, const int* in_sizes, int n_in,
                              void* d_out, int out_size)
{
    (void)in_sizes; (void)n_in; (void)out_size;
    const float* x  = (const float*)d_in[0];
    const float* Wq = (const float*)d_in[1];
    const float* bq = (const float*)d_in[2];
    const float* Wk = (const float*)d_in[3];
    const float* bk = (const float*)d_in[4];
    const float* Wv = (const float*)d_in[5];
    const float* bv = (const float*)d_in[6];
    const float* Wo = (const float*)d_in[7];
    const float* bo = (const float*)d_in[8];
    float* out = (float*)d_out;

    __half *xhi, *xlo, *q, *k, *v, *ahi, *alo, *wt;
    cudaGetSymbolAddress((void**)&xhi, g_xhi);
    cudaGetSymbolAddress((void**)&xlo, g_xlo);
    cudaGetSymbolAddress((void**)&q,   g_q);
    cudaGetSymbolAddress((void**)&k,   g_k);
    cudaGetSymbolAddress((void**)&v,   g_v);
    cudaGetSymbolAddress((void**)&ahi, g_ahi);
    cudaGetSymbolAddress((void**)&alo, g_alo);
    cudaGetSymbolAddress((void**)&wt,  g_wt);

    cudaFuncSetAttribute(gemm_mma_fp16<true>,
                         cudaFuncAttributeMaxDynamicSharedMemorySize, GEMM_SMEM);
    cudaFuncSetAttribute(gemm_mma_fp16<false>,
                         cudaFuncAttributeMaxDynamicSharedMemorySize, GEMM_SMEM);
    cudaFuncSetAttribute(flash_attn_mma,
                         cudaFuncAttributeMaxDynamicSharedMemorySize, FA_SMEM);

    const int nelem = MROWS * CDIM;

    split_f32<<<(nelem + 255) / 256, 256>>>(x, xhi, xlo, nelem);

    dim3 wt_grid(CDIM / 32, CDIM / 32, 4);
    dim3 wt_blk(32, 8);
    wtrans4<<<wt_grid, wt_blk>>>(Wq, Wk, Wv, Wo, wt);

    dim3 qkv_grid(36, MROWS / 128);
    gemm_mma_fp16<true><<<qkv_grid, 256, GEMM_SMEM>>>(
        xhi, xlo, wt, bq, bk, bv, nullptr, q, k, v);

    dim3 fa_grid(SEQT / 64, NHEAD, BATCH);     // (32, 12, 4) = 1536 CTAs
    flash_attn_mma<<<fa_grid, 128, FA_SMEM>>>(q, k, v, ahi, alo);

    dim3 wo_grid(12, MROWS / 128);
    gemm_mma_fp16<false><<<wo_grid, 256, GEMM_SMEM>>>(
        ahi, alo, wt, bo, nullptr, nullptr, out, nullptr, nullptr, nullptr);
}

// round 16
// speedup vs baseline: 2.0694x; 1.1779x over previous
#include <cuda_runtime.h>
#include <cuda_bf16.h>
#include <cuda_fp16.h>
#include <math.h>
#include <stdint.h>

#define BATCH 4
#define SEQT 2048
#define CDIM 768
#define NHEAD 12
#define HDIM 64
#define MROWS (BATCH * SEQT)   // 8192

// ---------------------------------------------------------------------------
// Scratch (allocation-free rule: device globals)
// ---------------------------------------------------------------------------
__device__ __half g_x[(size_t)MROWS * CDIM];     // x single fp16
__device__ __half g_q[(size_t)MROWS * CDIM];     // Q single fp16 (pre-scaled)
__device__ __half g_k[(size_t)MROWS * CDIM];     // K single fp16
__device__ __half g_v[(size_t)MROWS * CDIM];     // V single fp16
__device__ __half g_ahi[(size_t)MROWS * CDIM];   // attention out hi
__device__ __half g_alo[(size_t)MROWS * CDIM];   // attention out lo
// transposed weights, single fp16: [4][N=CDIM][K=CDIM] (Wq, Wk, Wv, Wo)
__device__ __half g_wt[4 * (size_t)CDIM * CDIM];

// ---------------------------------------------------------------------------
// PTX helpers (sm_80-era: legal under .target sm_103)
// ---------------------------------------------------------------------------
__device__ __forceinline__ uint32_t smem_to_u32(const void* p) {
    uint32_t a;
    asm("{ .reg .u64 t; cvta.to.shared.u64 t, %1; cvt.u32.u64 %0, t; }"
        : "=r"(a) : "l"(p));
    return a;
}

__device__ __forceinline__ void ldsm_x4(uint32_t* r, uint32_t addr) {
    asm volatile("ldmatrix.sync.aligned.m8n8.x4.shared.b16 {%0,%1,%2,%3}, [%4];"
        : "=r"(r[0]), "=r"(r[1]), "=r"(r[2]), "=r"(r[3]) : "r"(addr));
}

__device__ __forceinline__ void ldsm_x4_trans(uint32_t* r, uint32_t addr) {
    asm volatile("ldmatrix.sync.aligned.m8n8.x4.trans.shared.b16 {%0,%1,%2,%3}, [%4];"
        : "=r"(r[0]), "=r"(r[1]), "=r"(r[2]), "=r"(r[3]) : "r"(addr));
}

// fp16 MMA
__device__ __forceinline__ void mma16816h(float* c, const uint32_t* a, const uint32_t* b) {
    asm volatile(
        "mma.sync.aligned.m16n8k16.row.col.f32.f16.f16.f32 "
        "{%0,%1,%2,%3}, {%4,%5,%6,%7}, {%8,%9}, {%0,%1,%2,%3};"
        : "+f"(c[0]), "+f"(c[1]), "+f"(c[2]), "+f"(c[3])
        : "r"(a[0]), "r"(a[1]), "r"(a[2]), "r"(a[3]), "r"(b[0]), "r"(b[1]));
}

__device__ __forceinline__ float fast_ex2(float x) {
    float y;
    asm("ex2.approx.f32 %0, %1;" : "=f"(y) : "f"(x));
    return y;
}

// two fp16 exponentials in one MUFU op
__device__ __forceinline__ uint32_t ex2_h2(float a, float b) {
    __half2 h = __floats2half2_rn(a, b);
    uint32_t r;
    asm("ex2.approx.f16x2 %0, %1;" : "=r"(r) : "r"(*(uint32_t*)&h));
    return r;
}

#define CP16(dst, src) \
    asm volatile("cp.async.cg.shared.global [%0], [%1], 16;" \
                 :: "r"(dst), "l"(src) : "memory")
#define CP_COMMIT() asm volatile("cp.async.commit_group;" ::: "memory")
#define CP_WAIT2()  asm volatile("cp.async.wait_group 2;" ::: "memory")
#define CP_WAIT1()  asm volatile("cp.async.wait_group 1;" ::: "memory")
#define CP_WAIT0()  asm volatile("cp.async.wait_group 0;" ::: "memory")

#define SWZ128(off) ((off) ^ (((off) >> 3) & 0x70))

// 0.125 * log2(e): folded into Q at the QKV GEMM epilogue
#define QK_SCALE 0.18033688011112042f

// ---------------------------------------------------------------------------
// Conversion kernels
// ---------------------------------------------------------------------------
__global__ void tofp16(const float* __restrict__ in, __half* __restrict__ o, int n) {
    int i = blockIdx.x * blockDim.x + threadIdx.x;
    if (i < n) o[i] = __float2half_rn(in[i]);
}

__global__ void wtrans4(const float* __restrict__ W0, const float* __restrict__ W1,
                        const float* __restrict__ W2, const float* __restrict__ W3,
                        __half* __restrict__ wt) {
    __shared__ float t[32][33];
    const int z = blockIdx.z;
    const float* W = (z == 0) ? W0 : (z == 1) ? W1 : (z == 2) ? W2 : W3;
    const size_t zoff = (size_t)z * CDIM * CDIM;
    const int kx = blockIdx.x * 32;
    const int nx = blockIdx.y * 32;
    const int tx = threadIdx.x, ty = threadIdx.y;
    for (int j = ty; j < 32; j += 8)
        t[j][tx] = W[(size_t)(kx + j) * CDIM + nx + tx];
    __syncthreads();
    for (int j = ty; j < 32; j += 8)
        wt[zoff + (size_t)(nx + j) * CDIM + kx + tx] = __float2half_rn(t[tx][j]);
}

// ---------------------------------------------------------------------------
// fp16 GEMM: C = A @ W + bias. W single fp16.
//   A_SPLIT=true:  A fp16 hi/lo, 2 combos (Wo path).
//   A_SPLIT=false: A single fp16, 1 combo (QKV path).
//   128x64 tile, 2 stages, 2 CTAs/SM.
// ---------------------------------------------------------------------------
#define GK 64
#define NCHUNK (CDIM / GK)        // 12
#define CH_BYTES 40960
#define GEMM_SMEM (2 * CH_BYTES)  // 81920
#define T_AHI 0
#define T_ALO 16384
#define T_B   32768

template <bool SPLIT_OUT, bool A_SPLIT>
__global__ __launch_bounds__(256, 2) void gemm_mma_fp16(
    const __half* __restrict__ Ahi, const __half* __restrict__ Alo,
    const __half* __restrict__ Wt,
    const float* __restrict__ b0, const float* __restrict__ b1,
    const float* __restrict__ b2,
    float* __restrict__ Cout,
    __half* __restrict__ C0, __half* __restrict__ C1, __half* __restrict__ C2)
{
    extern __shared__ char smem[];
    const uint32_t sbase = smem_to_u32(smem);
    const int tid = threadIdx.x;
    const int lane = tid & 31;
    const int wid = tid >> 5;
    const int warp_m = wid >> 1;
    const int warp_n = wid & 1;
    const int row0 = blockIdx.y * 128;

    int wsel, col0;
    if (SPLIT_OUT) { wsel = blockIdx.x / 12; col0 = (blockIdx.x % 12) * 64; }
    else           { wsel = 3;              col0 = blockIdx.x * 64; }

    const size_t WSZ = (size_t)CDIM * CDIM;
    const __half* B = Wt + (size_t)wsel * WSZ;
    const float* bias = SPLIT_OUT ? (wsel == 0 ? b0 : wsel == 1 ? b1 : b2) : b0;
    __half* Cov = SPLIT_OUT ? (wsel == 0 ? C0 : wsel == 1 ? C1 : C2) : nullptr;
    const float oscale = (SPLIT_OUT && wsel == 0) ? QK_SCALE : 1.0f;

    const int lrow = lane & 7;
    const int lgrp = lane >> 3;
    const int a_roff = ((lgrp & 1) << 3) + lrow;
    const int a_kh   = (lgrp >> 1) << 4;
    const int b_roff = ((lgrp >> 1) << 3) + lrow;
    const int b_kh   = (lgrp & 1) << 4;

    const int ld_r   = tid >> 3;
    const int ld_c16 = (tid & 7) << 4;

    float acc[2][4][4];
#pragma unroll
    for (int i = 0; i < 2; i++)
#pragma unroll
        for (int j = 0; j < 4; j++)
#pragma unroll
            for (int r = 0; r < 4; r++) acc[i][j][r] = 0.0f;

    auto load_chunk = [&](int kc, int stage) {
        const uint32_t sb = sbase + stage * CH_BYTES;
        const int kcol = kc * GK;
#pragma unroll
        for (int t = 0; t < 4; t++) {
            const int r = ld_r + t * 32;
            const uint32_t sw = SWZ128(r * 128 + ld_c16);
            const char* pa = (const char*)(Ahi + (size_t)(row0 + r) * CDIM + kcol) + ld_c16;
            CP16(sb + T_AHI + sw, pa);
            if (A_SPLIT) {
                const char* pal = (const char*)(Alo + (size_t)(row0 + r) * CDIM + kcol) + ld_c16;
                CP16(sb + T_ALO + sw, pal);
            }
        }
#pragma unroll
        for (int t = 0; t < 2; t++) {
            const int idx = tid + t * 256;
            const int r = idx >> 3;
            const int c16 = (idx & 7) << 4;
            const uint32_t sw = SWZ128(r * 128 + c16);
            const char* pb = (const char*)(B + (size_t)(col0 + r) * CDIM + kcol) + c16;
            CP16(sb + T_B + sw, pb);
        }
        CP_COMMIT();
    };

    load_chunk(0, 0);

    for (int kc = 0; kc < NCHUNK; kc++) {
        CP_WAIT0();
        __syncthreads();
        if (kc + 1 < NCHUNK) load_chunk(kc + 1, (kc + 1) & 1);

        const uint32_t sb = sbase + (kc & 1) * CH_BYTES;
#pragma unroll
        for (int s = 0; s < 4; s++) {
            const int kb = s * 32;
            uint32_t ahi[2][4], alo[2][4];
#pragma unroll
            for (int i = 0; i < 2; i++) {
                const uint32_t off =
                    SWZ128((warp_m * 32 + i * 16 + a_roff) * 128 + kb + a_kh);
                ldsm_x4(ahi[i], sb + T_AHI + off);
                if (A_SPLIT) ldsm_x4(alo[i], sb + T_ALO + off);
            }
            uint32_t bf[4][2];
#pragma unroll
            for (int j2 = 0; j2 < 2; j2++) {
                const uint32_t off =
                    SWZ128((warp_n * 32 + j2 * 16 + b_roff) * 128 + kb + b_kh);
                uint32_t t[4];
                ldsm_x4(t, sb + T_B + off);
                bf[2 * j2][0] = t[0]; bf[2 * j2][1] = t[1];
                bf[2 * j2 + 1][0] = t[2]; bf[2 * j2 + 1][1] = t[3];
            }
#pragma unroll
            for (int i = 0; i < 2; i++)
#pragma unroll
                for (int j = 0; j < 4; j++)
                    mma16816h(acc[i][j], ahi[i], bf[j]);
            if (A_SPLIT) {
#pragma unroll
                for (int i = 0; i < 2; i++)
#pragma unroll
                    for (int j = 0; j < 4; j++)
                        mma16816h(acc[i][j], alo[i], bf[j]);
            }
        }
    }

    // ---- epilogue ----
#pragma unroll
    for (int i = 0; i < 2; i++) {
        const int mrow = row0 + warp_m * 32 + i * 16 + (lane >> 2);
#pragma unroll
        for (int j = 0; j < 4; j++) {
            const int ncol = col0 + warp_n * 32 + j * 8 + ((lane & 3) << 1);
            const float2 bv = *(const float2*)&bias[ncol];
            const float c0 = (acc[i][j][0] + bv.x) * oscale;
            const float c1 = (acc[i][j][1] + bv.y) * oscale;
            const float c2 = (acc[i][j][2] + bv.x) * oscale;
            const float c3 = (acc[i][j][3] + bv.y) * oscale;
            if (SPLIT_OUT) {
                *(__half2*)&Cov[(size_t)mrow * CDIM + ncol] = __floats2half2_rn(c0, c1);
                *(__half2*)&Cov[(size_t)(mrow + 8) * CDIM + ncol] = __floats2half2_rn(c2, c3);
            } else {
                float2 o0, o1;
                o0.x = c0; o0.y = c1;
                o1.x = c2; o1.y = c3;
                *(float2*)&Cout[(size_t)mrow * CDIM + ncol] = o0;
                *(float2*)&Cout[(size_t)(mrow + 8) * CDIM + ncol] = o1;
            }
        }
    }
}

// ---------------------------------------------------------------------------
// Flash attention (causal) — unchanged from R15 (97us; ex2.f16x2 + ones-MMA).
// ---------------------------------------------------------------------------
#define KV_BUF 16384
#define O_KHI 0
#define O_VHI 8192
#define Q_OFF (3 * KV_BUF)             // 49152
#define FA_SMEM (3 * KV_BUF + 8192)    // 57344

__global__ __launch_bounds__(128, 2) void flash_attn_mma(
    const __half* __restrict__ Qg,
    const __half* __restrict__ Kg,
    const __half* __restrict__ Vg,
    __half* __restrict__ Ohi, __half* __restrict__ Olo)
{
    extern __shared__ char smem[];
    const uint32_t sbase = smem_to_u32(smem);
    const int tid = threadIdx.x;
    const int lane = tid & 31;
    const int wid = tid >> 5;                      // 0..3
    const int qi = (gridDim.x - 1) - blockIdx.x;   // heavy CTAs first
    const int h = blockIdx.y;
    const int b = blockIdx.z;
    const int qrow0 = qi * 64;
    const int m0 = wid * 16;
    const int lr = lane & 7;
    const int lg = lane >> 3;

    const int nkt = qi + 1;

    const uint32_t ones[2] = {0x3C003C00u, 0x3C003C00u};

    // ---- load Q tile (64 rows x 128B) ----
#pragma unroll
    for (int t = 0; t < 4; t++) {
        const int idx = tid + t * 128;             // 0..511
        const int r = idx >> 3;
        const int c16 = (idx & 7) << 4;
        const uint32_t sw = SWZ128(r * 128 + c16);
        const size_t grow = (size_t)(b * SEQT + qrow0 + r) * CDIM + h * HDIM;
        CP16(sbase + Q_OFF + sw, (const char*)(Qg + grow) + c16);
    }
    CP_COMMIT();

    auto load_kv = [&](int kt) {
        const uint32_t sb = sbase + (uint32_t)(kt % 3) * KV_BUF;
#pragma unroll
        for (int t = 0; t < 4; t++) {
            const int idx = tid + t * 128;         // 0..511
            const int r = idx >> 3;
            const int c16 = (idx & 7) << 4;
            const uint32_t sw = SWZ128(r * 128 + c16);
            const size_t grow = (size_t)(b * SEQT + kt * 64 + r) * CDIM + h * HDIM;
            CP16(sb + O_KHI + sw, (const char*)(Kg + grow) + c16);
            CP16(sb + O_VHI + sw, (const char*)(Vg + grow) + c16);
        }
        CP_COMMIT();
    };
    load_kv(0);
    if (nkt > 1) load_kv(1);

    // ---- Q landed (kv0/kv1 may fly); hoist Q fragments ----
    if (nkt > 1) { CP_WAIT2(); } else { CP_WAIT1(); }
    __syncthreads();
    uint32_t qf[4][4];
#pragma unroll
    for (int s = 0; s < 4; s++) {
        const uint32_t sw = SWZ128((m0 + ((lg & 1) << 3) + lr) * 128
                                   + s * 32 + ((lg >> 1) << 4));
        ldsm_x4(qf[s], sbase + Q_OFF + sw);
    }

    float o[8][4];
#pragma unroll
    for (int j = 0; j < 8; j++)
#pragma unroll
        for (int r = 0; r < 4; r++) o[j][r] = 0.0f;
    float mR[2] = {-1e30f, -1e30f};
    float lR[2] = {0.0f, 0.0f};

    for (int kt = 0; kt < nkt; kt++) {
        if (kt + 1 < nkt) { CP_WAIT1(); } else { CP_WAIT0(); }
        __syncthreads();
        if (kt + 2 < nkt) load_kv(kt + 2);
        const uint32_t kb = sbase + (uint32_t)(kt % 3) * KV_BUF;

        // ---- S = Q @ K^T ----
        float sacc[8][4];
#pragma unroll
        for (int j = 0; j < 8; j++)
#pragma unroll
            for (int r = 0; r < 4; r++) sacc[j][r] = 0.0f;

#pragma unroll
        for (int s = 0; s < 4; s++) {
#pragma unroll
            for (int p = 0; p < 4; p++) {
                const uint32_t sw = SWZ128((p * 16 + ((lg >> 1) << 3) + lr) * 128
                                           + s * 32 + ((lg & 1) << 4));
                uint32_t kh[4];
                ldsm_x4(kh, kb + O_KHI + sw);
                mma16816h(sacc[2 * p],     qf[s], &kh[0]);
                mma16816h(sacc[2 * p + 1], qf[s], &kh[2]);
            }
        }

        // ---- causal mask ----
        if (kt == nkt - 1) {
            const int qg0 = qrow0 + m0 + (lane >> 2);
            const int qg1 = qg0 + 8;
#pragma unroll
            for (int j = 0; j < 8; j++) {
                const int kg = kt * 64 + j * 8 + ((lane & 3) << 1);
                if (kg > qg0)     sacc[j][0] = -1e30f;
                if (kg + 1 > qg0) sacc[j][1] = -1e30f;
                if (kg > qg1)     sacc[j][2] = -1e30f;
                if (kg + 1 > qg1) sacc[j][3] = -1e30f;
            }
        }

        // ---- row max ----
        float mp0 = sacc[0][0], mp1 = sacc[0][2];
#pragma unroll
        for (int j = 0; j < 8; j++) {
            mp0 = fmaxf(mp0, fmaxf(sacc[j][0], sacc[j][1]));
            mp1 = fmaxf(mp1, fmaxf(sacc[j][2], sacc[j][3]));
        }
        mp0 = fmaxf(mp0, __shfl_xor_sync(0xffffffffu, mp0, 1));
        mp0 = fmaxf(mp0, __shfl_xor_sync(0xffffffffu, mp0, 2));
        mp1 = fmaxf(mp1, __shfl_xor_sync(0xffffffffu, mp1, 1));
        mp1 = fmaxf(mp1, __shfl_xor_sync(0xffffffffu, mp1, 2));
        const float mn0 = fmaxf(mR[0], mp0);
        const float mn1 = fmaxf(mR[1], mp1);
        const float f0 = fast_ex2(mR[0] - mn0);
        const float f1 = fast_ex2(mR[1] - mn1);
        mR[0] = mn0;
        mR[1] = mn1;
#pragma unroll
        for (int j = 0; j < 8; j++) {
            o[j][0] *= f0; o[j][1] *= f0;
            o[j][2] *= f1; o[j][3] *= f1;
        }

        // ---- P via ex2.f16x2; l via ones-MMA; O += P @ V ----
        float lacc[4];
        lacc[0] = lacc[1] = lacc[2] = lacc[3] = 0.0f;
#pragma unroll
        for (int s2 = 0; s2 < 4; s2++) {
            uint32_t ph[4];
#pragma unroll
            for (int half = 0; half < 2; half++) {
                const int jt = 2 * s2 + half;
                ph[2 * half]     = ex2_h2(sacc[jt][0] - mn0, sacc[jt][1] - mn0);
                ph[2 * half + 1] = ex2_h2(sacc[jt][2] - mn1, sacc[jt][3] - mn1);
            }
            mma16816h(lacc, ph, ones);
#pragma unroll
            for (int dp = 0; dp < 4; dp++) {
                const uint32_t sw = SWZ128((s2 * 16 + ((lg & 1) << 3) + lr) * 128
                                           + dp * 32 + ((lg >> 1) << 4));
                uint32_t vh[4];
                ldsm_x4_trans(vh, kb + O_VHI + sw);
                mma16816h(o[2 * dp],     ph, &vh[0]);
                mma16816h(o[2 * dp + 1], ph, &vh[2]);
            }
        }
        lR[0] = lR[0] * f0 + lacc[0];
        lR[1] = lR[1] * f1 + lacc[2];
    }

    // ---- normalize + write fp16 hi/lo (Wo GEMM input format) ----
    const float inv0 = 1.0f / lR[0];
    const float inv1 = 1.0f / lR[1];
    const int r0 = b * SEQT + qrow0 + m0 + (lane >> 2);
#pragma unroll
    for (int j = 0; j < 8; j++) {
        const int col = h * HDIM + j * 8 + ((lane & 3) << 1);
        const float c0 = o[j][0] * inv0, c1 = o[j][1] * inv0;
        const float c2 = o[j][2] * inv1, c3 = o[j][3] * inv1;
        __half2 h0 = __floats2half2_rn(c0, c1);
        float2 hf0 = __half22float2(h0);
        __half2 l0 = __floats2half2_rn(c0 - hf0.x, c1 - hf0.y);
        __half2 h1 = __floats2half2_rn(c2, c3);
        float2 hf1 = __half22float2(h1);
        __half2 l1 = __floats2half2_rn(c2 - hf1.x, c3 - hf1.y);
        *(__half2*)&Ohi[(size_t)r0 * CDIM + col] = h0;
        *(__half2*)&Olo[(size_t)r0 * CDIM + col] = l0;
        *(__half2*)&Ohi[(size_t)(r0 + 8) * CDIM + col] = h1;
        *(__half2*)&Olo[(size_t)(r0 + 8) * CDIM + col] = l1;
    }
}

// ---------------------------------------------------------------------------
// Launch
// ---------------------------------------------------------------------------
extern "C" void kernel_launch(void* const* d_in, const int* in_sizes, int n_in,
                              void* d_out, int out_size)
{
    (void)in_sizes; (void)n_in; (void)out_size;
    const float* x  = (const float*)d_in[0];
    const float* Wq = (const float*)d_in[1];
    const float* bq = (const float*)d_in[2];
    const float* Wk = (const float*)d_in[3];
    const float* bk = (const float*)d_in[4];
    const float* Wv = (const float*)d_in[5];
    const float* bv = (const float*)d_in[6];
    const float* Wo = (const float*)d_in[7];
    const float* bo = (const float*)d_in[8];
    float* out = (float*)d_out;

    __half *xh, *q, *k, *v, *ahi, *alo, *wt;
    cudaGetSymbolAddress((void**)&xh,  g_x);
    cudaGetSymbolAddress((void**)&q,   g_q);
    cudaGetSymbolAddress((void**)&k,   g_k);
    cudaGetSymbolAddress((void**)&v,   g_v);
    cudaGetSymbolAddress((void**)&ahi, g_ahi);
    cudaGetSymbolAddress((void**)&alo, g_alo);
    cudaGetSymbolAddress((void**)&wt,  g_wt);

    cudaFuncSetAttribute((const void*)gemm_mma_fp16<true, false>,
                         cudaFuncAttributeMaxDynamicSharedMemorySize, GEMM_SMEM);
    cudaFuncSetAttribute((const void*)gemm_mma_fp16<false, true>,
                         cudaFuncAttributeMaxDynamicSharedMemorySize, GEMM_SMEM);
    cudaFuncSetAttribute(flash_attn_mma,
                         cudaFuncAttributeMaxDynamicSharedMemorySize, FA_SMEM);

    const int nelem = MROWS * CDIM;

    // 1. x -> single fp16
    tofp16<<<(nelem + 255) / 256, 256>>>(x, xh, nelem);

    // 2. transpose weights -> single fp16
    dim3 wt_grid(CDIM / 32, CDIM / 32, 4);
    dim3 wt_blk(32, 8);
    wtrans4<<<wt_grid, wt_blk>>>(Wq, Wk, Wv, Wo, wt);

    // 3. fused QKV projection (1 combo) -> single fp16 q/k/v
    dim3 qkv_grid(36, MROWS / 128);
    gemm_mma_fp16<true, false><<<qkv_grid, 256, GEMM_SMEM>>>(
        xh, nullptr, wt, bq, bk, bv, nullptr, q, k, v);

    // 4. flash attention -> fp16 hi/lo
    dim3 fa_grid(SEQT / 64, NHEAD, BATCH);     // (32, 12, 4) = 1536 CTAs
    flash_attn_mma<<<fa_grid, 128, FA_SMEM>>>(q, k, v, ahi, alo);

    // 5. output projection (2 combos, hi/lo input) -> fp32 out
    dim3 wo_grid(12, MROWS / 128);
    gemm_mma_fp16<false, true><<<wo_grid, 256, GEMM_SMEM>>>(
        ahi, alo, wt, bo, nullptr, nullptr, out, nullptr, nullptr, nullptr);
}

// round 17
// speedup vs baseline: 2.2849x; 1.1041x over previous
#include <cuda_runtime.h>
#include <cuda_bf16.h>
#include <cuda_fp16.h>
#include <math.h>
#include <stdint.h>

#define BATCH 4
#define SEQT 2048
#define CDIM 768
#define NHEAD 12
#define HDIM 64
#define MROWS (BATCH * SEQT)   // 8192

// ---------------------------------------------------------------------------
// Scratch (allocation-free rule: device globals)
// ---------------------------------------------------------------------------
__device__ __half g_x[(size_t)MROWS * CDIM];     // x single fp16
__device__ __half g_q[(size_t)MROWS * CDIM];     // Q single fp16 (pre-scaled)
__device__ __half g_k[(size_t)MROWS * CDIM];     // K single fp16
__device__ __half g_v[(size_t)MROWS * CDIM];     // V single fp16
__device__ __half g_a[(size_t)MROWS * CDIM];     // attention out single fp16
// transposed weights, single fp16: [4][N=CDIM][K=CDIM] (Wq, Wk, Wv, Wo)
__device__ __half g_wt[4 * (size_t)CDIM * CDIM];

// ---------------------------------------------------------------------------
// PTX helpers (sm_80-era: legal under .target sm_103)
// ---------------------------------------------------------------------------
__device__ __forceinline__ uint32_t smem_to_u32(const void* p) {
    uint32_t a;
    asm("{ .reg .u64 t; cvta.to.shared.u64 t, %1; cvt.u32.u64 %0, t; }"
        : "=r"(a) : "l"(p));
    return a;
}

__device__ __forceinline__ void ldsm_x4(uint32_t* r, uint32_t addr) {
    asm volatile("ldmatrix.sync.aligned.m8n8.x4.shared.b16 {%0,%1,%2,%3}, [%4];"
        : "=r"(r[0]), "=r"(r[1]), "=r"(r[2]), "=r"(r[3]) : "r"(addr));
}

__device__ __forceinline__ void ldsm_x4_trans(uint32_t* r, uint32_t addr) {
    asm volatile("ldmatrix.sync.aligned.m8n8.x4.trans.shared.b16 {%0,%1,%2,%3}, [%4];"
        : "=r"(r[0]), "=r"(r[1]), "=r"(r[2]), "=r"(r[3]) : "r"(addr));
}

// fp16 MMA
__device__ __forceinline__ void mma16816h(float* c, const uint32_t* a, const uint32_t* b) {
    asm volatile(
        "mma.sync.aligned.m16n8k16.row.col.f32.f16.f16.f32 "
        "{%0,%1,%2,%3}, {%4,%5,%6,%7}, {%8,%9}, {%0,%1,%2,%3};"
        : "+f"(c[0]), "+f"(c[1]), "+f"(c[2]), "+f"(c[3])
        : "r"(a[0]), "r"(a[1]), "r"(a[2]), "r"(a[3]), "r"(b[0]), "r"(b[1]));
}

__device__ __forceinline__ float fast_ex2(float x) {
    float y;
    asm("ex2.approx.f32 %0, %1;" : "=f"(y) : "f"(x));
    return y;
}

// two fp16 exponentials in one MUFU op
__device__ __forceinline__ uint32_t ex2_h2(float a, float b) {
    __half2 h = __floats2half2_rn(a, b);
    uint32_t r;
    asm("ex2.approx.f16x2 %0, %1;" : "=r"(r) : "r"(*(uint32_t*)&h));
    return r;
}

#define CP16(dst, src) \
    asm volatile("cp.async.cg.shared.global [%0], [%1], 16;" \
                 :: "r"(dst), "l"(src) : "memory")
#define CP_COMMIT() asm volatile("cp.async.commit_group;" ::: "memory")
#define CP_WAIT2()  asm volatile("cp.async.wait_group 2;" ::: "memory")
#define CP_WAIT1()  asm volatile("cp.async.wait_group 1;" ::: "memory")
#define CP_WAIT0()  asm volatile("cp.async.wait_group 0;" ::: "memory")

#define SWZ128(off) ((off) ^ (((off) >> 3) & 0x70))

// 0.125 * log2(e): folded into Q at the QKV GEMM epilogue
#define QK_SCALE 0.18033688011112042f

// ---------------------------------------------------------------------------
// Conversion kernels
// ---------------------------------------------------------------------------
__global__ void tofp16(const float* __restrict__ in, __half* __restrict__ o, int n) {
    int i = blockIdx.x * blockDim.x + threadIdx.x;
    if (i < n) o[i] = __float2half_rn(in[i]);
}

__global__ void wtrans4(const float* __restrict__ W0, const float* __restrict__ W1,
                        const float* __restrict__ W2, const float* __restrict__ W3,
                        __half* __restrict__ wt) {
    __shared__ float t[32][33];
    const int z = blockIdx.z;
    const float* W = (z == 0) ? W0 : (z == 1) ? W1 : (z == 2) ? W2 : W3;
    const size_t zoff = (size_t)z * CDIM * CDIM;
    const int kx = blockIdx.x * 32;
    const int nx = blockIdx.y * 32;
    const int tx = threadIdx.x, ty = threadIdx.y;
    for (int j = ty; j < 32; j += 8)
        t[j][tx] = W[(size_t)(kx + j) * CDIM + nx + tx];
    __syncthreads();
    for (int j = ty; j < 32; j += 8)
        wt[zoff + (size_t)(nx + j) * CDIM + kx + tx] = __float2half_rn(t[tx][j]);
}

// ---------------------------------------------------------------------------
// fp16 GEMM: C = A @ W + bias. A single fp16, W single fp16 (1 combo).
//   128x64 tile, 2 stages, 2 CTAs/SM.
//   SPLIT_OUT=true: fused QKV -> single fp16 outputs (Q pre-scaled).
//   SPLIT_OUT=false: Wo -> fp32 output.
// ---------------------------------------------------------------------------
#define GK 64
#define NCHUNK (CDIM / GK)        // 12
#define CH_BYTES 24576            // A 16KB + B 8KB
#define GEMM_SMEM (2 * CH_BYTES)  // 49152
#define T_A 0
#define T_B 16384

template <bool SPLIT_OUT>
__global__ __launch_bounds__(256, 2) void gemm_mma_fp16(
    const __half* __restrict__ A,
    const __half* __restrict__ Wt,
    const float* __restrict__ b0, const float* __restrict__ b1,
    const float* __restrict__ b2,
    float* __restrict__ Cout,
    __half* __restrict__ C0, __half* __restrict__ C1, __half* __restrict__ C2)
{
    extern __shared__ char smem[];
    const uint32_t sbase = smem_to_u32(smem);
    const int tid = threadIdx.x;
    const int lane = tid & 31;
    const int wid = tid >> 5;
    const int warp_m = wid >> 1;
    const int warp_n = wid & 1;
    const int row0 = blockIdx.y * 128;

    int wsel, col0;
    if (SPLIT_OUT) { wsel = blockIdx.x / 12; col0 = (blockIdx.x % 12) * 64; }
    else           { wsel = 3;              col0 = blockIdx.x * 64; }

    const size_t WSZ = (size_t)CDIM * CDIM;
    const __half* B = Wt + (size_t)wsel * WSZ;
    const float* bias = SPLIT_OUT ? (wsel == 0 ? b0 : wsel == 1 ? b1 : b2) : b0;
    __half* Cov = SPLIT_OUT ? (wsel == 0 ? C0 : wsel == 1 ? C1 : C2) : nullptr;
    const float oscale = (SPLIT_OUT && wsel == 0) ? QK_SCALE : 1.0f;

    const int lrow = lane & 7;
    const int lgrp = lane >> 3;
    const int a_roff = ((lgrp & 1) << 3) + lrow;
    const int a_kh   = (lgrp >> 1) << 4;
    const int b_roff = ((lgrp >> 1) << 3) + lrow;
    const int b_kh   = (lgrp & 1) << 4;

    const int ld_r   = tid >> 3;
    const int ld_c16 = (tid & 7) << 4;

    float acc[2][4][4];
#pragma unroll
    for (int i = 0; i < 2; i++)
#pragma unroll
        for (int j = 0; j < 4; j++)
#pragma unroll
            for (int r = 0; r < 4; r++) acc[i][j][r] = 0.0f;

    auto load_chunk = [&](int kc, int stage) {
        const uint32_t sb = sbase + stage * CH_BYTES;
        const int kcol = kc * GK;
#pragma unroll
        for (int t = 0; t < 4; t++) {   // A: 128 rows
            const int r = ld_r + t * 32;
            const uint32_t sw = SWZ128(r * 128 + ld_c16);
            const char* pa = (const char*)(A + (size_t)(row0 + r) * CDIM + kcol) + ld_c16;
            CP16(sb + T_A + sw, pa);
        }
#pragma unroll
        for (int t = 0; t < 2; t++) {   // B: 64 rows
            const int idx = tid + t * 256;
            const int r = idx >> 3;
            const int c16 = (idx & 7) << 4;
            const uint32_t sw = SWZ128(r * 128 + c16);
            const char* pb = (const char*)(B + (size_t)(col0 + r) * CDIM + kcol) + c16;
            CP16(sb + T_B + sw, pb);
        }
        CP_COMMIT();
    };

    load_chunk(0, 0);

    for (int kc = 0; kc < NCHUNK; kc++) {
        CP_WAIT0();
        __syncthreads();
        if (kc + 1 < NCHUNK) load_chunk(kc + 1, (kc + 1) & 1);

        const uint32_t sb = sbase + (kc & 1) * CH_BYTES;
#pragma unroll
        for (int s = 0; s < 4; s++) {
            const int kb = s * 32;
            uint32_t af[2][4];
#pragma unroll
            for (int i = 0; i < 2; i++) {
                const uint32_t off =
                    SWZ128((warp_m * 32 + i * 16 + a_roff) * 128 + kb + a_kh);
                ldsm_x4(af[i], sb + T_A + off);
            }
            uint32_t bf[4][2];
#pragma unroll
            for (int j2 = 0; j2 < 2; j2++) {
                const uint32_t off =
                    SWZ128((warp_n * 32 + j2 * 16 + b_roff) * 128 + kb + b_kh);
                uint32_t t[4];
                ldsm_x4(t, sb + T_B + off);
                bf[2 * j2][0] = t[0]; bf[2 * j2][1] = t[1];
                bf[2 * j2 + 1][0] = t[2]; bf[2 * j2 + 1][1] = t[3];
            }
#pragma unroll
            for (int i = 0; i < 2; i++)
#pragma unroll
                for (int j = 0; j < 4; j++)
                    mma16816h(acc[i][j], af[i], bf[j]);
        }
    }

    // ---- epilogue ----
#pragma unroll
    for (int i = 0; i < 2; i++) {
        const int mrow = row0 + warp_m * 32 + i * 16 + (lane >> 2);
#pragma unroll
        for (int j = 0; j < 4; j++) {
            const int ncol = col0 + warp_n * 32 + j * 8 + ((lane & 3) << 1);
            const float2 bv = *(const float2*)&bias[ncol];
            const float c0 = (acc[i][j][0] + bv.x) * oscale;
            const float c1 = (acc[i][j][1] + bv.y) * oscale;
            const float c2 = (acc[i][j][2] + bv.x) * oscale;
            const float c3 = (acc[i][j][3] + bv.y) * oscale;
            if (SPLIT_OUT) {
                *(__half2*)&Cov[(size_t)mrow * CDIM + ncol] = __floats2half2_rn(c0, c1);
                *(__half2*)&Cov[(size_t)(mrow + 8) * CDIM + ncol] = __floats2half2_rn(c2, c3);
            } else {
                float2 o0, o1;
                o0.x = c0; o0.y = c1;
                o1.x = c2; o1.y = c3;
                *(float2*)&Cout[(size_t)mrow * CDIM + ncol] = o0;
                *(float2*)&Cout[(size_t)(mrow + 8) * CDIM + ncol] = o1;
            }
        }
    }
}

// ---------------------------------------------------------------------------
// Flash attention (causal) — R15 mainloop; output now SINGLE fp16.
// ---------------------------------------------------------------------------
#define KV_BUF 16384
#define O_KHI 0
#define O_VHI 8192
#define Q_OFF (3 * KV_BUF)             // 49152
#define FA_SMEM (3 * KV_BUF + 8192)    // 57344

__global__ __launch_bounds__(128, 2) void flash_attn_mma(
    const __half* __restrict__ Qg,
    const __half* __restrict__ Kg,
    const __half* __restrict__ Vg,
    __half* __restrict__ Og)
{
    extern __shared__ char smem[];
    const uint32_t sbase = smem_to_u32(smem);
    const int tid = threadIdx.x;
    const int lane = tid & 31;
    const int wid = tid >> 5;                      // 0..3
    const int qi = (gridDim.x - 1) - blockIdx.x;   // heavy CTAs first
    const int h = blockIdx.y;
    const int b = blockIdx.z;
    const int qrow0 = qi * 64;
    const int m0 = wid * 16;
    const int lr = lane & 7;
    const int lg = lane >> 3;

    const int nkt = qi + 1;

    const uint32_t ones[2] = {0x3C003C00u, 0x3C003C00u};

    // ---- load Q tile (64 rows x 128B) ----
#pragma unroll
    for (int t = 0; t < 4; t++) {
        const int idx = tid + t * 128;             // 0..511
        const int r = idx >> 3;
        const int c16 = (idx & 7) << 4;
        const uint32_t sw = SWZ128(r * 128 + c16);
        const size_t grow = (size_t)(b * SEQT + qrow0 + r) * CDIM + h * HDIM;
        CP16(sbase + Q_OFF + sw, (const char*)(Qg + grow) + c16);
    }
    CP_COMMIT();

    auto load_kv = [&](int kt) {
        const uint32_t sb = sbase + (uint32_t)(kt % 3) * KV_BUF;
#pragma unroll
        for (int t = 0; t < 4; t++) {
            const int idx = tid + t * 128;         // 0..511
            const int r = idx >> 3;
            const int c16 = (idx & 7) << 4;
            const uint32_t sw = SWZ128(r * 128 + c16);
            const size_t grow = (size_t)(b * SEQT + kt * 64 + r) * CDIM + h * HDIM;
            CP16(sb + O_KHI + sw, (const char*)(Kg + grow) + c16);
            CP16(sb + O_VHI + sw, (const char*)(Vg + grow) + c16);
        }
        CP_COMMIT();
    };
    load_kv(0);
    if (nkt > 1) load_kv(1);

    // ---- Q landed (kv0/kv1 may fly); hoist Q fragments ----
    if (nkt > 1) { CP_WAIT2(); } else { CP_WAIT1(); }
    __syncthreads();
    uint32_t qf[4][4];
#pragma unroll
    for (int s = 0; s < 4; s++) {
        const uint32_t sw = SWZ128((m0 + ((lg & 1) << 3) + lr) * 128
                                   + s * 32 + ((lg >> 1) << 4));
        ldsm_x4(qf[s], sbase + Q_OFF + sw);
    }

    float o[8][4];
#pragma unroll
    for (int j = 0; j < 8; j++)
#pragma unroll
        for (int r = 0; r < 4; r++) o[j][r] = 0.0f;
    float mR[2] = {-1e30f, -1e30f};
    float lR[2] = {0.0f, 0.0f};

    for (int kt = 0; kt < nkt; kt++) {
        if (kt + 1 < nkt) { CP_WAIT1(); } else { CP_WAIT0(); }
        __syncthreads();
        if (kt + 2 < nkt) load_kv(kt + 2);
        const uint32_t kb = sbase + (uint32_t)(kt % 3) * KV_BUF;

        // ---- S = Q @ K^T ----
        float sacc[8][4];
#pragma unroll
        for (int j = 0; j < 8; j++)
#pragma unroll
            for (int r = 0; r < 4; r++) sacc[j][r] = 0.0f;

#pragma unroll
        for (int s = 0; s < 4; s++) {
#pragma unroll
            for (int p = 0; p < 4; p++) {
                const uint32_t sw = SWZ128((p * 16 + ((lg >> 1) << 3) + lr) * 128
                                           + s * 32 + ((lg & 1) << 4));
                uint32_t kh[4];
                ldsm_x4(kh, kb + O_KHI + sw);
                mma16816h(sacc[2 * p],     qf[s], &kh[0]);
                mma16816h(sacc[2 * p + 1], qf[s], &kh[2]);
            }
        }

        // ---- causal mask (only the diagonal tile kt == qi) ----
        if (kt == nkt - 1) {
            const int qg0 = qrow0 + m0 + (lane >> 2);
            const int qg1 = qg0 + 8;
#pragma unroll
            for (int j = 0; j < 8; j++) {
                const int kg = kt * 64 + j * 8 + ((lane & 3) << 1);
                if (kg > qg0)     sacc[j][0] = -1e30f;
                if (kg + 1 > qg0) sacc[j][1] = -1e30f;
                if (kg > qg1)     sacc[j][2] = -1e30f;
                if (kg + 1 > qg1) sacc[j][3] = -1e30f;
            }
        }

        // ---- row max (scores already in log2 units) ----
        float mp0 = sacc[0][0], mp1 = sacc[0][2];
#pragma unroll
        for (int j = 0; j < 8; j++) {
            mp0 = fmaxf(mp0, fmaxf(sacc[j][0], sacc[j][1]));
            mp1 = fmaxf(mp1, fmaxf(sacc[j][2], sacc[j][3]));
        }
        mp0 = fmaxf(mp0, __shfl_xor_sync(0xffffffffu, mp0, 1));
        mp0 = fmaxf(mp0, __shfl_xor_sync(0xffffffffu, mp0, 2));
        mp1 = fmaxf(mp1, __shfl_xor_sync(0xffffffffu, mp1, 1));
        mp1 = fmaxf(mp1, __shfl_xor_sync(0xffffffffu, mp1, 2));
        const float mn0 = fmaxf(mR[0], mp0);
        const float mn1 = fmaxf(mR[1], mp1);
        const float f0 = fast_ex2(mR[0] - mn0);
        const float f1 = fast_ex2(mR[1] - mn1);
        mR[0] = mn0;
        mR[1] = mn1;
#pragma unroll
        for (int j = 0; j < 8; j++) {
            o[j][0] *= f0; o[j][1] *= f0;
            o[j][2] *= f1; o[j][3] *= f1;
        }

        // ---- P via ex2.f16x2; l via ones-MMA; O += P @ V ----
        float lacc[4];
        lacc[0] = lacc[1] = lacc[2] = lacc[3] = 0.0f;
#pragma unroll
        for (int s2 = 0; s2 < 4; s2++) {
            uint32_t ph[4];
#pragma unroll
            for (int half = 0; half < 2; half++) {
                const int jt = 2 * s2 + half;
                ph[2 * half]     = ex2_h2(sacc[jt][0] - mn0, sacc[jt][1] - mn0);
                ph[2 * half + 1] = ex2_h2(sacc[jt][2] - mn1, sacc[jt][3] - mn1);
            }
            mma16816h(lacc, ph, ones);
#pragma unroll
            for (int dp = 0; dp < 4; dp++) {
                const uint32_t sw = SWZ128((s2 * 16 + ((lg & 1) << 3) + lr) * 128
                                           + dp * 32 + ((lg >> 1) << 4));
                uint32_t vh[4];
                ldsm_x4_trans(vh, kb + O_VHI + sw);
                mma16816h(o[2 * dp],     ph, &vh[0]);
                mma16816h(o[2 * dp + 1], ph, &vh[2]);
            }
        }
        lR[0] = lR[0] * f0 + lacc[0];
        lR[1] = lR[1] * f1 + lacc[2];
    }

    // ---- normalize + write single fp16 ----
    const float inv0 = 1.0f / lR[0];
    const float inv1 = 1.0f / lR[1];
    const int r0 = b * SEQT + qrow0 + m0 + (lane >> 2);
#pragma unroll
    for (int j = 0; j < 8; j++) {
        const int col = h * HDIM + j * 8 + ((lane & 3) << 1);
        *(__half2*)&Og[(size_t)r0 * CDIM + col] =
            __floats2half2_rn(o[j][0] * inv0, o[j][1] * inv0);
        *(__half2*)&Og[(size_t)(r0 + 8) * CDIM + col] =
            __floats2half2_rn(o[j][2] * inv1, o[j][3] * inv1);
    }
}

// ---------------------------------------------------------------------------
// Launch
// ---------------------------------------------------------------------------
extern "C" void kernel_launch(void* const* d_in, const int* in_sizes, int n_in,
                              void* d_out, int out_size)
{
    (void)in_sizes; (void)n_in; (void)out_size;
    const float* x  = (const float*)d_in[0];
    const float* Wq = (const float*)d_in[1];
    const float* bq = (const float*)d_in[2];
    const float* Wk = (const float*)d_in[3];
    const float* bk = (const float*)d_in[4];
    const float* Wv = (const float*)d_in[5];
    const float* bv = (const float*)d_in[6];
    const float* Wo = (const float*)d_in[7];
    const float* bo = (const float*)d_in[8];
    float* out = (float*)d_out;

    __half *xh, *q, *k, *v, *a, *wt;
    cudaGetSymbolAddress((void**)&xh, g_x);
    cudaGetSymbolAddress((void**)&q,  g_q);
    cudaGetSymbolAddress((void**)&k,  g_k);
    cudaGetSymbolAddress((void**)&v,  g_v);
    cudaGetSymbolAddress((void**)&a,  g_a);
    cudaGetSymbolAddress((void**)&wt, g_wt);

    cudaFuncSetAttribute((const void*)gemm_mma_fp16<true>,
                         cudaFuncAttributeMaxDynamicSharedMemorySize, GEMM_SMEM);
    cudaFuncSetAttribute((const void*)gemm_mma_fp16<false>,
                         cudaFuncAttributeMaxDynamicSharedMemorySize, GEMM_SMEM);
    cudaFuncSetAttribute(flash_attn_mma,
                         cudaFuncAttributeMaxDynamicSharedMemorySize, FA_SMEM);

    const int nelem = MROWS * CDIM;

    // 1. x -> single fp16
    tofp16<<<(nelem + 255) / 256, 256>>>(x, xh, nelem);

    // 2. transpose weights -> single fp16
    dim3 wt_grid(CDIM / 32, CDIM / 32, 4);
    dim3 wt_blk(32, 8);
    wtrans4<<<wt_grid, wt_blk>>>(Wq, Wk, Wv, Wo, wt);

    // 3. fused QKV projection (1 combo) -> single fp16 q/k/v
    dim3 qkv_grid(36, MROWS / 128);
    gemm_mma_fp16<true><<<qkv_grid, 256, GEMM_SMEM>>>(
        xh, wt, bq, bk, bv, nullptr, q, k, v);

    // 4. flash attention -> single fp16
    dim3 fa_grid(SEQT / 64, NHEAD, BATCH);     // (32, 12, 4) = 1536 CTAs
    flash_attn_mma<<<fa_grid, 128, FA_SMEM>>>(q, k, v, a);

    // 5. output projection (1 combo) -> fp32 out
    dim3 wo_grid(12, MROWS / 128);
    gemm_mma_fp16<false><<<wo_grid, 256, GEMM_SMEM>>>(
        a, wt, bo, nullptr, nullptr, out, nullptr, nullptr, nullptr);
}